// round 2
// baseline (speedup 1.0000x reference)
#include <cuda_runtime.h>
#include <math.h>

// ---------------------------------------------------------------------------
// Problem constants
//   B=16, S=2048, C=8, P=16 -> N=128 patches, T=B*N=2048 tokens
//   PD=128, IRH=512, D=512, NH=8, dh=64, L=12, E=4, H=2048
// ---------------------------------------------------------------------------
#define T_TOK 2048
#define DIM   512
#define HDIM  2048

// Scratch (static __device__ arrays; no allocation anywhere)
__device__ float g_patches[T_TOK * 128];
__device__ float g_tmp    [T_TOK * 512];   // ir hidden (IRH=512)
__device__ float g_hp     [T_TOK * 128];
__device__ float g_h      [T_TOK * DIM];
__device__ float g_hn     [T_TOK * DIM];
__device__ float g_qkv    [T_TOK * 3 * DIM];
__device__ float g_attn   [T_TOK * DIM];
__device__ float g_eh     [T_TOK * HDIM];  // 16 MB expert hidden
__device__ float g_wgt    [T_TOK * 4];

// ---------------------------------------------------------------------------
// Tiled SGEMM: C[M,N] = epilogue(A[M,K] @ B[K,N] + bias)
// 64x64 tile, BK=16, 256 threads, 4x4 per thread. M,N,K multiples of 64/16.
// EPI: 0 store, 1 gelu, 2 res+v, 3 C+=v, 4 C+=scale[row*4]*v
// ---------------------------------------------------------------------------
template<int EPI>
__global__ void __launch_bounds__(256) gemm_k(
    const float* __restrict__ A, const float* __restrict__ B,
    const float* __restrict__ bias, float* __restrict__ C,
    int M, int N, int K,
    const float* __restrict__ res, const float* __restrict__ scale)
{
    __shared__ float As[16][64];
    __shared__ float Bs[16][64];
    const int t  = threadIdx.x;
    const int tx = t & 15, ty = t >> 4;
    const int m0 = blockIdx.y * 64, n0 = blockIdx.x * 64;

    const int ar = t >> 2, ak = (t & 3) * 4;   // A tile loader coords
    const int bk = t >> 4, bc = (t & 15) * 4;  // B tile loader coords
    const float* Ag = A + (size_t)(m0 + ar) * K + ak;
    const float* Bg = B + (size_t)bk * N + n0 + bc;

    float acc[4][4] = {};

    for (int k0 = 0; k0 < K; k0 += 16) {
        float4 a4 = *(const float4*)(Ag + k0);
        As[ak + 0][ar] = a4.x; As[ak + 1][ar] = a4.y;
        As[ak + 2][ar] = a4.z; As[ak + 3][ar] = a4.w;
        *(float4*)&Bs[bk][bc] = *(const float4*)(Bg + (size_t)k0 * N);
        __syncthreads();
        #pragma unroll
        for (int k = 0; k < 16; k++) {
            float4 av = *(const float4*)&As[k][ty * 4];
            float4 bv = *(const float4*)&Bs[k][tx * 4];
            float am[4] = {av.x, av.y, av.z, av.w};
            float bm[4] = {bv.x, bv.y, bv.z, bv.w};
            #pragma unroll
            for (int i = 0; i < 4; i++)
                #pragma unroll
                for (int j = 0; j < 4; j++)
                    acc[i][j] += am[i] * bm[j];
        }
        __syncthreads();
    }

    #pragma unroll
    for (int i = 0; i < 4; i++) {
        const int row = m0 + ty * 4 + i;
        #pragma unroll
        for (int j = 0; j < 4; j++) {
            const int col = n0 + tx * 4 + j;
            float v = acc[i][j] + bias[col];
            const size_t idx = (size_t)row * N + col;
            if (EPI == 0)      C[idx] = v;
            else if (EPI == 1) C[idx] = 0.5f * v * (1.0f + erff(v * 0.70710678118654752f));
            else if (EPI == 2) C[idx] = res[idx] + v;
            else if (EPI == 3) C[idx] += v;
            else if (EPI == 4) C[idx] += scale[(size_t)row * 4] * v;
        }
    }
}

// ---------------------------------------------------------------------------
// Instance norm over 128-float patches (eps 1e-6, biased var). Patches are a
// contiguous reinterpret of x [16,2048,8] -> [2048,128]. One warp per patch.
// ---------------------------------------------------------------------------
__global__ void patchnorm_kernel(const float* __restrict__ x, float* __restrict__ y)
{
    const int warp = threadIdx.x >> 5, lane = threadIdx.x & 31;
    const int row = blockIdx.x * 8 + warp;
    const float* xr = x + (size_t)row * 128;
    float4 f = *(const float4*)(xr + lane * 4);
    float s = f.x + f.y + f.z + f.w;
    #pragma unroll
    for (int o = 16; o; o >>= 1) s += __shfl_xor_sync(0xffffffffu, s, o);
    const float mu = s * (1.0f / 128.0f);
    float q = (f.x - mu) * (f.x - mu) + (f.y - mu) * (f.y - mu)
            + (f.z - mu) * (f.z - mu) + (f.w - mu) * (f.w - mu);
    #pragma unroll
    for (int o = 16; o; o >>= 1) q += __shfl_xor_sync(0xffffffffu, q, o);
    const float rs = rsqrtf(q * (1.0f / 128.0f) + 1e-6f);
    float4 r = make_float4((f.x - mu) * rs, (f.y - mu) * rs, (f.z - mu) * rs, (f.w - mu) * rs);
    *(float4*)(y + (size_t)row * 128 + lane * 4) = r;
}

// ---------------------------------------------------------------------------
// LayerNorm over D=512 (eps 1e-5). One warp per row, 8 rows per block.
// ---------------------------------------------------------------------------
__global__ void ln512_kernel(const float* __restrict__ x, float* __restrict__ y,
                             const float* __restrict__ g, const float* __restrict__ b)
{
    const int warp = threadIdx.x >> 5, lane = threadIdx.x & 31;
    const int row = blockIdx.x * 8 + warp;
    const float* xr = x + (size_t)row * 512;
    float v[16];
    float s = 0.f;
    #pragma unroll
    for (int c = 0; c < 4; c++) {
        float4 f = *(const float4*)(xr + c * 128 + lane * 4);
        v[c * 4 + 0] = f.x; v[c * 4 + 1] = f.y; v[c * 4 + 2] = f.z; v[c * 4 + 3] = f.w;
        s += f.x + f.y + f.z + f.w;
    }
    #pragma unroll
    for (int o = 16; o; o >>= 1) s += __shfl_xor_sync(0xffffffffu, s, o);
    const float mu = s * (1.0f / 512.0f);
    float q = 0.f;
    #pragma unroll
    for (int k = 0; k < 16; k++) { float d = v[k] - mu; q += d * d; }
    #pragma unroll
    for (int o = 16; o; o >>= 1) q += __shfl_xor_sync(0xffffffffu, q, o);
    const float rs = rsqrtf(q * (1.0f / 512.0f) + 1e-5f);
    #pragma unroll
    for (int c = 0; c < 4; c++) {
        const int col = c * 128 + lane * 4;
        float4 gg = *(const float4*)(g + col);
        float4 bb = *(const float4*)(b + col);
        float4 r;
        r.x = gg.x * (v[c * 4 + 0] - mu) * rs + bb.x;
        r.y = gg.y * (v[c * 4 + 1] - mu) * rs + bb.y;
        r.z = gg.z * (v[c * 4 + 2] - mu) * rs + bb.z;
        r.w = gg.w * (v[c * 4 + 3] - mu) * rs + bb.w;
        *(float4*)(y + (size_t)row * 512 + col) = r;
    }
}

// h[b,n,:] += freq_emb[freq_id[b], :]
__global__ void freqadd_kernel(float* __restrict__ h, const float* __restrict__ emb,
                               const int* __restrict__ fid)
{
    const int i = blockIdx.x * 256 + threadIdx.x;       // < 2048*512
    const int row = i >> 9, d = i & 511, b = row >> 7;
    h[i] += emb[(size_t)fid[b] * 512 + d];
}

// ---------------------------------------------------------------------------
// Causal attention, NH=8, dh=64, n=128. One warp per (b, head, query row).
// Online softmax; K/V streamed from L1/L2 (32 KB per (b,h), reused 128x).
// ---------------------------------------------------------------------------
__global__ void attn_kernel(const float* __restrict__ qkv, float* __restrict__ o)
{
    const int gw = blockIdx.x * 8 + (threadIdx.x >> 5);
    const int lane = threadIdx.x & 31;
    const int i = gw & 127, hh = (gw >> 7) & 7, b = gw >> 10;
    const float* base = qkv + (size_t)b * 128 * 1536;
    const float* qp = base + (size_t)i * 1536 + hh * 64 + lane * 2;
    const float qx = qp[0], qy = qp[1];
    const float* kp = base + 512  + hh * 64 + lane * 2;
    const float* vp = base + 1024 + hh * 64 + lane * 2;
    float m = -1e30f, l = 0.f, ox = 0.f, oy = 0.f;
    for (int j = 0; j <= i; j++) {
        float2 k2 = *(const float2*)(kp + (size_t)j * 1536);
        float p = qx * k2.x + qy * k2.y;
        #pragma unroll
        for (int off = 16; off; off >>= 1) p += __shfl_xor_sync(0xffffffffu, p, off);
        const float s = p * 0.125f;                 // 1/sqrt(64)
        const float nm = fmaxf(m, s);
        const float sc = __expf(m - nm), e = __expf(s - nm);
        l = l * sc + e;
        float2 v2 = *(const float2*)(vp + (size_t)j * 1536);
        ox = ox * sc + e * v2.x;
        oy = oy * sc + e * v2.y;
        m = nm;
    }
    const float inv = 1.0f / l;
    float* op = o + ((size_t)b * 128 + i) * 512 + hh * 64 + lane * 2;
    op[0] = ox * inv; op[1] = oy * inv;
}

// ---------------------------------------------------------------------------
// Gate: softmax(hn @ gate_w + gate_b) over E=4, keep top-2, zero the rest.
// One warp per token.
// ---------------------------------------------------------------------------
__global__ void gate_kernel(const float* __restrict__ hn, const float* __restrict__ gw,
                            const float* __restrict__ gb, float* __restrict__ wgt)
{
    const int warp = threadIdx.x >> 5, lane = threadIdx.x & 31;
    const int row = blockIdx.x * 8 + warp;
    const float* xr = hn + (size_t)row * 512;
    float a0 = 0.f, a1 = 0.f, a2 = 0.f, a3 = 0.f;
    for (int d = lane; d < 512; d += 32) {
        const float hv = xr[d];
        float4 w = *(const float4*)(gw + (size_t)d * 4);
        a0 += hv * w.x; a1 += hv * w.y; a2 += hv * w.z; a3 += hv * w.w;
    }
    #pragma unroll
    for (int o = 16; o; o >>= 1) {
        a0 += __shfl_xor_sync(0xffffffffu, a0, o);
        a1 += __shfl_xor_sync(0xffffffffu, a1, o);
        a2 += __shfl_xor_sync(0xffffffffu, a2, o);
        a3 += __shfl_xor_sync(0xffffffffu, a3, o);
    }
    if (lane == 0) {
        float p[4] = {a0 + gb[0], a1 + gb[1], a2 + gb[2], a3 + gb[3]};
        const float mx = fmaxf(fmaxf(p[0], p[1]), fmaxf(p[2], p[3]));
        float s = 0.f;
        #pragma unroll
        for (int e = 0; e < 4; e++) { p[e] = expf(p[e] - mx); s += p[e]; }
        const float invs = 1.0f / s;
        #pragma unroll
        for (int e = 0; e < 4; e++) p[e] *= invs;
        int i0 = 0;
        #pragma unroll
        for (int e = 1; e < 4; e++) if (p[e] > p[i0]) i0 = e;
        int i1 = -1;
        #pragma unroll
        for (int e = 0; e < 4; e++) if (e != i0 && (i1 < 0 || p[e] > p[i1])) i1 = e;
        float w4[4] = {0.f, 0.f, 0.f, 0.f};
        w4[i0] = p[i0]; w4[i1] = p[i1];
        float* wr = wgt + (size_t)row * 4;
        wr[0] = w4[0]; wr[1] = w4[1]; wr[2] = w4[2]; wr[3] = w4[3];
    }
}

// ---------------------------------------------------------------------------
// Head: only token 127 of each batch matters. LN(fn) -> LN(head) -> dot head_w.
// One warp per batch; 16 warps in one block.
// ---------------------------------------------------------------------------
__global__ void head_kernel(const float* __restrict__ h,
                            const float* __restrict__ fng, const float* __restrict__ fnb,
                            const float* __restrict__ hg,  const float* __restrict__ hb,
                            const float* __restrict__ hw,  const float* __restrict__ hbias,
                            float* __restrict__ out, int out_size)
{
    const int warp = threadIdx.x >> 5, lane = threadIdx.x & 31;
    const int b = warp;
    const float* xr = h + ((size_t)b * 128 + 127) * 512;
    float v[16];
    float s = 0.f;
    #pragma unroll
    for (int c = 0; c < 4; c++) {
        float4 f = *(const float4*)(xr + c * 128 + lane * 4);
        v[c * 4 + 0] = f.x; v[c * 4 + 1] = f.y; v[c * 4 + 2] = f.z; v[c * 4 + 3] = f.w;
        s += f.x + f.y + f.z + f.w;
    }
    #pragma unroll
    for (int o = 16; o; o >>= 1) s += __shfl_xor_sync(0xffffffffu, s, o);
    float mu = s * (1.0f / 512.0f);
    float q = 0.f;
    #pragma unroll
    for (int k = 0; k < 16; k++) { float d = v[k] - mu; q += d * d; }
    #pragma unroll
    for (int o = 16; o; o >>= 1) q += __shfl_xor_sync(0xffffffffu, q, o);
    float rs = rsqrtf(q * (1.0f / 512.0f) + 1e-5f);
    #pragma unroll
    for (int c = 0; c < 4; c++)
        #pragma unroll
        for (int j = 0; j < 4; j++) {
            const int col = c * 128 + lane * 4 + j;
            v[c * 4 + j] = fng[col] * (v[c * 4 + j] - mu) * rs + fnb[col];
        }
    // second LN (head)
    s = 0.f;
    #pragma unroll
    for (int k = 0; k < 16; k++) s += v[k];
    #pragma unroll
    for (int o = 16; o; o >>= 1) s += __shfl_xor_sync(0xffffffffu, s, o);
    mu = s * (1.0f / 512.0f);
    q = 0.f;
    #pragma unroll
    for (int k = 0; k < 16; k++) { float d = v[k] - mu; q += d * d; }
    #pragma unroll
    for (int o = 16; o; o >>= 1) q += __shfl_xor_sync(0xffffffffu, q, o);
    rs = rsqrtf(q * (1.0f / 512.0f) + 1e-5f);
    float dot = 0.f;
    #pragma unroll
    for (int c = 0; c < 4; c++)
        #pragma unroll
        for (int j = 0; j < 4; j++) {
            const int col = c * 128 + lane * 4 + j;
            const float hl = hg[col] * (v[c * 4 + j] - mu) * rs + hb[col];
            dot += hl * hw[col];
        }
    #pragma unroll
    for (int o = 16; o; o >>= 1) dot += __shfl_xor_sync(0xffffffffu, dot, o);
    if (lane == 0) {
        const float logit = dot + hbias[0];
        if (out_size >= 32) {
            out[b] = logit;
            out[16 + b] = 1.0f / (1.0f + expf(-logit));
        } else {
            out[b] = logit;
        }
    }
}

// ---------------------------------------------------------------------------
// Host launcher (no statics, no caching: symbol lookups every call;
// they are cheap, capture-safe, and allocation-free)
// ---------------------------------------------------------------------------
extern "C" void kernel_launch(void* const* d_in, const int* in_sizes, int n_in,
                              void* d_out, int out_size)
{
    const float* x        = (const float*)d_in[0];
    const int*   fid      = (const int*)  d_in[1];
    const float* ir_w1    = (const float*)d_in[2];
    const float* ir_b1    = (const float*)d_in[3];
    const float* ir_w2    = (const float*)d_in[4];
    const float* ir_b2    = (const float*)d_in[5];
    const float* p2m_w    = (const float*)d_in[6];
    const float* p2m_b    = (const float*)d_in[7];
    const float* freq_emb = (const float*)d_in[8];
    const float* ln1_g    = (const float*)d_in[9];
    const float* ln1_b    = (const float*)d_in[10];
    const float* qkv_w    = (const float*)d_in[11];
    const float* qkv_b    = (const float*)d_in[12];
    const float* out_w    = (const float*)d_in[13];
    const float* out_b    = (const float*)d_in[14];
    const float* ln2_g    = (const float*)d_in[15];
    const float* ln2_b    = (const float*)d_in[16];
    const float* gate_w   = (const float*)d_in[17];
    const float* gate_b   = (const float*)d_in[18];
    const float* exp_w1   = (const float*)d_in[19];
    const float* exp_b1   = (const float*)d_in[20];
    const float* exp_w2   = (const float*)d_in[21];
    const float* exp_b2   = (const float*)d_in[22];
    const float* fn_g     = (const float*)d_in[23];
    const float* fn_b     = (const float*)d_in[24];
    const float* head_g   = (const float*)d_in[25];
    const float* head_b   = (const float*)d_in[26];
    const float* head_w   = (const float*)d_in[27];
    const float* head_bias= (const float*)d_in[28];

    float *patches, *tmp, *hp, *h, *hn, *qkv, *attn, *eh, *wgt;
    cudaGetSymbolAddress((void**)&patches, g_patches);
    cudaGetSymbolAddress((void**)&tmp,     g_tmp);
    cudaGetSymbolAddress((void**)&hp,      g_hp);
    cudaGetSymbolAddress((void**)&h,       g_h);
    cudaGetSymbolAddress((void**)&hn,      g_hn);
    cudaGetSymbolAddress((void**)&qkv,     g_qkv);
    cudaGetSymbolAddress((void**)&attn,    g_attn);
    cudaGetSymbolAddress((void**)&eh,      g_eh);
    cudaGetSymbolAddress((void**)&wgt,     g_wgt);

    // Front end: patch instance-norm -> residual MLP -> p2m -> +freq_emb
    patchnorm_kernel<<<256, 256>>>(x, patches);
    gemm_k<1><<<dim3(8, 32),  256>>>(patches, ir_w1, ir_b1, tmp, T_TOK, 512, 128, nullptr, nullptr);
    gemm_k<2><<<dim3(2, 32),  256>>>(tmp, ir_w2, ir_b2, hp, T_TOK, 128, 512, patches, nullptr);
    gemm_k<0><<<dim3(8, 32),  256>>>(hp, p2m_w, p2m_b, h, T_TOK, 512, 128, nullptr, nullptr);
    freqadd_kernel<<<(T_TOK * 512) / 256, 256>>>(h, freq_emb, fid);

    for (int l = 0; l < 12; l++) {
        // attention block
        ln512_kernel<<<256, 256>>>(h, hn, ln1_g + (size_t)l * 512, ln1_b + (size_t)l * 512);
        gemm_k<0><<<dim3(24, 32), 256>>>(hn, qkv_w + (size_t)l * 512 * 1536,
                                         qkv_b + (size_t)l * 1536, qkv,
                                         T_TOK, 1536, 512, nullptr, nullptr);
        attn_kernel<<<2048, 256>>>(qkv, attn);
        gemm_k<3><<<dim3(8, 32), 256>>>(attn, out_w + (size_t)l * 512 * 512,
                                        out_b + (size_t)l * 512, h,
                                        T_TOK, 512, 512, nullptr, nullptr);
        // MoE block
        ln512_kernel<<<256, 256>>>(h, hn, ln2_g + (size_t)l * 512, ln2_b + (size_t)l * 512);
        gate_kernel<<<256, 256>>>(hn, gate_w + (size_t)l * 512 * 4, gate_b + (size_t)l * 4, wgt);
        for (int e = 0; e < 4; e++) {
            const size_t le = (size_t)(l * 4 + e);
            gemm_k<1><<<dim3(32, 32), 256>>>(hn, exp_w1 + le * 512 * 2048,
                                             exp_b1 + le * 2048, eh,
                                             T_TOK, 2048, 512, nullptr, nullptr);
            gemm_k<4><<<dim3(8, 32), 256>>>(eh, exp_w2 + le * 2048 * 512,
                                            exp_b2 + le * 512, h,
                                            T_TOK, 512, 2048, nullptr, wgt + e);
        }
    }

    head_kernel<<<1, 512>>>(h, fn_g, fn_b, head_g, head_b, head_w, head_bias,
                            (float*)d_out, out_size);
}

// round 3
// speedup vs baseline: 1.2878x; 1.2878x over previous
#include <cuda_runtime.h>
#include <math.h>

// ---------------------------------------------------------------------------
// B=16, S=2048, C=8, P=16 -> N=128 patches, T=2048 tokens
// PD=128, IRH=512, D=512, NH=8, dh=64, L=12, E=4, H=2048, top-2 routing
// ---------------------------------------------------------------------------
#define T_TOK 2048
#define DIM   512
#define HDIM  2048

__device__ float g_patches[T_TOK * 128];
__device__ float g_tmp    [T_TOK * 512];
__device__ float g_hp     [T_TOK * 128];
__device__ float g_h      [T_TOK * DIM];
__device__ float g_hn     [T_TOK * DIM];
__device__ float g_qkv    [T_TOK * 3 * DIM];
__device__ float g_attn   [T_TOK * DIM];
__device__ float g_eh     [4 * T_TOK * HDIM];   // per-expert compact hidden
__device__ int   g_cnt    [4];
__device__ int   g_idx    [4 * T_TOK];          // compact slot -> token
__device__ float g_rw     [4 * T_TOK];          // compact slot -> combine weight

// ---------------------------------------------------------------------------
// Tiled SGEMM, 128x64 tile, BK=16, 256 threads, 8x4 per thread,
// double-buffered smem with register prefetch.
// EPI: 0 store, 1 gelu, 2 res+v, 3 C+=v, 5 scatter: C[idx[row]] += rw[row]*v
// GA: gather A rows through idx. GUARD: live-row count from *cntp.
// ---------------------------------------------------------------------------
template<int EPI, bool GA, bool GUARD>
__global__ void __launch_bounds__(256) gemm_k(
    const float* __restrict__ A, const float* __restrict__ B,
    const float* __restrict__ bias, float* __restrict__ C,
    int M, int N, int K,
    const float* __restrict__ res,
    const int* __restrict__ idx,
    const float* __restrict__ rowscale,
    const int* __restrict__ cntp)
{
    __shared__ float As[2][16][128];
    __shared__ float Bs[2][16][64];
    const int t  = threadIdx.x;
    const int m0 = blockIdx.y * 128, n0 = blockIdx.x * 64;

    int cnt = M;
    if (GUARD) { cnt = *cntp; if (m0 >= cnt) return; }

    // loader coords
    const int lrow = t >> 1, lk = (t & 1) * 8;     // A: 128 rows x 16k, 8 floats/thread
    const int brow = t >> 4, bcol = (t & 15) * 4;  // B: 16 rows x 64 cols
    // compute coords
    const int tx = t & 15, ty = t >> 4;

    const int arow = m0 + lrow;
    int garow;
    if (GA)         garow = (arow < cnt) ? idx[arow] : 0;
    else            garow = arow;
    const float* Ap = A + (size_t)garow * K + lk;
    const float* Bp = B + (size_t)brow * N + n0 + bcol;

    float4 pa0 = *(const float4*)(Ap);
    float4 pa1 = *(const float4*)(Ap + 4);
    float4 pb  = *(const float4*)(Bp);

    int buf = 0;
    As[0][lk + 0][lrow] = pa0.x; As[0][lk + 1][lrow] = pa0.y;
    As[0][lk + 2][lrow] = pa0.z; As[0][lk + 3][lrow] = pa0.w;
    As[0][lk + 4][lrow] = pa1.x; As[0][lk + 5][lrow] = pa1.y;
    As[0][lk + 6][lrow] = pa1.z; As[0][lk + 7][lrow] = pa1.w;
    *(float4*)&Bs[0][brow][bcol] = pb;
    __syncthreads();

    float acc[8][4] = {};

    for (int k0 = 16; k0 <= K; k0 += 16) {
        const bool more = (k0 < K);
        if (more) {
            pa0 = *(const float4*)(Ap + k0);
            pa1 = *(const float4*)(Ap + k0 + 4);
            pb  = *(const float4*)(Bp + (size_t)k0 * N);
        }
        #pragma unroll
        for (int k = 0; k < 16; k++) {
            float4 x0 = *(const float4*)&As[buf][k][ty * 8];
            float4 x1 = *(const float4*)&As[buf][k][ty * 8 + 4];
            float4 y  = *(const float4*)&Bs[buf][k][tx * 4];
            float a8[8] = {x0.x, x0.y, x0.z, x0.w, x1.x, x1.y, x1.z, x1.w};
            float b4[4] = {y.x, y.y, y.z, y.w};
            #pragma unroll
            for (int i = 0; i < 8; i++)
                #pragma unroll
                for (int j = 0; j < 4; j++)
                    acc[i][j] += a8[i] * b4[j];
        }
        if (more) {
            const int nb = buf ^ 1;
            As[nb][lk + 0][lrow] = pa0.x; As[nb][lk + 1][lrow] = pa0.y;
            As[nb][lk + 2][lrow] = pa0.z; As[nb][lk + 3][lrow] = pa0.w;
            As[nb][lk + 4][lrow] = pa1.x; As[nb][lk + 5][lrow] = pa1.y;
            As[nb][lk + 6][lrow] = pa1.z; As[nb][lk + 7][lrow] = pa1.w;
            *(float4*)&Bs[nb][brow][bcol] = pb;
            buf = nb;
            __syncthreads();
        }
    }

    #pragma unroll
    for (int i = 0; i < 8; i++) {
        const int row = m0 + ty * 8 + i;
        if (GUARD && row >= cnt) break;
        #pragma unroll
        for (int j = 0; j < 4; j++) {
            const int col = n0 + tx * 4 + j;
            float v = acc[i][j] + bias[col];
            const size_t cix = (size_t)row * N + col;
            if (EPI == 0)      C[cix] = v;
            else if (EPI == 1) C[cix] = 0.5f * v * (1.0f + erff(v * 0.70710678118654752f));
            else if (EPI == 2) C[cix] = res[cix] + v;
            else if (EPI == 3) C[cix] += v;
            else if (EPI == 5) C[(size_t)idx[row] * N + col] += rowscale[row] * v;
        }
    }
}

// ---------------------------------------------------------------------------
// Instance norm over 128-float patches (eps 1e-6). One warp per patch.
// ---------------------------------------------------------------------------
__global__ void patchnorm_kernel(const float* __restrict__ x, float* __restrict__ y)
{
    const int warp = threadIdx.x >> 5, lane = threadIdx.x & 31;
    const int row = blockIdx.x * 8 + warp;
    const float* xr = x + (size_t)row * 128;
    float4 f = *(const float4*)(xr + lane * 4);
    float s = f.x + f.y + f.z + f.w;
    #pragma unroll
    for (int o = 16; o; o >>= 1) s += __shfl_xor_sync(0xffffffffu, s, o);
    const float mu = s * (1.0f / 128.0f);
    float q = (f.x - mu) * (f.x - mu) + (f.y - mu) * (f.y - mu)
            + (f.z - mu) * (f.z - mu) + (f.w - mu) * (f.w - mu);
    #pragma unroll
    for (int o = 16; o; o >>= 1) q += __shfl_xor_sync(0xffffffffu, q, o);
    const float rs = rsqrtf(q * (1.0f / 128.0f) + 1e-6f);
    float4 r = make_float4((f.x - mu) * rs, (f.y - mu) * rs, (f.z - mu) * rs, (f.w - mu) * rs);
    *(float4*)(y + (size_t)row * 128 + lane * 4) = r;
}

// ---------------------------------------------------------------------------
// LayerNorm over D=512 (eps 1e-5). One warp per row, 8 rows per block.
// ---------------------------------------------------------------------------
__global__ void ln512_kernel(const float* __restrict__ x, float* __restrict__ y,
                             const float* __restrict__ g, const float* __restrict__ b)
{
    const int warp = threadIdx.x >> 5, lane = threadIdx.x & 31;
    const int row = blockIdx.x * 8 + warp;
    const float* xr = x + (size_t)row * 512;
    float v[16];
    float s = 0.f;
    #pragma unroll
    for (int c = 0; c < 4; c++) {
        float4 f = *(const float4*)(xr + c * 128 + lane * 4);
        v[c * 4 + 0] = f.x; v[c * 4 + 1] = f.y; v[c * 4 + 2] = f.z; v[c * 4 + 3] = f.w;
        s += f.x + f.y + f.z + f.w;
    }
    #pragma unroll
    for (int o = 16; o; o >>= 1) s += __shfl_xor_sync(0xffffffffu, s, o);
    const float mu = s * (1.0f / 512.0f);
    float q = 0.f;
    #pragma unroll
    for (int k = 0; k < 16; k++) { float d = v[k] - mu; q += d * d; }
    #pragma unroll
    for (int o = 16; o; o >>= 1) q += __shfl_xor_sync(0xffffffffu, q, o);
    const float rs = rsqrtf(q * (1.0f / 512.0f) + 1e-5f);
    #pragma unroll
    for (int c = 0; c < 4; c++) {
        const int col = c * 128 + lane * 4;
        float4 gg = *(const float4*)(g + col);
        float4 bb = *(const float4*)(b + col);
        float4 r;
        r.x = gg.x * (v[c * 4 + 0] - mu) * rs + bb.x;
        r.y = gg.y * (v[c * 4 + 1] - mu) * rs + bb.y;
        r.z = gg.z * (v[c * 4 + 2] - mu) * rs + bb.z;
        r.w = gg.w * (v[c * 4 + 3] - mu) * rs + bb.w;
        *(float4*)(y + (size_t)row * 512 + col) = r;
    }
}

__global__ void freqadd_kernel(float* __restrict__ h, const float* __restrict__ emb,
                               const int* __restrict__ fid)
{
    const int i = blockIdx.x * 256 + threadIdx.x;
    const int row = i >> 9, d = i & 511, b = row >> 7;
    h[i] += emb[(size_t)fid[b] * 512 + d];
}

// ---------------------------------------------------------------------------
// Causal attention, NH=8, dh=64, n=128. One warp per (b, head, query row).
// ---------------------------------------------------------------------------
__global__ void attn_kernel(const float* __restrict__ qkv, float* __restrict__ o)
{
    const int gw = blockIdx.x * 8 + (threadIdx.x >> 5);
    const int lane = threadIdx.x & 31;
    const int i = gw & 127, hh = (gw >> 7) & 7, b = gw >> 10;
    const float* base = qkv + (size_t)b * 128 * 1536;
    const float* qp = base + (size_t)i * 1536 + hh * 64 + lane * 2;
    const float qx = qp[0], qy = qp[1];
    const float* kp = base + 512  + hh * 64 + lane * 2;
    const float* vp = base + 1024 + hh * 64 + lane * 2;
    float m = -1e30f, l = 0.f, ox = 0.f, oy = 0.f;
    for (int j = 0; j <= i; j++) {
        float2 k2 = *(const float2*)(kp + (size_t)j * 1536);
        float p = qx * k2.x + qy * k2.y;
        #pragma unroll
        for (int off = 16; off; off >>= 1) p += __shfl_xor_sync(0xffffffffu, p, off);
        const float s = p * 0.125f;
        const float nm = fmaxf(m, s);
        const float sc = __expf(m - nm), e = __expf(s - nm);
        l = l * sc + e;
        float2 v2 = *(const float2*)(vp + (size_t)j * 1536);
        ox = ox * sc + e * v2.x;
        oy = oy * sc + e * v2.y;
        m = nm;
    }
    const float inv = 1.0f / l;
    float* op = o + ((size_t)b * 128 + i) * 512 + hh * 64 + lane * 2;
    op[0] = ox * inv; op[1] = oy * inv;
}

__global__ void zero_cnt_kernel(int* cnt)
{
    if (threadIdx.x < 4) cnt[threadIdx.x] = 0;
}

// ---------------------------------------------------------------------------
// Gate + top-2 routing: softmax over E=4, compact per-expert token lists.
// One warp per token. Slot order nondeterministic; output values are not.
// ---------------------------------------------------------------------------
__global__ void gate_route_kernel(const float* __restrict__ hn, const float* __restrict__ gw,
                                  const float* __restrict__ gb,
                                  int* __restrict__ cnt, int* __restrict__ idx,
                                  float* __restrict__ rw)
{
    const int warp = threadIdx.x >> 5, lane = threadIdx.x & 31;
    const int row = blockIdx.x * 8 + warp;
    const float* xr = hn + (size_t)row * 512;
    float a0 = 0.f, a1 = 0.f, a2 = 0.f, a3 = 0.f;
    for (int d = lane; d < 512; d += 32) {
        const float hv = xr[d];
        float4 w = *(const float4*)(gw + (size_t)d * 4);
        a0 += hv * w.x; a1 += hv * w.y; a2 += hv * w.z; a3 += hv * w.w;
    }
    #pragma unroll
    for (int o = 16; o; o >>= 1) {
        a0 += __shfl_xor_sync(0xffffffffu, a0, o);
        a1 += __shfl_xor_sync(0xffffffffu, a1, o);
        a2 += __shfl_xor_sync(0xffffffffu, a2, o);
        a3 += __shfl_xor_sync(0xffffffffu, a3, o);
    }
    if (lane == 0) {
        float p[4] = {a0 + gb[0], a1 + gb[1], a2 + gb[2], a3 + gb[3]};
        const float mx = fmaxf(fmaxf(p[0], p[1]), fmaxf(p[2], p[3]));
        float s = 0.f;
        #pragma unroll
        for (int e = 0; e < 4; e++) { p[e] = expf(p[e] - mx); s += p[e]; }
        const float invs = 1.0f / s;
        #pragma unroll
        for (int e = 0; e < 4; e++) p[e] *= invs;
        int i0 = 0;
        #pragma unroll
        for (int e = 1; e < 4; e++) if (p[e] > p[i0]) i0 = e;
        int i1 = -1;
        #pragma unroll
        for (int e = 0; e < 4; e++) if (e != i0 && (i1 < 0 || p[e] > p[i1])) i1 = e;
        int s0 = atomicAdd(&cnt[i0], 1);
        idx[i0 * T_TOK + s0] = row; rw[i0 * T_TOK + s0] = p[i0];
        int s1 = atomicAdd(&cnt[i1], 1);
        idx[i1 * T_TOK + s1] = row; rw[i1 * T_TOK + s1] = p[i1];
    }
}

// ---------------------------------------------------------------------------
// Head: token 127 of each batch -> LN(fn) -> LN(head) -> dot. Warp per batch.
// ---------------------------------------------------------------------------
__global__ void head_kernel(const float* __restrict__ h,
                            const float* __restrict__ fng, const float* __restrict__ fnb,
                            const float* __restrict__ hg,  const float* __restrict__ hb,
                            const float* __restrict__ hw,  const float* __restrict__ hbias,
                            float* __restrict__ out, int out_size)
{
    const int warp = threadIdx.x >> 5, lane = threadIdx.x & 31;
    const int b = warp;
    const float* xr = h + ((size_t)b * 128 + 127) * 512;
    float v[16];
    float s = 0.f;
    #pragma unroll
    for (int c = 0; c < 4; c++) {
        float4 f = *(const float4*)(xr + c * 128 + lane * 4);
        v[c * 4 + 0] = f.x; v[c * 4 + 1] = f.y; v[c * 4 + 2] = f.z; v[c * 4 + 3] = f.w;
        s += f.x + f.y + f.z + f.w;
    }
    #pragma unroll
    for (int o = 16; o; o >>= 1) s += __shfl_xor_sync(0xffffffffu, s, o);
    float mu = s * (1.0f / 512.0f);
    float q = 0.f;
    #pragma unroll
    for (int k = 0; k < 16; k++) { float d = v[k] - mu; q += d * d; }
    #pragma unroll
    for (int o = 16; o; o >>= 1) q += __shfl_xor_sync(0xffffffffu, q, o);
    float rs = rsqrtf(q * (1.0f / 512.0f) + 1e-5f);
    #pragma unroll
    for (int c = 0; c < 4; c++)
        #pragma unroll
        for (int j = 0; j < 4; j++) {
            const int col = c * 128 + lane * 4 + j;
            v[c * 4 + j] = fng[col] * (v[c * 4 + j] - mu) * rs + fnb[col];
        }
    s = 0.f;
    #pragma unroll
    for (int k = 0; k < 16; k++) s += v[k];
    #pragma unroll
    for (int o = 16; o; o >>= 1) s += __shfl_xor_sync(0xffffffffu, s, o);
    mu = s * (1.0f / 512.0f);
    q = 0.f;
    #pragma unroll
    for (int k = 0; k < 16; k++) { float d = v[k] - mu; q += d * d; }
    #pragma unroll
    for (int o = 16; o; o >>= 1) q += __shfl_xor_sync(0xffffffffu, q, o);
    rs = rsqrtf(q * (1.0f / 512.0f) + 1e-5f);
    float dot = 0.f;
    #pragma unroll
    for (int c = 0; c < 4; c++)
        #pragma unroll
        for (int j = 0; j < 4; j++) {
            const int col = c * 128 + lane * 4 + j;
            const float hl = hg[col] * (v[c * 4 + j] - mu) * rs + hb[col];
            dot += hl * hw[col];
        }
    #pragma unroll
    for (int o = 16; o; o >>= 1) dot += __shfl_xor_sync(0xffffffffu, dot, o);
    if (lane == 0) {
        const float logit = dot + hbias[0];
        if (out_size >= 32) {
            out[b] = logit;
            out[16 + b] = 1.0f / (1.0f + expf(-logit));
        } else {
            out[b] = logit;
        }
    }
}

// ---------------------------------------------------------------------------
// Host launcher
// ---------------------------------------------------------------------------
extern "C" void kernel_launch(void* const* d_in, const int* in_sizes, int n_in,
                              void* d_out, int out_size)
{
    const float* x        = (const float*)d_in[0];
    const int*   fid      = (const int*)  d_in[1];
    const float* ir_w1    = (const float*)d_in[2];
    const float* ir_b1    = (const float*)d_in[3];
    const float* ir_w2    = (const float*)d_in[4];
    const float* ir_b2    = (const float*)d_in[5];
    const float* p2m_w    = (const float*)d_in[6];
    const float* p2m_b    = (const float*)d_in[7];
    const float* freq_emb = (const float*)d_in[8];
    const float* ln1_g    = (const float*)d_in[9];
    const float* ln1_b    = (const float*)d_in[10];
    const float* qkv_w    = (const float*)d_in[11];
    const float* qkv_b    = (const float*)d_in[12];
    const float* out_w    = (const float*)d_in[13];
    const float* out_b    = (const float*)d_in[14];
    const float* ln2_g    = (const float*)d_in[15];
    const float* ln2_b    = (const float*)d_in[16];
    const float* gate_w   = (const float*)d_in[17];
    const float* gate_b   = (const float*)d_in[18];
    const float* exp_w1   = (const float*)d_in[19];
    const float* exp_b1   = (const float*)d_in[20];
    const float* exp_w2   = (const float*)d_in[21];
    const float* exp_b2   = (const float*)d_in[22];
    const float* fn_g     = (const float*)d_in[23];
    const float* fn_b     = (const float*)d_in[24];
    const float* head_g   = (const float*)d_in[25];
    const float* head_b   = (const float*)d_in[26];
    const float* head_w   = (const float*)d_in[27];
    const float* head_bias= (const float*)d_in[28];

    float *patches, *tmp, *hp, *h, *hn, *qkv, *attn, *eh, *rw;
    int *cnt, *idx;
    cudaGetSymbolAddress((void**)&patches, g_patches);
    cudaGetSymbolAddress((void**)&tmp,     g_tmp);
    cudaGetSymbolAddress((void**)&hp,      g_hp);
    cudaGetSymbolAddress((void**)&h,       g_h);
    cudaGetSymbolAddress((void**)&hn,      g_hn);
    cudaGetSymbolAddress((void**)&qkv,     g_qkv);
    cudaGetSymbolAddress((void**)&attn,    g_attn);
    cudaGetSymbolAddress((void**)&eh,      g_eh);
    cudaGetSymbolAddress((void**)&cnt,     g_cnt);
    cudaGetSymbolAddress((void**)&idx,     g_idx);
    cudaGetSymbolAddress((void**)&rw,      g_rw);

    // Front end
    patchnorm_kernel<<<256, 256>>>(x, patches);
    gemm_k<1,false,false><<<dim3(8, 16),  256>>>(patches, ir_w1, ir_b1, tmp,
        T_TOK, 512, 128, nullptr, nullptr, nullptr, nullptr);
    gemm_k<2,false,false><<<dim3(2, 16),  256>>>(tmp, ir_w2, ir_b2, hp,
        T_TOK, 128, 512, patches, nullptr, nullptr, nullptr);
    gemm_k<0,false,false><<<dim3(8, 16),  256>>>(hp, p2m_w, p2m_b, h,
        T_TOK, 512, 128, nullptr, nullptr, nullptr, nullptr);
    freqadd_kernel<<<(T_TOK * 512) / 256, 256>>>(h, freq_emb, fid);

    for (int l = 0; l < 12; l++) {
        // attention
        ln512_kernel<<<256, 256>>>(h, hn, ln1_g + (size_t)l * 512, ln1_b + (size_t)l * 512);
        gemm_k<0,false,false><<<dim3(24, 16), 256>>>(hn,
            qkv_w + (size_t)l * 512 * 1536, qkv_b + (size_t)l * 1536, qkv,
            T_TOK, 1536, 512, nullptr, nullptr, nullptr, nullptr);
        attn_kernel<<<2048, 256>>>(qkv, attn);
        gemm_k<3,false,false><<<dim3(8, 16), 256>>>(attn,
            out_w + (size_t)l * 512 * 512, out_b + (size_t)l * 512, h,
            T_TOK, 512, 512, nullptr, nullptr, nullptr, nullptr);
        // sparse MoE
        ln512_kernel<<<256, 256>>>(h, hn, ln2_g + (size_t)l * 512, ln2_b + (size_t)l * 512);
        zero_cnt_kernel<<<1, 32>>>(cnt);
        gate_route_kernel<<<256, 256>>>(hn, gate_w + (size_t)l * 512 * 4,
                                        gate_b + (size_t)l * 4, cnt, idx, rw);
        for (int e = 0; e < 4; e++) {
            const size_t le = (size_t)(l * 4 + e);
            gemm_k<1,true,true><<<dim3(32, 16), 256>>>(hn,
                exp_w1 + le * 512 * 2048, exp_b1 + le * 2048,
                eh + (size_t)e * T_TOK * HDIM,
                T_TOK, 2048, 512, nullptr, idx + e * T_TOK, nullptr, cnt + e);
            gemm_k<5,false,true><<<dim3(8, 16), 256>>>(eh + (size_t)e * T_TOK * HDIM,
                exp_w2 + le * 2048 * 512, exp_b2 + le * 512, h,
                T_TOK, 512, 2048, nullptr, idx + e * T_TOK, rw + e * T_TOK, cnt + e);
        }
    }

    head_kernel<<<1, 512>>>(h, fn_g, fn_b, head_g, head_b, head_w, head_bias,
                            (float*)d_out, out_size);
}

// round 4
// speedup vs baseline: 1.7718x; 1.3758x over previous
#include <cuda_runtime.h>
#include <math.h>

// ---------------------------------------------------------------------------
// B=16, S=2048, C=8, P=16 -> N=128 patches, T=2048 tokens
// PD=128, IRH=512, D=512, NH=8, dh=64, L=12, E=4, H=2048, top-2 routing
// ---------------------------------------------------------------------------
#define T_TOK 2048
#define DIM   512
#define HDIM  2048

__device__ float g_patches[T_TOK * 128];
__device__ float g_tmp    [T_TOK * 512];
__device__ float g_hp     [T_TOK * 128];
__device__ float g_h      [T_TOK * DIM];
__device__ float g_hn     [T_TOK * DIM];
__device__ float g_qkv    [T_TOK * 3 * DIM];
__device__ float g_attn   [T_TOK * DIM];
__device__ float g_eh     [4 * T_TOK * HDIM];
__device__ int   g_cnt    [4];
__device__ int   g_idx    [4 * T_TOK];
__device__ float g_rw     [4 * T_TOK];

// ---- packed f32x2 helpers (sm_100+) ---------------------------------------
__device__ __forceinline__ unsigned long long pk2(float x, float y) {
    unsigned long long r;
    asm("mov.b64 %0, {%1, %2};" : "=l"(r) : "f"(x), "f"(y));
    return r;
}
__device__ __forceinline__ void fma2(unsigned long long& d,
                                     unsigned long long a, unsigned long long b) {
    asm("fma.rn.f32x2 %0, %1, %2, %0;" : "+l"(d) : "l"(a), "l"(b));
}
__device__ __forceinline__ float2 upk(unsigned long long v) {
    float2 r;
    asm("mov.b64 {%0, %1}, %2;" : "=f"(r.x), "=f"(r.y) : "l"(v));
    return r;
}

// ---------------------------------------------------------------------------
// SGEMM via FFMA2: 128x128 tile, BK=16, 256 threads, 8x8 per thread,
// double-buffered smem, conflict-free split-half LDS.
// EPI: 0 store, 1 gelu, 2 res+v, 3 C+=v, 5 atomic scatter C[idx[r]] += rw[r]*v
// GA: gather A rows via idx. GUARD: live rows from *cnt. EXPZ: blockIdx.z expert
// ---------------------------------------------------------------------------
template<int EPI, bool GA, bool GUARD, bool EXPZ>
__global__ void __launch_bounds__(256, 2) gemm2(
    const float* __restrict__ A, const float* __restrict__ B,
    const float* __restrict__ bias, float* __restrict__ C,
    int M, int N, int K,
    const float* __restrict__ res,
    const int* __restrict__ idx,
    const float* __restrict__ rw,
    const int* __restrict__ cnt,
    size_t zA, size_t zC)
{
    __shared__ float As[2][16][128];
    __shared__ float Bs[2][16][128];

    if (EXPZ) {
        const int z = blockIdx.z;
        A    += (size_t)z * zA;
        B    += (size_t)z * K * N;
        bias += (size_t)z * N;
        C    += (size_t)z * zC;
        idx  += z * T_TOK;
        if (rw) rw += z * T_TOK;
        cnt  += z;
    }

    const int t  = threadIdx.x;
    const int m0 = blockIdx.y * 128, n0 = blockIdx.x * 128;

    int cq = M;
    if (GUARD) { cq = *cnt; if (m0 >= cq) return; }

    // loaders
    const int lrow = t & 127, lk = (t >> 7) * 8;    // A: row, k-half
    const int brow = t >> 4,  bcol = (t & 15) * 8;  // B: k-row, col
    // compute
    const int tx = t & 15, ty = t >> 4;

    int garow = m0 + lrow;
    if (GA) garow = (garow < cq) ? idx[garow] : idx[0];
    const float* Ap = A + (size_t)garow * K + lk;
    const float* Bp = B + (size_t)brow * N + n0 + bcol;

    float4 pa0 = *(const float4*)(Ap);
    float4 pa1 = *(const float4*)(Ap + 4);
    float4 pb0 = *(const float4*)(Bp);
    float4 pb1 = *(const float4*)(Bp + 4);

    int buf = 0;
    As[0][lk + 0][lrow] = pa0.x; As[0][lk + 1][lrow] = pa0.y;
    As[0][lk + 2][lrow] = pa0.z; As[0][lk + 3][lrow] = pa0.w;
    As[0][lk + 4][lrow] = pa1.x; As[0][lk + 5][lrow] = pa1.y;
    As[0][lk + 6][lrow] = pa1.z; As[0][lk + 7][lrow] = pa1.w;
    *(float4*)&Bs[0][brow][bcol]     = pb0;
    *(float4*)&Bs[0][brow][bcol + 4] = pb1;
    __syncthreads();

    unsigned long long acc[8][4];
    #pragma unroll
    for (int i = 0; i < 8; i++)
        #pragma unroll
        for (int j = 0; j < 4; j++) acc[i][j] = 0ull;

    for (int k0 = 16; k0 <= K; k0 += 16) {
        const bool more = (k0 < K);
        if (more) {
            pa0 = *(const float4*)(Ap + k0);
            pa1 = *(const float4*)(Ap + k0 + 4);
            pb0 = *(const float4*)(Bp + (size_t)k0 * N);
            pb1 = *(const float4*)(Bp + (size_t)k0 * N + 4);
        }
        #pragma unroll
        for (int k = 0; k < 16; k++) {
            float4 a0v = *(const float4*)&As[buf][k][ty * 4];
            float4 a1v = *(const float4*)&As[buf][k][64 + ty * 4];
            float4 b0v = *(const float4*)&Bs[buf][k][tx * 4];
            float4 b1v = *(const float4*)&Bs[buf][k][64 + tx * 4];
            unsigned long long B4[4] = {
                pk2(b0v.x, b0v.y), pk2(b0v.z, b0v.w),
                pk2(b1v.x, b1v.y), pk2(b1v.z, b1v.w)
            };
            float a8[8] = {a0v.x, a0v.y, a0v.z, a0v.w,
                           a1v.x, a1v.y, a1v.z, a1v.w};
            #pragma unroll
            for (int i = 0; i < 8; i++) {
                unsigned long long Ad = pk2(a8[i], a8[i]);
                #pragma unroll
                for (int j = 0; j < 4; j++) fma2(acc[i][j], Ad, B4[j]);
            }
        }
        if (more) {
            const int nb = buf ^ 1;
            As[nb][lk + 0][lrow] = pa0.x; As[nb][lk + 1][lrow] = pa0.y;
            As[nb][lk + 2][lrow] = pa0.z; As[nb][lk + 3][lrow] = pa0.w;
            As[nb][lk + 4][lrow] = pa1.x; As[nb][lk + 5][lrow] = pa1.y;
            As[nb][lk + 6][lrow] = pa1.z; As[nb][lk + 7][lrow] = pa1.w;
            *(float4*)&Bs[nb][brow][bcol]     = pb0;
            *(float4*)&Bs[nb][brow][bcol + 4] = pb1;
            buf = nb;
            __syncthreads();
        }
    }

    #pragma unroll
    for (int i = 0; i < 8; i++) {
        const int row = m0 + ((i < 4) ? (ty * 4 + i) : (64 + ty * 4 + i - 4));
        if (GUARD && row >= cq) continue;
        #pragma unroll
        for (int j = 0; j < 4; j++) {
            const int col = n0 + ((j < 2) ? (tx * 4 + j * 2) : (64 + tx * 4 + (j - 2) * 2));
            float2 v = upk(acc[i][j]);
            v.x += bias[col];
            v.y += bias[col + 1];
            const size_t cix = (size_t)row * N + col;
            if (EPI == 0) {
                *(float2*)&C[cix] = v;
            } else if (EPI == 1) {
                v.x = 0.5f * v.x * (1.0f + erff(v.x * 0.70710678118654752f));
                v.y = 0.5f * v.y * (1.0f + erff(v.y * 0.70710678118654752f));
                *(float2*)&C[cix] = v;
            } else if (EPI == 2) {
                float2 r = *(const float2*)&res[cix];
                v.x += r.x; v.y += r.y;
                *(float2*)&C[cix] = v;
            } else if (EPI == 3) {
                float2 c = *(const float2*)&C[cix];
                v.x += c.x; v.y += c.y;
                *(float2*)&C[cix] = v;
            } else if (EPI == 5) {
                const float w = rw[row];
                float* dst = C + (size_t)idx[row] * N + col;
                atomicAdd(dst,     w * v.x);
                atomicAdd(dst + 1, w * v.y);
            }
        }
    }
}

// ---------------------------------------------------------------------------
__global__ void patchnorm_kernel(const float* __restrict__ x, float* __restrict__ y)
{
    const int warp = threadIdx.x >> 5, lane = threadIdx.x & 31;
    const int row = blockIdx.x * 8 + warp;
    const float* xr = x + (size_t)row * 128;
    float4 f = *(const float4*)(xr + lane * 4);
    float s = f.x + f.y + f.z + f.w;
    #pragma unroll
    for (int o = 16; o; o >>= 1) s += __shfl_xor_sync(0xffffffffu, s, o);
    const float mu = s * (1.0f / 128.0f);
    float q = (f.x - mu) * (f.x - mu) + (f.y - mu) * (f.y - mu)
            + (f.z - mu) * (f.z - mu) + (f.w - mu) * (f.w - mu);
    #pragma unroll
    for (int o = 16; o; o >>= 1) q += __shfl_xor_sync(0xffffffffu, q, o);
    const float rs = rsqrtf(q * (1.0f / 128.0f) + 1e-6f);
    float4 r = make_float4((f.x - mu) * rs, (f.y - mu) * rs, (f.z - mu) * rs, (f.w - mu) * rs);
    *(float4*)(y + (size_t)row * 128 + lane * 4) = r;
}

__global__ void ln512_kernel(const float* __restrict__ x, float* __restrict__ y,
                             const float* __restrict__ g, const float* __restrict__ b)
{
    const int warp = threadIdx.x >> 5, lane = threadIdx.x & 31;
    const int row = blockIdx.x * 8 + warp;
    const float* xr = x + (size_t)row * 512;
    float v[16];
    float s = 0.f;
    #pragma unroll
    for (int c = 0; c < 4; c++) {
        float4 f = *(const float4*)(xr + c * 128 + lane * 4);
        v[c * 4 + 0] = f.x; v[c * 4 + 1] = f.y; v[c * 4 + 2] = f.z; v[c * 4 + 3] = f.w;
        s += f.x + f.y + f.z + f.w;
    }
    #pragma unroll
    for (int o = 16; o; o >>= 1) s += __shfl_xor_sync(0xffffffffu, s, o);
    const float mu = s * (1.0f / 512.0f);
    float q = 0.f;
    #pragma unroll
    for (int k = 0; k < 16; k++) { float d = v[k] - mu; q += d * d; }
    #pragma unroll
    for (int o = 16; o; o >>= 1) q += __shfl_xor_sync(0xffffffffu, q, o);
    const float rs = rsqrtf(q * (1.0f / 512.0f) + 1e-5f);
    #pragma unroll
    for (int c = 0; c < 4; c++) {
        const int col = c * 128 + lane * 4;
        float4 gg = *(const float4*)(g + col);
        float4 bb = *(const float4*)(b + col);
        float4 r;
        r.x = gg.x * (v[c * 4 + 0] - mu) * rs + bb.x;
        r.y = gg.y * (v[c * 4 + 1] - mu) * rs + bb.y;
        r.z = gg.z * (v[c * 4 + 2] - mu) * rs + bb.z;
        r.w = gg.w * (v[c * 4 + 3] - mu) * rs + bb.w;
        *(float4*)(y + (size_t)row * 512 + col) = r;
    }
}

__global__ void freqadd_kernel(float* __restrict__ h, const float* __restrict__ emb,
                               const int* __restrict__ fid)
{
    const int i = blockIdx.x * 256 + threadIdx.x;
    const int row = i >> 9, d = i & 511, b = row >> 7;
    h[i] += emb[(size_t)fid[b] * 512 + d];
}

__global__ void attn_kernel(const float* __restrict__ qkv, float* __restrict__ o)
{
    const int gw = blockIdx.x * 8 + (threadIdx.x >> 5);
    const int lane = threadIdx.x & 31;
    const int i = gw & 127, hh = (gw >> 7) & 7, b = gw >> 10;
    const float* base = qkv + (size_t)b * 128 * 1536;
    const float* qp = base + (size_t)i * 1536 + hh * 64 + lane * 2;
    const float qx = qp[0], qy = qp[1];
    const float* kp = base + 512  + hh * 64 + lane * 2;
    const float* vp = base + 1024 + hh * 64 + lane * 2;
    float m = -1e30f, l = 0.f, ox = 0.f, oy = 0.f;
    for (int j = 0; j <= i; j++) {
        float2 k2 = *(const float2*)(kp + (size_t)j * 1536);
        float p = qx * k2.x + qy * k2.y;
        #pragma unroll
        for (int off = 16; off; off >>= 1) p += __shfl_xor_sync(0xffffffffu, p, off);
        const float s = p * 0.125f;
        const float nm = fmaxf(m, s);
        const float sc = __expf(m - nm), e = __expf(s - nm);
        l = l * sc + e;
        float2 v2 = *(const float2*)(vp + (size_t)j * 1536);
        ox = ox * sc + e * v2.x;
        oy = oy * sc + e * v2.y;
        m = nm;
    }
    const float inv = 1.0f / l;
    float* op = o + ((size_t)b * 128 + i) * 512 + hh * 64 + lane * 2;
    op[0] = ox * inv; op[1] = oy * inv;
}

__global__ void zero_cnt_kernel(int* cnt)
{
    if (threadIdx.x < 4) cnt[threadIdx.x] = 0;
}

__global__ void gate_route_kernel(const float* __restrict__ hn, const float* __restrict__ gw,
                                  const float* __restrict__ gb,
                                  int* __restrict__ cnt, int* __restrict__ idx,
                                  float* __restrict__ rw)
{
    const int warp = threadIdx.x >> 5, lane = threadIdx.x & 31;
    const int row = blockIdx.x * 8 + warp;
    const float* xr = hn + (size_t)row * 512;
    float a0 = 0.f, a1 = 0.f, a2 = 0.f, a3 = 0.f;
    for (int d = lane; d < 512; d += 32) {
        const float hv = xr[d];
        float4 w = *(const float4*)(gw + (size_t)d * 4);
        a0 += hv * w.x; a1 += hv * w.y; a2 += hv * w.z; a3 += hv * w.w;
    }
    #pragma unroll
    for (int o = 16; o; o >>= 1) {
        a0 += __shfl_xor_sync(0xffffffffu, a0, o);
        a1 += __shfl_xor_sync(0xffffffffu, a1, o);
        a2 += __shfl_xor_sync(0xffffffffu, a2, o);
        a3 += __shfl_xor_sync(0xffffffffu, a3, o);
    }
    if (lane == 0) {
        float p[4] = {a0 + gb[0], a1 + gb[1], a2 + gb[2], a3 + gb[3]};
        const float mx = fmaxf(fmaxf(p[0], p[1]), fmaxf(p[2], p[3]));
        float s = 0.f;
        #pragma unroll
        for (int e = 0; e < 4; e++) { p[e] = expf(p[e] - mx); s += p[e]; }
        const float invs = 1.0f / s;
        #pragma unroll
        for (int e = 0; e < 4; e++) p[e] *= invs;
        int i0 = 0;
        #pragma unroll
        for (int e = 1; e < 4; e++) if (p[e] > p[i0]) i0 = e;
        int i1 = -1;
        #pragma unroll
        for (int e = 0; e < 4; e++) if (e != i0 && (i1 < 0 || p[e] > p[i1])) i1 = e;
        int s0 = atomicAdd(&cnt[i0], 1);
        idx[i0 * T_TOK + s0] = row; rw[i0 * T_TOK + s0] = p[i0];
        int s1 = atomicAdd(&cnt[i1], 1);
        idx[i1 * T_TOK + s1] = row; rw[i1 * T_TOK + s1] = p[i1];
    }
}

__global__ void head_kernel(const float* __restrict__ h,
                            const float* __restrict__ fng, const float* __restrict__ fnb,
                            const float* __restrict__ hg,  const float* __restrict__ hb,
                            const float* __restrict__ hw,  const float* __restrict__ hbias,
                            float* __restrict__ out, int out_size)
{
    const int warp = threadIdx.x >> 5, lane = threadIdx.x & 31;
    const int b = warp;
    const float* xr = h + ((size_t)b * 128 + 127) * 512;
    float v[16];
    float s = 0.f;
    #pragma unroll
    for (int c = 0; c < 4; c++) {
        float4 f = *(const float4*)(xr + c * 128 + lane * 4);
        v[c * 4 + 0] = f.x; v[c * 4 + 1] = f.y; v[c * 4 + 2] = f.z; v[c * 4 + 3] = f.w;
        s += f.x + f.y + f.z + f.w;
    }
    #pragma unroll
    for (int o = 16; o; o >>= 1) s += __shfl_xor_sync(0xffffffffu, s, o);
    float mu = s * (1.0f / 512.0f);
    float q = 0.f;
    #pragma unroll
    for (int k = 0; k < 16; k++) { float d = v[k] - mu; q += d * d; }
    #pragma unroll
    for (int o = 16; o; o >>= 1) q += __shfl_xor_sync(0xffffffffu, q, o);
    float rs = rsqrtf(q * (1.0f / 512.0f) + 1e-5f);
    #pragma unroll
    for (int c = 0; c < 4; c++)
        #pragma unroll
        for (int j = 0; j < 4; j++) {
            const int col = c * 128 + lane * 4 + j;
            v[c * 4 + j] = fng[col] * (v[c * 4 + j] - mu) * rs + fnb[col];
        }
    s = 0.f;
    #pragma unroll
    for (int k = 0; k < 16; k++) s += v[k];
    #pragma unroll
    for (int o = 16; o; o >>= 1) s += __shfl_xor_sync(0xffffffffu, s, o);
    mu = s * (1.0f / 512.0f);
    q = 0.f;
    #pragma unroll
    for (int k = 0; k < 16; k++) { float d = v[k] - mu; q += d * d; }
    #pragma unroll
    for (int o = 16; o; o >>= 1) q += __shfl_xor_sync(0xffffffffu, q, o);
    rs = rsqrtf(q * (1.0f / 512.0f) + 1e-5f);
    float dot = 0.f;
    #pragma unroll
    for (int c = 0; c < 4; c++)
        #pragma unroll
        for (int j = 0; j < 4; j++) {
            const int col = c * 128 + lane * 4 + j;
            const float hl = hg[col] * (v[c * 4 + j] - mu) * rs + hb[col];
            dot += hl * hw[col];
        }
    #pragma unroll
    for (int o = 16; o; o >>= 1) dot += __shfl_xor_sync(0xffffffffu, dot, o);
    if (lane == 0) {
        const float logit = dot + hbias[0];
        if (out_size >= 32) {
            out[b] = logit;
            out[16 + b] = 1.0f / (1.0f + expf(-logit));
        } else {
            out[b] = logit;
        }
    }
}

// ---------------------------------------------------------------------------
extern "C" void kernel_launch(void* const* d_in, const int* in_sizes, int n_in,
                              void* d_out, int out_size)
{
    const float* x        = (const float*)d_in[0];
    const int*   fid      = (const int*)  d_in[1];
    const float* ir_w1    = (const float*)d_in[2];
    const float* ir_b1    = (const float*)d_in[3];
    const float* ir_w2    = (const float*)d_in[4];
    const float* ir_b2    = (const float*)d_in[5];
    const float* p2m_w    = (const float*)d_in[6];
    const float* p2m_b    = (const float*)d_in[7];
    const float* freq_emb = (const float*)d_in[8];
    const float* ln1_g    = (const float*)d_in[9];
    const float* ln1_b    = (const float*)d_in[10];
    const float* qkv_w    = (const float*)d_in[11];
    const float* qkv_b    = (const float*)d_in[12];
    const float* out_w    = (const float*)d_in[13];
    const float* out_b    = (const float*)d_in[14];
    const float* ln2_g    = (const float*)d_in[15];
    const float* ln2_b    = (const float*)d_in[16];
    const float* gate_w   = (const float*)d_in[17];
    const float* gate_b   = (const float*)d_in[18];
    const float* exp_w1   = (const float*)d_in[19];
    const float* exp_b1   = (const float*)d_in[20];
    const float* exp_w2   = (const float*)d_in[21];
    const float* exp_b2   = (const float*)d_in[22];
    const float* fn_g     = (const float*)d_in[23];
    const float* fn_b     = (const float*)d_in[24];
    const float* head_g   = (const float*)d_in[25];
    const float* head_b   = (const float*)d_in[26];
    const float* head_w   = (const float*)d_in[27];
    const float* head_bias= (const float*)d_in[28];

    float *patches, *tmp, *hp, *h, *hn, *qkv, *attn, *eh, *rw;
    int *cnt, *idx;
    cudaGetSymbolAddress((void**)&patches, g_patches);
    cudaGetSymbolAddress((void**)&tmp,     g_tmp);
    cudaGetSymbolAddress((void**)&hp,      g_hp);
    cudaGetSymbolAddress((void**)&h,       g_h);
    cudaGetSymbolAddress((void**)&hn,      g_hn);
    cudaGetSymbolAddress((void**)&qkv,     g_qkv);
    cudaGetSymbolAddress((void**)&attn,    g_attn);
    cudaGetSymbolAddress((void**)&eh,      g_eh);
    cudaGetSymbolAddress((void**)&cnt,     g_cnt);
    cudaGetSymbolAddress((void**)&idx,     g_idx);
    cudaGetSymbolAddress((void**)&rw,      g_rw);

    const size_t EHZ = (size_t)T_TOK * HDIM;

    // Front end
    patchnorm_kernel<<<256, 256>>>(x, patches);
    gemm2<1,false,false,false><<<dim3(4, 16), 256>>>(patches, ir_w1, ir_b1, tmp,
        T_TOK, 512, 128, nullptr, nullptr, nullptr, nullptr, 0, 0);
    gemm2<2,false,false,false><<<dim3(1, 16), 256>>>(tmp, ir_w2, ir_b2, hp,
        T_TOK, 128, 512, patches, nullptr, nullptr, nullptr, 0, 0);
    gemm2<0,false,false,false><<<dim3(4, 16), 256>>>(hp, p2m_w, p2m_b, h,
        T_TOK, 512, 128, nullptr, nullptr, nullptr, nullptr, 0, 0);
    freqadd_kernel<<<(T_TOK * 512) / 256, 256>>>(h, freq_emb, fid);

    for (int l = 0; l < 12; l++) {
        // attention
        ln512_kernel<<<256, 256>>>(h, hn, ln1_g + (size_t)l * 512, ln1_b + (size_t)l * 512);
        gemm2<0,false,false,false><<<dim3(12, 16), 256>>>(hn,
            qkv_w + (size_t)l * 512 * 1536, qkv_b + (size_t)l * 1536, qkv,
            T_TOK, 1536, 512, nullptr, nullptr, nullptr, nullptr, 0, 0);
        attn_kernel<<<2048, 256>>>(qkv, attn);
        gemm2<3,false,false,false><<<dim3(4, 16), 256>>>(attn,
            out_w + (size_t)l * 512 * 512, out_b + (size_t)l * 512, h,
            T_TOK, 512, 512, nullptr, nullptr, nullptr, nullptr, 0, 0);
        // sparse MoE (all 4 experts fused per launch via blockIdx.z)
        ln512_kernel<<<256, 256>>>(h, hn, ln2_g + (size_t)l * 512, ln2_b + (size_t)l * 512);
        zero_cnt_kernel<<<1, 32>>>(cnt);
        gate_route_kernel<<<256, 256>>>(hn, gate_w + (size_t)l * 512 * 4,
                                        gate_b + (size_t)l * 4, cnt, idx, rw);
        gemm2<1,true,true,true><<<dim3(16, 16, 4), 256>>>(hn,
            exp_w1 + (size_t)l * 4 * 512 * 2048, exp_b1 + (size_t)l * 4 * 2048, eh,
            T_TOK, 2048, 512, nullptr, idx, nullptr, cnt, 0, EHZ);
        gemm2<5,false,true,true><<<dim3(4, 16, 4), 256>>>(eh,
            exp_w2 + (size_t)l * 4 * 2048 * 512, exp_b2 + (size_t)l * 4 * 512, h,
            T_TOK, 512, 2048, nullptr, idx, rw, cnt, EHZ, 0);
    }

    head_kernel<<<1, 512>>>(h, fn_g, fn_b, head_g, head_b, head_w, head_bias,
                            (float*)d_out, out_size);
}

// round 7
// speedup vs baseline: 2.5756x; 1.4537x over previous
#include <cuda_runtime.h>
#include <cuda_fp16.h>
#include <math.h>
#include <stdint.h>

// ---------------------------------------------------------------------------
// B=16, S=2048, C=8, P=16 -> N=128 patches, T=2048 tokens
// PD=128, IRH=512, D=512, NH=8, dh=64, L=12, E=4, H=2048, top-2 routing
// GEMMs via mma.sync m16n8k16 f16 with split-precision (hi+lo) operands:
//   A*B ~= Ahi*Bhi + Ahi*Blo + Alo*Bhi  (fp32 accum) -> ~fp32-grade accuracy.
// ---------------------------------------------------------------------------
#define T_TOK 2048
#define DIM   512
#define HDIM  2048

__device__ float g_patches[T_TOK * 128];
__device__ float g_tmp    [T_TOK * 512];
__device__ float g_hp     [T_TOK * 128];
__device__ float g_h      [T_TOK * DIM];
__device__ float g_hn     [T_TOK * DIM];
__device__ float g_qkv    [T_TOK * 3 * DIM];
__device__ float g_attn   [T_TOK * DIM];
__device__ float g_eh     [4 * T_TOK * HDIM];
__device__ int   g_cnt    [4];
__device__ int   g_idx    [4 * T_TOK];
__device__ float g_rw     [4 * T_TOK];

// ---- helpers ---------------------------------------------------------------
__device__ __forceinline__ void split2(float f0, float f1, uint32_t& hi, uint32_t& lo) {
    __half2 h = __floats2half2_rn(f0, f1);
    float2 hf = __half22float2(h);
    __half2 l = __floats2half2_rn(f0 - hf.x, f1 - hf.y);
    hi = *(uint32_t*)&h;
    lo = *(uint32_t*)&l;
}
__device__ __forceinline__ void mma_f16(float* d, const uint32_t* a, const uint32_t* b) {
    asm volatile(
        "mma.sync.aligned.m16n8k16.row.col.f32.f16.f16.f32 "
        "{%0,%1,%2,%3}, {%4,%5,%6,%7}, {%8,%9}, {%0,%1,%2,%3};"
        : "+f"(d[0]), "+f"(d[1]), "+f"(d[2]), "+f"(d[3])
        : "r"(a[0]), "r"(a[1]), "r"(a[2]), "r"(a[3]), "r"(b[0]), "r"(b[1]));
}
__device__ __forceinline__ void cpasync16(uint32_t s, const void* g) {
    asm volatile("cp.async.ca.shared.global [%0], [%1], 16;" :: "r"(s), "l"(g));
}
#define CP_COMMIT() asm volatile("cp.async.commit_group;" ::: "memory")
#define CP_WAIT(n)  asm volatile("cp.async.wait_group %0;" :: "n"(n) : "memory")

// ---------------------------------------------------------------------------
// Split-fp16 GEMM: C[M,N] = epi(A[M,K] @ B[K,N] + bias)
// Tile 128x128, BK=32, 256 threads = 8 warps (2m x 4n), warp tile 64x32.
// A smem [128][36], B smem [32][136], double-buffered via cp.async.
// EPI: 0 store, 1 gelu, 2 res+v, 3 C+=v, 5 atomic scatter C[idx[r]] += rw[r]*v
// GA: gather A rows via idx. GUARD: live rows from *cnt. EXPZ: blockIdx.z expert
// ---------------------------------------------------------------------------
#define ASTRIDE 36
#define BSTRIDE 136
#define ABUF (128 * ASTRIDE)
#define BBUF (32 * BSTRIDE)
#define SMEM_MMA ((2 * ABUF + 2 * BBUF) * 4)

template<int EPI, bool GA, bool GUARD, bool EXPZ>
__global__ void __launch_bounds__(256, 2) mma_gemm(
    const float* __restrict__ A, const float* __restrict__ B,
    const float* __restrict__ bias, float* __restrict__ C,
    int M, int N, int K,
    const float* __restrict__ res,
    const int* __restrict__ idx,
    const float* __restrict__ rw,
    const int* __restrict__ cnt,
    size_t zA, size_t zC)
{
    if (EXPZ) {
        const int z = blockIdx.z;
        A    += (size_t)z * zA;
        B    += (size_t)z * K * N;
        bias += (size_t)z * N;
        C    += (size_t)z * zC;
        idx  += z * T_TOK;
        if (rw) rw += z * T_TOK;
        cnt  += z;
    }
    const int t = threadIdx.x, wid = t >> 5, lane = t & 31;
    const int m0 = blockIdx.y * 128, n0 = blockIdx.x * 128;

    int cq = M;
    if (GUARD) { cq = *cnt; if (m0 >= cq) return; }

    extern __shared__ float sm[];
    float* Asm[2] = { sm, sm + ABUF };
    float* Bsm[2] = { sm + 2 * ABUF, sm + 2 * ABUF + BBUF };
    const uint32_t smaddr = (uint32_t)__cvta_generic_to_shared(sm);

    // loaders: A: 2 threads/row, 16 floats each (4x cp.async 16B)
    const int ar = t >> 1, ac = (t & 1) * 16;
    int garow = m0 + ar;
    if (GA) garow = (garow < cq) ? idx[garow] : idx[0];
    const float* Agp = A + (size_t)garow * K + ac;
    // B: k=t>>3, 4 cols at (t&7)*4 + q*32
    const int bk = t >> 3, bc = (t & 7) * 4;
    const float* Bgp = B + (size_t)bk * N + n0 + bc;

    const uint32_t aso = (uint32_t)(ar * ASTRIDE + ac) * 4u;
    const uint32_t bso = (uint32_t)(bk * BSTRIDE + bc) * 4u;

    #pragma unroll
    for (int q = 0; q < 4; q++)
        cpasync16(smaddr + aso + q * 16u, Agp + q * 4);
    #pragma unroll
    for (int q = 0; q < 4; q++)
        cpasync16(smaddr + (uint32_t)(2 * ABUF) * 4u + bso + q * 128u, Bgp + q * 32);
    CP_COMMIT();

    const int wm = wid >> 2, wn = wid & 3;
    const int gid = lane >> 2, tig = lane & 3;

    float acc[4][4][4];
    #pragma unroll
    for (int i = 0; i < 4; i++)
        #pragma unroll
        for (int j = 0; j < 4; j++)
            #pragma unroll
            for (int q = 0; q < 4; q++) acc[i][j][q] = 0.f;

    const int nkt = K >> 5;
    for (int j = 0; j < nkt; j++) {
        const int cur = j & 1;
        if (j + 1 < nkt) {
            const int nxt = cur ^ 1;
            const int k0 = (j + 1) << 5;
            const uint32_t abase = smaddr + (uint32_t)(nxt ? ABUF : 0) * 4u;
            const uint32_t bbase = smaddr + (uint32_t)(2 * ABUF + (nxt ? BBUF : 0)) * 4u;
            #pragma unroll
            for (int q = 0; q < 4; q++)
                cpasync16(abase + aso + q * 16u, Agp + k0 + q * 4);
            #pragma unroll
            for (int q = 0; q < 4; q++)
                cpasync16(bbase + bso + q * 128u, Bgp + (size_t)k0 * N + q * 32);
            CP_COMMIT();
            CP_WAIT(1);
        } else {
            CP_WAIT(0);
        }
        __syncthreads();

        const float* Asb = Asm[cur];
        const float* Bsb = Bsm[cur];
        #pragma unroll
        for (int ks = 0; ks < 2; ks++) {
            const int kb = ks * 16;
            uint32_t bhi[4][2], blo[4][2];
            #pragma unroll
            for (int ni = 0; ni < 4; ni++) {
                const float* bp = &Bsb[(size_t)(kb + 2 * tig) * BSTRIDE + wn * 32 + ni * 8 + gid];
                split2(bp[0], bp[BSTRIDE], bhi[ni][0], blo[ni][0]);
                split2(bp[8 * BSTRIDE], bp[9 * BSTRIDE], bhi[ni][1], blo[ni][1]);
            }
            #pragma unroll
            for (int mi = 0; mi < 4; mi++) {
                const float* ap = &Asb[(size_t)(wm * 64 + mi * 16 + gid) * ASTRIDE + kb + 2 * tig];
                float2 v0 = *(const float2*)(ap);
                float2 v1 = *(const float2*)(ap + 8 * ASTRIDE);
                float2 v2 = *(const float2*)(ap + 8);
                float2 v3 = *(const float2*)(ap + 8 * ASTRIDE + 8);
                uint32_t ahi[4], alo[4];
                split2(v0.x, v0.y, ahi[0], alo[0]);
                split2(v1.x, v1.y, ahi[1], alo[1]);
                split2(v2.x, v2.y, ahi[2], alo[2]);
                split2(v3.x, v3.y, ahi[3], alo[3]);
                #pragma unroll
                for (int ni = 0; ni < 4; ni++) {
                    mma_f16(acc[mi][ni], ahi, bhi[ni]);
                    mma_f16(acc[mi][ni], ahi, blo[ni]);
                    mma_f16(acc[mi][ni], alo, bhi[ni]);
                }
            }
        }
        __syncthreads();
    }

    // epilogue: c0,c1 at (row, col..col+1); c2,c3 at (row+8, ...)
    #pragma unroll
    for (int mi = 0; mi < 4; mi++) {
        #pragma unroll
        for (int half = 0; half < 2; half++) {
            const int row = m0 + wm * 64 + mi * 16 + gid + half * 8;
            if (GUARD && row >= cq) continue;
            #pragma unroll
            for (int ni = 0; ni < 4; ni++) {
                const int col = n0 + wn * 32 + ni * 8 + tig * 2;
                float vx = acc[mi][ni][half * 2 + 0] + bias[col];
                float vy = acc[mi][ni][half * 2 + 1] + bias[col + 1];
                if (EPI == 5) {
                    const float w = rw[row];
                    float* dst = C + (size_t)idx[row] * N + col;
                    atomicAdd(dst,     w * vx);
                    atomicAdd(dst + 1, w * vy);
                } else {
                    float* dst = C + (size_t)row * N + col;
                    if (EPI == 1) {
                        vx = 0.5f * vx * (1.0f + erff(vx * 0.70710678118654752f));
                        vy = 0.5f * vy * (1.0f + erff(vy * 0.70710678118654752f));
                    } else if (EPI == 2) {
                        const float2 rr = *(const float2*)(res + (size_t)row * N + col);
                        vx += rr.x; vy += rr.y;
                    } else if (EPI == 3) {
                        const float2 cc = *(const float2*)dst;
                        vx += cc.x; vy += cc.y;
                    }
                    *(float2*)dst = make_float2(vx, vy);
                }
            }
        }
    }
}

// ---------------------------------------------------------------------------
__global__ void patchnorm_kernel(const float* __restrict__ x, float* __restrict__ y)
{
    const int warp = threadIdx.x >> 5, lane = threadIdx.x & 31;
    const int row = blockIdx.x * 8 + warp;
    const float* xr = x + (size_t)row * 128;
    float4 f = *(const float4*)(xr + lane * 4);
    float s = f.x + f.y + f.z + f.w;
    #pragma unroll
    for (int o = 16; o; o >>= 1) s += __shfl_xor_sync(0xffffffffu, s, o);
    const float mu = s * (1.0f / 128.0f);
    float q = (f.x - mu) * (f.x - mu) + (f.y - mu) * (f.y - mu)
            + (f.z - mu) * (f.z - mu) + (f.w - mu) * (f.w - mu);
    #pragma unroll
    for (int o = 16; o; o >>= 1) q += __shfl_xor_sync(0xffffffffu, q, o);
    const float rs = rsqrtf(q * (1.0f / 128.0f) + 1e-6f);
    float4 r = make_float4((f.x - mu) * rs, (f.y - mu) * rs, (f.z - mu) * rs, (f.w - mu) * rs);
    *(float4*)(y + (size_t)row * 128 + lane * 4) = r;
}

__global__ void ln512_kernel(const float* __restrict__ x, float* __restrict__ y,
                             const float* __restrict__ g, const float* __restrict__ b)
{
    const int warp = threadIdx.x >> 5, lane = threadIdx.x & 31;
    const int row = blockIdx.x * 8 + warp;
    const float* xr = x + (size_t)row * 512;
    float v[16];
    float s = 0.f;
    #pragma unroll
    for (int c = 0; c < 4; c++) {
        float4 f = *(const float4*)(xr + c * 128 + lane * 4);
        v[c * 4 + 0] = f.x; v[c * 4 + 1] = f.y; v[c * 4 + 2] = f.z; v[c * 4 + 3] = f.w;
        s += f.x + f.y + f.z + f.w;
    }
    #pragma unroll
    for (int o = 16; o; o >>= 1) s += __shfl_xor_sync(0xffffffffu, s, o);
    const float mu = s * (1.0f / 512.0f);
    float q = 0.f;
    #pragma unroll
    for (int k = 0; k < 16; k++) { float d = v[k] - mu; q += d * d; }
    #pragma unroll
    for (int o = 16; o; o >>= 1) q += __shfl_xor_sync(0xffffffffu, q, o);
    const float rs = rsqrtf(q * (1.0f / 512.0f) + 1e-5f);
    #pragma unroll
    for (int c = 0; c < 4; c++) {
        const int col = c * 128 + lane * 4;
        float4 gg = *(const float4*)(g + col);
        float4 bb = *(const float4*)(b + col);
        float4 r;
        r.x = gg.x * (v[c * 4 + 0] - mu) * rs + bb.x;
        r.y = gg.y * (v[c * 4 + 1] - mu) * rs + bb.y;
        r.z = gg.z * (v[c * 4 + 2] - mu) * rs + bb.z;
        r.w = gg.w * (v[c * 4 + 3] - mu) * rs + bb.w;
        *(float4*)(y + (size_t)row * 512 + col) = r;
    }
}

__global__ void freqadd_kernel(float* __restrict__ h, const float* __restrict__ emb,
                               const int* __restrict__ fid)
{
    const int i = blockIdx.x * 256 + threadIdx.x;
    const int row = i >> 9, d = i & 511, b = row >> 7;
    h[i] += emb[(size_t)fid[b] * 512 + d];
}

__global__ void attn_kernel(const float* __restrict__ qkv, float* __restrict__ o)
{
    const int gw = blockIdx.x * 8 + (threadIdx.x >> 5);
    const int lane = threadIdx.x & 31;
    const int i = gw & 127, hh = (gw >> 7) & 7, b = gw >> 10;
    const float* base = qkv + (size_t)b * 128 * 1536;
    const float* qp = base + (size_t)i * 1536 + hh * 64 + lane * 2;
    const float qx = qp[0], qy = qp[1];
    const float* kp = base + 512  + hh * 64 + lane * 2;
    const float* vp = base + 1024 + hh * 64 + lane * 2;
    float m = -1e30f, l = 0.f, ox = 0.f, oy = 0.f;
    for (int j = 0; j <= i; j++) {
        float2 k2 = *(const float2*)(kp + (size_t)j * 1536);
        float p = qx * k2.x + qy * k2.y;
        #pragma unroll
        for (int off = 16; off; off >>= 1) p += __shfl_xor_sync(0xffffffffu, p, off);
        const float s = p * 0.125f;
        const float nm = fmaxf(m, s);
        const float sc = __expf(m - nm), e = __expf(s - nm);
        l = l * sc + e;
        float2 v2 = *(const float2*)(vp + (size_t)j * 1536);
        ox = ox * sc + e * v2.x;
        oy = oy * sc + e * v2.y;
        m = nm;
    }
    const float inv = 1.0f / l;
    float* op = o + ((size_t)b * 128 + i) * 512 + hh * 64 + lane * 2;
    op[0] = ox * inv; op[1] = oy * inv;
}

__global__ void zero_cnt_kernel(int* cnt)
{
    if (threadIdx.x < 4) cnt[threadIdx.x] = 0;
}

__global__ void gate_route_kernel(const float* __restrict__ hn, const float* __restrict__ gw,
                                  const float* __restrict__ gb,
                                  int* __restrict__ cnt, int* __restrict__ idx,
                                  float* __restrict__ rw)
{
    const int warp = threadIdx.x >> 5, lane = threadIdx.x & 31;
    const int row = blockIdx.x * 8 + warp;
    const float* xr = hn + (size_t)row * 512;
    float a0 = 0.f, a1 = 0.f, a2 = 0.f, a3 = 0.f;
    for (int d = lane; d < 512; d += 32) {
        const float hv = xr[d];
        float4 w = *(const float4*)(gw + (size_t)d * 4);
        a0 += hv * w.x; a1 += hv * w.y; a2 += hv * w.z; a3 += hv * w.w;
    }
    #pragma unroll
    for (int o = 16; o; o >>= 1) {
        a0 += __shfl_xor_sync(0xffffffffu, a0, o);
        a1 += __shfl_xor_sync(0xffffffffu, a1, o);
        a2 += __shfl_xor_sync(0xffffffffu, a2, o);
        a3 += __shfl_xor_sync(0xffffffffu, a3, o);
    }
    if (lane == 0) {
        float p[4] = {a0 + gb[0], a1 + gb[1], a2 + gb[2], a3 + gb[3]};
        const float mx = fmaxf(fmaxf(p[0], p[1]), fmaxf(p[2], p[3]));
        float s = 0.f;
        #pragma unroll
        for (int e = 0; e < 4; e++) { p[e] = expf(p[e] - mx); s += p[e]; }
        const float invs = 1.0f / s;
        #pragma unroll
        for (int e = 0; e < 4; e++) p[e] *= invs;
        int i0 = 0;
        #pragma unroll
        for (int e = 1; e < 4; e++) if (p[e] > p[i0]) i0 = e;
        int i1 = -1;
        #pragma unroll
        for (int e = 0; e < 4; e++) if (e != i0 && (i1 < 0 || p[e] > p[i1])) i1 = e;
        int s0 = atomicAdd(&cnt[i0], 1);
        idx[i0 * T_TOK + s0] = row; rw[i0 * T_TOK + s0] = p[i0];
        int s1 = atomicAdd(&cnt[i1], 1);
        idx[i1 * T_TOK + s1] = row; rw[i1 * T_TOK + s1] = p[i1];
    }
}

__global__ void head_kernel(const float* __restrict__ h,
                            const float* __restrict__ fng, const float* __restrict__ fnb,
                            const float* __restrict__ hg,  const float* __restrict__ hb,
                            const float* __restrict__ hw,  const float* __restrict__ hbias,
                            float* __restrict__ out, int out_size)
{
    const int warp = threadIdx.x >> 5, lane = threadIdx.x & 31;
    const int b = warp;
    const float* xr = h + ((size_t)b * 128 + 127) * 512;
    float v[16];
    float s = 0.f;
    #pragma unroll
    for (int c = 0; c < 4; c++) {
        float4 f = *(const float4*)(xr + c * 128 + lane * 4);
        v[c * 4 + 0] = f.x; v[c * 4 + 1] = f.y; v[c * 4 + 2] = f.z; v[c * 4 + 3] = f.w;
        s += f.x + f.y + f.z + f.w;
    }
    #pragma unroll
    for (int o = 16; o; o >>= 1) s += __shfl_xor_sync(0xffffffffu, s, o);
    float mu = s * (1.0f / 512.0f);
    float q = 0.f;
    #pragma unroll
    for (int k = 0; k < 16; k++) { float d = v[k] - mu; q += d * d; }
    #pragma unroll
    for (int o = 16; o; o >>= 1) q += __shfl_xor_sync(0xffffffffu, q, o);
    float rs = rsqrtf(q * (1.0f / 512.0f) + 1e-5f);
    #pragma unroll
    for (int c = 0; c < 4; c++)
        #pragma unroll
        for (int j = 0; j < 4; j++) {
            const int col = c * 128 + lane * 4 + j;
            v[c * 4 + j] = fng[col] * (v[c * 4 + j] - mu) * rs + fnb[col];
        }
    s = 0.f;
    #pragma unroll
    for (int k = 0; k < 16; k++) s += v[k];
    #pragma unroll
    for (int o = 16; o; o >>= 1) s += __shfl_xor_sync(0xffffffffu, s, o);
    mu = s * (1.0f / 512.0f);
    q = 0.f;
    #pragma unroll
    for (int k = 0; k < 16; k++) { float d = v[k] - mu; q += d * d; }
    #pragma unroll
    for (int o = 16; o; o >>= 1) q += __shfl_xor_sync(0xffffffffu, q, o);
    rs = rsqrtf(q * (1.0f / 512.0f) + 1e-5f);
    float dot = 0.f;
    #pragma unroll
    for (int c = 0; c < 4; c++)
        #pragma unroll
        for (int j = 0; j < 4; j++) {
            const int col = c * 128 + lane * 4 + j;
            const float hl = hg[col] * (v[c * 4 + j] - mu) * rs + hb[col];
            dot += hl * hw[col];
        }
    #pragma unroll
    for (int o = 16; o; o >>= 1) dot += __shfl_xor_sync(0xffffffffu, dot, o);
    if (lane == 0) {
        const float logit = dot + hbias[0];
        if (out_size >= 32) {
            out[b] = logit;
            out[16 + b] = 1.0f / (1.0f + expf(-logit));
        } else {
            out[b] = logit;
        }
    }
}

// ---------------------------------------------------------------------------
extern "C" void kernel_launch(void* const* d_in, const int* in_sizes, int n_in,
                              void* d_out, int out_size)
{
    const float* x        = (const float*)d_in[0];
    const int*   fid      = (const int*)  d_in[1];
    const float* ir_w1    = (const float*)d_in[2];
    const float* ir_b1    = (const float*)d_in[3];
    const float* ir_w2    = (const float*)d_in[4];
    const float* ir_b2    = (const float*)d_in[5];
    const float* p2m_w    = (const float*)d_in[6];
    const float* p2m_b    = (const float*)d_in[7];
    const float* freq_emb = (const float*)d_in[8];
    const float* ln1_g    = (const float*)d_in[9];
    const float* ln1_b    = (const float*)d_in[10];
    const float* qkv_w    = (const float*)d_in[11];
    const float* qkv_b    = (const float*)d_in[12];
    const float* out_w    = (const float*)d_in[13];
    const float* out_b    = (const float*)d_in[14];
    const float* ln2_g    = (const float*)d_in[15];
    const float* ln2_b    = (const float*)d_in[16];
    const float* gate_w   = (const float*)d_in[17];
    const float* gate_b   = (const float*)d_in[18];
    const float* exp_w1   = (const float*)d_in[19];
    const float* exp_b1   = (const float*)d_in[20];
    const float* exp_w2   = (const float*)d_in[21];
    const float* exp_b2   = (const float*)d_in[22];
    const float* fn_g     = (const float*)d_in[23];
    const float* fn_b     = (const float*)d_in[24];
    const float* head_g   = (const float*)d_in[25];
    const float* head_b   = (const float*)d_in[26];
    const float* head_w   = (const float*)d_in[27];
    const float* head_bias= (const float*)d_in[28];

    float *patches, *tmp, *hp, *h, *hn, *qkv, *attn, *eh, *rw;
    int *cnt, *idx;
    cudaGetSymbolAddress((void**)&patches, g_patches);
    cudaGetSymbolAddress((void**)&tmp,     g_tmp);
    cudaGetSymbolAddress((void**)&hp,      g_hp);
    cudaGetSymbolAddress((void**)&h,       g_h);
    cudaGetSymbolAddress((void**)&hn,      g_hn);
    cudaGetSymbolAddress((void**)&qkv,     g_qkv);
    cudaGetSymbolAddress((void**)&attn,    g_attn);
    cudaGetSymbolAddress((void**)&eh,      g_eh);
    cudaGetSymbolAddress((void**)&cnt,     g_cnt);
    cudaGetSymbolAddress((void**)&idx,     g_idx);
    cudaGetSymbolAddress((void**)&rw,      g_rw);

    cudaFuncSetAttribute(mma_gemm<0,false,false,false>, cudaFuncAttributeMaxDynamicSharedMemorySize, SMEM_MMA);
    cudaFuncSetAttribute(mma_gemm<1,false,false,false>, cudaFuncAttributeMaxDynamicSharedMemorySize, SMEM_MMA);
    cudaFuncSetAttribute(mma_gemm<2,false,false,false>, cudaFuncAttributeMaxDynamicSharedMemorySize, SMEM_MMA);
    cudaFuncSetAttribute(mma_gemm<3,false,false,false>, cudaFuncAttributeMaxDynamicSharedMemorySize, SMEM_MMA);
    cudaFuncSetAttribute(mma_gemm<1,true,true,true>,    cudaFuncAttributeMaxDynamicSharedMemorySize, SMEM_MMA);
    cudaFuncSetAttribute(mma_gemm<5,false,true,true>,   cudaFuncAttributeMaxDynamicSharedMemorySize, SMEM_MMA);

    const size_t EHZ = (size_t)T_TOK * HDIM;

    // Front end
    patchnorm_kernel<<<256, 256>>>(x, patches);
    mma_gemm<1,false,false,false><<<dim3(4, 16), 256, SMEM_MMA>>>(patches, ir_w1, ir_b1, tmp,
        T_TOK, 512, 128, nullptr, nullptr, nullptr, nullptr, 0, 0);
    mma_gemm<2,false,false,false><<<dim3(1, 16), 256, SMEM_MMA>>>(tmp, ir_w2, ir_b2, hp,
        T_TOK, 128, 512, patches, nullptr, nullptr, nullptr, 0, 0);
    mma_gemm<0,false,false,false><<<dim3(4, 16), 256, SMEM_MMA>>>(hp, p2m_w, p2m_b, h,
        T_TOK, 512, 128, nullptr, nullptr, nullptr, nullptr, 0, 0);
    freqadd_kernel<<<(T_TOK * 512) / 256, 256>>>(h, freq_emb, fid);

    for (int l = 0; l < 12; l++) {
        // attention
        ln512_kernel<<<256, 256>>>(h, hn, ln1_g + (size_t)l * 512, ln1_b + (size_t)l * 512);
        mma_gemm<0,false,false,false><<<dim3(12, 16), 256, SMEM_MMA>>>(hn,
            qkv_w + (size_t)l * 512 * 1536, qkv_b + (size_t)l * 1536, qkv,
            T_TOK, 1536, 512, nullptr, nullptr, nullptr, nullptr, 0, 0);
        attn_kernel<<<2048, 256>>>(qkv, attn);
        mma_gemm<3,false,false,false><<<dim3(4, 16), 256, SMEM_MMA>>>(attn,
            out_w + (size_t)l * 512 * 512, out_b + (size_t)l * 512, h,
            T_TOK, 512, 512, nullptr, nullptr, nullptr, nullptr, 0, 0);
        // sparse MoE (4 experts fused via blockIdx.z)
        ln512_kernel<<<256, 256>>>(h, hn, ln2_g + (size_t)l * 512, ln2_b + (size_t)l * 512);
        zero_cnt_kernel<<<1, 32>>>(cnt);
        gate_route_kernel<<<256, 256>>>(hn, gate_w + (size_t)l * 512 * 4,
                                        gate_b + (size_t)l * 4, cnt, idx, rw);
        mma_gemm<1,true,true,true><<<dim3(16, 16, 4), 256, SMEM_MMA>>>(hn,
            exp_w1 + (size_t)l * 4 * 512 * 2048, exp_b1 + (size_t)l * 4 * 2048, eh,
            T_TOK, 2048, 512, nullptr, idx, nullptr, cnt, 0, EHZ);
        mma_gemm<5,false,true,true><<<dim3(4, 16, 4), 256, SMEM_MMA>>>(eh,
            exp_w2 + (size_t)l * 4 * 2048 * 512, exp_b2 + (size_t)l * 4 * 512, h,
            T_TOK, 512, 2048, nullptr, idx, rw, cnt, EHZ, 0);
    }

    head_kernel<<<1, 512>>>(h, fn_g, fn_b, head_g, head_b, head_w, head_bias,
                            (float*)d_out, out_size);
}

// round 8
// speedup vs baseline: 3.5116x; 1.3634x over previous
#include <cuda_runtime.h>
#include <cuda_fp16.h>
#include <math.h>
#include <stdint.h>

// ---------------------------------------------------------------------------
// B=16, S=2048, C=8, P=16 -> N=128 patches, T=2048 tokens
// PD=128, IRH=512, D=512, NH=8, dh=64, L=12, E=4, H=2048, top-2 routing
// GEMMs: mma.sync m16n8k16 f16 split-precision (Ahi*Bhi + Ahi*Blo + Alo*Bhi),
// hi/lo split done ONCE at smem tile load; inner loop = pure LDS + HMMA.
// Tile 64x128, BK=32, 8 warps (2m x 4n), warp tile 32x32, 2 CTAs/SM.
// ---------------------------------------------------------------------------
#define T_TOK 2048
#define DIM   512
#define HDIM  2048

__device__ float g_patches[T_TOK * 128];
__device__ float g_tmp    [T_TOK * 512];
__device__ float g_hp     [T_TOK * 128];
__device__ float g_h      [T_TOK * DIM];
__device__ float g_hn     [T_TOK * DIM];
__device__ float g_qkv    [T_TOK * 3 * DIM];
__device__ float g_attn   [T_TOK * DIM];
__device__ float g_eh     [4 * T_TOK * HDIM];
__device__ int   g_cnt    [4];
__device__ int   g_idx    [4 * T_TOK];
__device__ float g_rw     [4 * T_TOK];

// ---- helpers ---------------------------------------------------------------
__device__ __forceinline__ void split2(float f0, float f1, uint32_t& hi, uint32_t& lo) {
    __half2 h = __floats2half2_rn(f0, f1);
    float2 hf = __half22float2(h);
    __half2 l = __floats2half2_rn(f0 - hf.x, f1 - hf.y);
    hi = *(uint32_t*)&h;
    lo = *(uint32_t*)&l;
}
__device__ __forceinline__ void mma_f16(float* d, const uint32_t* a, const uint32_t* b) {
    asm volatile(
        "mma.sync.aligned.m16n8k16.row.col.f32.f16.f16.f32 "
        "{%0,%1,%2,%3}, {%4,%5,%6,%7}, {%8,%9}, {%0,%1,%2,%3};"
        : "+f"(d[0]), "+f"(d[1]), "+f"(d[2]), "+f"(d[3])
        : "r"(a[0]), "r"(a[1]), "r"(a[2]), "r"(a[3]), "r"(b[0]), "r"(b[1]));
}

// smem layout (halves): stride 40 per row (conflict-free frag LDS)
#define KST 40
#define AH_SZ (64 * KST)    // 2560 halves per A tile
#define BH_SZ (128 * KST)   // 5120 halves per B tile
// offsets: AH0 AH1 AL0 AL1 BH0 BH1 BL0 BL1
#define OFF_AH(b) ((b) * AH_SZ)
#define OFF_AL(b) (2 * AH_SZ + (b) * AH_SZ)
#define OFF_BH(b) (4 * AH_SZ + (b) * BH_SZ)
#define OFF_BL(b) (4 * AH_SZ + 2 * BH_SZ + (b) * BH_SZ)
#define SMEM_MMA ((4 * AH_SZ + 4 * BH_SZ) * 2)   // 61440 bytes

// ---------------------------------------------------------------------------
// EPI: 0 store, 1 gelu, 2 res+v, 3 C+=v, 5 atomic scatter C[idx[r]] += rw[r]*v
// GA: gather A rows via idx. GUARD: live rows from *cnt. EXPZ: blockIdx.z expert
// ---------------------------------------------------------------------------
template<int EPI, bool GA, bool GUARD, bool EXPZ>
__global__ void __launch_bounds__(256, 2) mma_gemm(
    const float* __restrict__ A, const float* __restrict__ B,
    const float* __restrict__ bias, float* __restrict__ C,
    int M, int N, int K,
    const float* __restrict__ res,
    const int* __restrict__ idx,
    const float* __restrict__ rw,
    const int* __restrict__ cnt,
    size_t zA, size_t zC)
{
    if (EXPZ) {
        const int z = blockIdx.z;
        A    += (size_t)z * zA;
        B    += (size_t)z * K * N;
        bias += (size_t)z * N;
        C    += (size_t)z * zC;
        idx  += z * T_TOK;
        if (rw) rw += z * T_TOK;
        cnt  += z;
    }
    const int t = threadIdx.x, wid = t >> 5, lane = t & 31;
    const int m0 = blockIdx.y * 64, n0 = blockIdx.x * 128;

    int cq = M;
    if (GUARD) { cq = *cnt; if (m0 >= cq) return; }

    extern __shared__ __half sh[];

    // A loader: 4 threads/row, 8 k each
    const int arow = t >> 2, akof = (t & 3) * 8;
    int garow = m0 + arow;
    if (GA) garow = (garow < cq) ? idx[garow] : idx[0];
    const float* Agp = A + (size_t)garow * K + akof;
    // B loader: thread -> column nB, k-half kk2 (16 k values, strided LDG)
    const int nB = t & 127, kk2 = t >> 7;
    const float* Bcol = B + n0 + nB;

    const int wm = wid >> 2, wn = wid & 3;
    const int gid = lane >> 2, tig = lane & 3;

    float4 pa0, pa1;
    float pb[16];

    // ---- prefetch + store k-tile 0 ----
    pa0 = *(const float4*)(Agp);
    pa1 = *(const float4*)(Agp + 4);
    #pragma unroll
    for (int i = 0; i < 4; i++)
        #pragma unroll
        for (int jj = 0; jj < 4; jj++)
            pb[i * 4 + jj] = Bcol[(size_t)(kk2 * 16 + i * 4 + jj) * N];
    {
        uint32_t h0,l0,h1,l1,h2,l2,h3,l3;
        split2(pa0.x, pa0.y, h0, l0); split2(pa0.z, pa0.w, h1, l1);
        split2(pa1.x, pa1.y, h2, l2); split2(pa1.z, pa1.w, h3, l3);
        *(uint4*)&sh[OFF_AH(0) + arow * KST + akof] = make_uint4(h0,h1,h2,h3);
        *(uint4*)&sh[OFF_AL(0) + arow * KST + akof] = make_uint4(l0,l1,l2,l3);
        #pragma unroll
        for (int i = 0; i < 4; i++) {
            const int kb = kk2 * 16 + i * 4;
            uint32_t bh0,bl0,bh1,bl1;
            split2(pb[i*4+0], pb[i*4+1], bh0, bl0);
            split2(pb[i*4+2], pb[i*4+3], bh1, bl1);
            *(uint2*)&sh[OFF_BH(0) + nB * KST + kb] = make_uint2(bh0, bh1);
            *(uint2*)&sh[OFF_BL(0) + nB * KST + kb] = make_uint2(bl0, bl1);
        }
    }
    __syncthreads();

    float acc[2][4][4];
    #pragma unroll
    for (int i = 0; i < 2; i++)
        #pragma unroll
        for (int j = 0; j < 4; j++)
            #pragma unroll
            for (int q = 0; q < 4; q++) acc[i][j][q] = 0.f;

    const int nkt = K >> 5;
    for (int j = 0; j < nkt; j++) {
        const int cur = j & 1;
        const bool more = (j + 1 < nkt);
        if (more) {
            const int k0 = (j + 1) << 5;
            pa0 = *(const float4*)(Agp + k0);
            pa1 = *(const float4*)(Agp + k0 + 4);
            #pragma unroll
            for (int i = 0; i < 4; i++)
                #pragma unroll
                for (int jj = 0; jj < 4; jj++)
                    pb[i * 4 + jj] = Bcol[(size_t)(k0 + kk2 * 16 + i * 4 + jj) * N];
        }
        // ---- compute on cur ----
        {
            const __half* Ah = sh + OFF_AH(cur);
            const __half* Al = sh + OFF_AL(cur);
            const __half* Bh = sh + OFF_BH(cur);
            const __half* Bl = sh + OFF_BL(cur);
            #pragma unroll
            for (int ks = 0; ks < 2; ks++) {
                const int kb = ks * 16 + tig * 2;
                uint32_t bh[4][2], bl[4][2];
                #pragma unroll
                for (int ni = 0; ni < 4; ni++) {
                    const int n = (wn * 32 + ni * 8 + gid) * KST + kb;
                    bh[ni][0] = *(const uint32_t*)&Bh[n];
                    bh[ni][1] = *(const uint32_t*)&Bh[n + 8];
                    bl[ni][0] = *(const uint32_t*)&Bl[n];
                    bl[ni][1] = *(const uint32_t*)&Bl[n + 8];
                }
                #pragma unroll
                for (int mi = 0; mi < 2; mi++) {
                    const int r = (wm * 32 + mi * 16 + gid) * KST + kb;
                    uint32_t ah[4], al[4];
                    ah[0] = *(const uint32_t*)&Ah[r];
                    ah[1] = *(const uint32_t*)&Ah[r + 8 * KST];
                    ah[2] = *(const uint32_t*)&Ah[r + 8];
                    ah[3] = *(const uint32_t*)&Ah[r + 8 * KST + 8];
                    al[0] = *(const uint32_t*)&Al[r];
                    al[1] = *(const uint32_t*)&Al[r + 8 * KST];
                    al[2] = *(const uint32_t*)&Al[r + 8];
                    al[3] = *(const uint32_t*)&Al[r + 8 * KST + 8];
                    #pragma unroll
                    for (int ni = 0; ni < 4; ni++) {
                        mma_f16(acc[mi][ni], ah, bh[ni]);
                        mma_f16(acc[mi][ni], ah, bl[ni]);
                        mma_f16(acc[mi][ni], al, bh[ni]);
                    }
                }
            }
        }
        if (more) {
            const int nxt = cur ^ 1;
            uint32_t h0,l0,h1,l1,h2,l2,h3,l3;
            split2(pa0.x, pa0.y, h0, l0); split2(pa0.z, pa0.w, h1, l1);
            split2(pa1.x, pa1.y, h2, l2); split2(pa1.z, pa1.w, h3, l3);
            *(uint4*)&sh[OFF_AH(nxt) + arow * KST + akof] = make_uint4(h0,h1,h2,h3);
            *(uint4*)&sh[OFF_AL(nxt) + arow * KST + akof] = make_uint4(l0,l1,l2,l3);
            #pragma unroll
            for (int i = 0; i < 4; i++) {
                const int kb = kk2 * 16 + i * 4;
                uint32_t bh0,bl0,bh1,bl1;
                split2(pb[i*4+0], pb[i*4+1], bh0, bl0);
                split2(pb[i*4+2], pb[i*4+3], bh1, bl1);
                *(uint2*)&sh[OFF_BH(nxt) + nB * KST + kb] = make_uint2(bh0, bh1);
                *(uint2*)&sh[OFF_BL(nxt) + nB * KST + kb] = make_uint2(bl0, bl1);
            }
            __syncthreads();
        }
    }

    // ---- epilogue ----
    #pragma unroll
    for (int mi = 0; mi < 2; mi++) {
        #pragma unroll
        for (int half = 0; half < 2; half++) {
            const int row = m0 + wm * 32 + mi * 16 + gid + half * 8;
            if (GUARD && row >= cq) continue;
            #pragma unroll
            for (int ni = 0; ni < 4; ni++) {
                const int col = n0 + wn * 32 + ni * 8 + tig * 2;
                float vx = acc[mi][ni][half * 2 + 0] + bias[col];
                float vy = acc[mi][ni][half * 2 + 1] + bias[col + 1];
                if (EPI == 5) {
                    const float w = rw[row];
                    float* dst = C + (size_t)idx[row] * N + col;
                    atomicAdd(dst,     w * vx);
                    atomicAdd(dst + 1, w * vy);
                } else {
                    float* dst = C + (size_t)row * N + col;
                    if (EPI == 1) {
                        vx = 0.5f * vx * (1.0f + erff(vx * 0.70710678118654752f));
                        vy = 0.5f * vy * (1.0f + erff(vy * 0.70710678118654752f));
                    } else if (EPI == 2) {
                        const float2 rr = *(const float2*)(res + (size_t)row * N + col);
                        vx += rr.x; vy += rr.y;
                    } else if (EPI == 3) {
                        const float2 cc = *(const float2*)dst;
                        vx += cc.x; vy += cc.y;
                    }
                    *(float2*)dst = make_float2(vx, vy);
                }
            }
        }
    }
}

// ---------------------------------------------------------------------------
__global__ void patchnorm_kernel(const float* __restrict__ x, float* __restrict__ y)
{
    const int warp = threadIdx.x >> 5, lane = threadIdx.x & 31;
    const int row = blockIdx.x * 8 + warp;
    const float* xr = x + (size_t)row * 128;
    float4 f = *(const float4*)(xr + lane * 4);
    float s = f.x + f.y + f.z + f.w;
    #pragma unroll
    for (int o = 16; o; o >>= 1) s += __shfl_xor_sync(0xffffffffu, s, o);
    const float mu = s * (1.0f / 128.0f);
    float q = (f.x - mu) * (f.x - mu) + (f.y - mu) * (f.y - mu)
            + (f.z - mu) * (f.z - mu) + (f.w - mu) * (f.w - mu);
    #pragma unroll
    for (int o = 16; o; o >>= 1) q += __shfl_xor_sync(0xffffffffu, q, o);
    const float rs = rsqrtf(q * (1.0f / 128.0f) + 1e-6f);
    float4 r = make_float4((f.x - mu) * rs, (f.y - mu) * rs, (f.z - mu) * rs, (f.w - mu) * rs);
    *(float4*)(y + (size_t)row * 128 + lane * 4) = r;
}

__global__ void ln512_kernel(const float* __restrict__ x, float* __restrict__ y,
                             const float* __restrict__ g, const float* __restrict__ b)
{
    const int warp = threadIdx.x >> 5, lane = threadIdx.x & 31;
    const int row = blockIdx.x * 8 + warp;
    const float* xr = x + (size_t)row * 512;
    float v[16];
    float s = 0.f;
    #pragma unroll
    for (int c = 0; c < 4; c++) {
        float4 f = *(const float4*)(xr + c * 128 + lane * 4);
        v[c * 4 + 0] = f.x; v[c * 4 + 1] = f.y; v[c * 4 + 2] = f.z; v[c * 4 + 3] = f.w;
        s += f.x + f.y + f.z + f.w;
    }
    #pragma unroll
    for (int o = 16; o; o >>= 1) s += __shfl_xor_sync(0xffffffffu, s, o);
    const float mu = s * (1.0f / 512.0f);
    float q = 0.f;
    #pragma unroll
    for (int k = 0; k < 16; k++) { float d = v[k] - mu; q += d * d; }
    #pragma unroll
    for (int o = 16; o; o >>= 1) q += __shfl_xor_sync(0xffffffffu, q, o);
    const float rs = rsqrtf(q * (1.0f / 512.0f) + 1e-5f);
    #pragma unroll
    for (int c = 0; c < 4; c++) {
        const int col = c * 128 + lane * 4;
        float4 gg = *(const float4*)(g + col);
        float4 bb = *(const float4*)(b + col);
        float4 r;
        r.x = gg.x * (v[c * 4 + 0] - mu) * rs + bb.x;
        r.y = gg.y * (v[c * 4 + 1] - mu) * rs + bb.y;
        r.z = gg.z * (v[c * 4 + 2] - mu) * rs + bb.z;
        r.w = gg.w * (v[c * 4 + 3] - mu) * rs + bb.w;
        *(float4*)(y + (size_t)row * 512 + col) = r;
    }
}

__global__ void freqadd_kernel(float* __restrict__ h, const float* __restrict__ emb,
                               const int* __restrict__ fid)
{
    const int i = blockIdx.x * 256 + threadIdx.x;
    const int row = i >> 9, d = i & 511, b = row >> 7;
    h[i] += emb[(size_t)fid[b] * 512 + d];
}

__global__ void attn_kernel(const float* __restrict__ qkv, float* __restrict__ o)
{
    const int gw = blockIdx.x * 8 + (threadIdx.x >> 5);
    const int lane = threadIdx.x & 31;
    const int i = gw & 127, hh = (gw >> 7) & 7, b = gw >> 10;
    const float* base = qkv + (size_t)b * 128 * 1536;
    const float* qp = base + (size_t)i * 1536 + hh * 64 + lane * 2;
    const float qx = qp[0], qy = qp[1];
    const float* kp = base + 512  + hh * 64 + lane * 2;
    const float* vp = base + 1024 + hh * 64 + lane * 2;
    float m = -1e30f, l = 0.f, ox = 0.f, oy = 0.f;
    for (int j = 0; j <= i; j++) {
        float2 k2 = *(const float2*)(kp + (size_t)j * 1536);
        float p = qx * k2.x + qy * k2.y;
        #pragma unroll
        for (int off = 16; off; off >>= 1) p += __shfl_xor_sync(0xffffffffu, p, off);
        const float s = p * 0.125f;
        const float nm = fmaxf(m, s);
        const float sc = __expf(m - nm), e = __expf(s - nm);
        l = l * sc + e;
        float2 v2 = *(const float2*)(vp + (size_t)j * 1536);
        ox = ox * sc + e * v2.x;
        oy = oy * sc + e * v2.y;
        m = nm;
    }
    const float inv = 1.0f / l;
    float* op = o + ((size_t)b * 128 + i) * 512 + hh * 64 + lane * 2;
    op[0] = ox * inv; op[1] = oy * inv;
}

__global__ void zero_cnt_kernel(int* cnt)
{
    if (threadIdx.x < 4) cnt[threadIdx.x] = 0;
}

__global__ void gate_route_kernel(const float* __restrict__ hn, const float* __restrict__ gw,
                                  const float* __restrict__ gb,
                                  int* __restrict__ cnt, int* __restrict__ idx,
                                  float* __restrict__ rw)
{
    const int warp = threadIdx.x >> 5, lane = threadIdx.x & 31;
    const int row = blockIdx.x * 8 + warp;
    const float* xr = hn + (size_t)row * 512;
    float a0 = 0.f, a1 = 0.f, a2 = 0.f, a3 = 0.f;
    for (int d = lane; d < 512; d += 32) {
        const float hv = xr[d];
        float4 w = *(const float4*)(gw + (size_t)d * 4);
        a0 += hv * w.x; a1 += hv * w.y; a2 += hv * w.z; a3 += hv * w.w;
    }
    #pragma unroll
    for (int o = 16; o; o >>= 1) {
        a0 += __shfl_xor_sync(0xffffffffu, a0, o);
        a1 += __shfl_xor_sync(0xffffffffu, a1, o);
        a2 += __shfl_xor_sync(0xffffffffu, a2, o);
        a3 += __shfl_xor_sync(0xffffffffu, a3, o);
    }
    if (lane == 0) {
        float p[4] = {a0 + gb[0], a1 + gb[1], a2 + gb[2], a3 + gb[3]};
        const float mx = fmaxf(fmaxf(p[0], p[1]), fmaxf(p[2], p[3]));
        float s = 0.f;
        #pragma unroll
        for (int e = 0; e < 4; e++) { p[e] = expf(p[e] - mx); s += p[e]; }
        const float invs = 1.0f / s;
        #pragma unroll
        for (int e = 0; e < 4; e++) p[e] *= invs;
        int i0 = 0;
        #pragma unroll
        for (int e = 1; e < 4; e++) if (p[e] > p[i0]) i0 = e;
        int i1 = -1;
        #pragma unroll
        for (int e = 0; e < 4; e++) if (e != i0 && (i1 < 0 || p[e] > p[i1])) i1 = e;
        int s0 = atomicAdd(&cnt[i0], 1);
        idx[i0 * T_TOK + s0] = row; rw[i0 * T_TOK + s0] = p[i0];
        int s1 = atomicAdd(&cnt[i1], 1);
        idx[i1 * T_TOK + s1] = row; rw[i1 * T_TOK + s1] = p[i1];
    }
}

__global__ void head_kernel(const float* __restrict__ h,
                            const float* __restrict__ fng, const float* __restrict__ fnb,
                            const float* __restrict__ hg,  const float* __restrict__ hb,
                            const float* __restrict__ hw,  const float* __restrict__ hbias,
                            float* __restrict__ out, int out_size)
{
    const int warp = threadIdx.x >> 5, lane = threadIdx.x & 31;
    const int b = warp;
    const float* xr = h + ((size_t)b * 128 + 127) * 512;
    float v[16];
    float s = 0.f;
    #pragma unroll
    for (int c = 0; c < 4; c++) {
        float4 f = *(const float4*)(xr + c * 128 + lane * 4);
        v[c * 4 + 0] = f.x; v[c * 4 + 1] = f.y; v[c * 4 + 2] = f.z; v[c * 4 + 3] = f.w;
        s += f.x + f.y + f.z + f.w;
    }
    #pragma unroll
    for (int o = 16; o; o >>= 1) s += __shfl_xor_sync(0xffffffffu, s, o);
    float mu = s * (1.0f / 512.0f);
    float q = 0.f;
    #pragma unroll
    for (int k = 0; k < 16; k++) { float d = v[k] - mu; q += d * d; }
    #pragma unroll
    for (int o = 16; o; o >>= 1) q += __shfl_xor_sync(0xffffffffu, q, o);
    float rs = rsqrtf(q * (1.0f / 512.0f) + 1e-5f);
    #pragma unroll
    for (int c = 0; c < 4; c++)
        #pragma unroll
        for (int j = 0; j < 4; j++) {
            const int col = c * 128 + lane * 4 + j;
            v[c * 4 + j] = fng[col] * (v[c * 4 + j] - mu) * rs + fnb[col];
        }
    s = 0.f;
    #pragma unroll
    for (int k = 0; k < 16; k++) s += v[k];
    #pragma unroll
    for (int o = 16; o; o >>= 1) s += __shfl_xor_sync(0xffffffffu, s, o);
    mu = s * (1.0f / 512.0f);
    q = 0.f;
    #pragma unroll
    for (int k = 0; k < 16; k++) { float d = v[k] - mu; q += d * d; }
    #pragma unroll
    for (int o = 16; o; o >>= 1) q += __shfl_xor_sync(0xffffffffu, q, o);
    rs = rsqrtf(q * (1.0f / 512.0f) + 1e-5f);
    float dot = 0.f;
    #pragma unroll
    for (int c = 0; c < 4; c++)
        #pragma unroll
        for (int j = 0; j < 4; j++) {
            const int col = c * 128 + lane * 4 + j;
            const float hl = hg[col] * (v[c * 4 + j] - mu) * rs + hb[col];
            dot += hl * hw[col];
        }
    #pragma unroll
    for (int o = 16; o; o >>= 1) dot += __shfl_xor_sync(0xffffffffu, dot, o);
    if (lane == 0) {
        const float logit = dot + hbias[0];
        if (out_size >= 32) {
            out[b] = logit;
            out[16 + b] = 1.0f / (1.0f + expf(-logit));
        } else {
            out[b] = logit;
        }
    }
}

// ---------------------------------------------------------------------------
extern "C" void kernel_launch(void* const* d_in, const int* in_sizes, int n_in,
                              void* d_out, int out_size)
{
    const float* x        = (const float*)d_in[0];
    const int*   fid      = (const int*)  d_in[1];
    const float* ir_w1    = (const float*)d_in[2];
    const float* ir_b1    = (const float*)d_in[3];
    const float* ir_w2    = (const float*)d_in[4];
    const float* ir_b2    = (const float*)d_in[5];
    const float* p2m_w    = (const float*)d_in[6];
    const float* p2m_b    = (const float*)d_in[7];
    const float* freq_emb = (const float*)d_in[8];
    const float* ln1_g    = (const float*)d_in[9];
    const float* ln1_b    = (const float*)d_in[10];
    const float* qkv_w    = (const float*)d_in[11];
    const float* qkv_b    = (const float*)d_in[12];
    const float* out_w    = (const float*)d_in[13];
    const float* out_b    = (const float*)d_in[14];
    const float* ln2_g    = (const float*)d_in[15];
    const float* ln2_b    = (const float*)d_in[16];
    const float* gate_w   = (const float*)d_in[17];
    const float* gate_b   = (const float*)d_in[18];
    const float* exp_w1   = (const float*)d_in[19];
    const float* exp_b1   = (const float*)d_in[20];
    const float* exp_w2   = (const float*)d_in[21];
    const float* exp_b2   = (const float*)d_in[22];
    const float* fn_g     = (const float*)d_in[23];
    const float* fn_b     = (const float*)d_in[24];
    const float* head_g   = (const float*)d_in[25];
    const float* head_b   = (const float*)d_in[26];
    const float* head_w   = (const float*)d_in[27];
    const float* head_bias= (const float*)d_in[28];

    float *patches, *tmp, *hp, *h, *hn, *qkv, *attn, *eh, *rw;
    int *cnt, *idx;
    cudaGetSymbolAddress((void**)&patches, g_patches);
    cudaGetSymbolAddress((void**)&tmp,     g_tmp);
    cudaGetSymbolAddress((void**)&hp,      g_hp);
    cudaGetSymbolAddress((void**)&h,       g_h);
    cudaGetSymbolAddress((void**)&hn,      g_hn);
    cudaGetSymbolAddress((void**)&qkv,     g_qkv);
    cudaGetSymbolAddress((void**)&attn,    g_attn);
    cudaGetSymbolAddress((void**)&eh,      g_eh);
    cudaGetSymbolAddress((void**)&cnt,     g_cnt);
    cudaGetSymbolAddress((void**)&idx,     g_idx);
    cudaGetSymbolAddress((void**)&rw,      g_rw);

    cudaFuncSetAttribute(mma_gemm<0,false,false,false>, cudaFuncAttributeMaxDynamicSharedMemorySize, SMEM_MMA);
    cudaFuncSetAttribute(mma_gemm<1,false,false,false>, cudaFuncAttributeMaxDynamicSharedMemorySize, SMEM_MMA);
    cudaFuncSetAttribute(mma_gemm<2,false,false,false>, cudaFuncAttributeMaxDynamicSharedMemorySize, SMEM_MMA);
    cudaFuncSetAttribute(mma_gemm<3,false,false,false>, cudaFuncAttributeMaxDynamicSharedMemorySize, SMEM_MMA);
    cudaFuncSetAttribute(mma_gemm<1,true,true,true>,    cudaFuncAttributeMaxDynamicSharedMemorySize, SMEM_MMA);
    cudaFuncSetAttribute(mma_gemm<5,false,true,true>,   cudaFuncAttributeMaxDynamicSharedMemorySize, SMEM_MMA);

    const size_t EHZ = (size_t)T_TOK * HDIM;

    // Front end
    patchnorm_kernel<<<256, 256>>>(x, patches);
    mma_gemm<1,false,false,false><<<dim3(4, 32), 256, SMEM_MMA>>>(patches, ir_w1, ir_b1, tmp,
        T_TOK, 512, 128, nullptr, nullptr, nullptr, nullptr, 0, 0);
    mma_gemm<2,false,false,false><<<dim3(1, 32), 256, SMEM_MMA>>>(tmp, ir_w2, ir_b2, hp,
        T_TOK, 128, 512, patches, nullptr, nullptr, nullptr, 0, 0);
    mma_gemm<0,false,false,false><<<dim3(4, 32), 256, SMEM_MMA>>>(hp, p2m_w, p2m_b, h,
        T_TOK, 512, 128, nullptr, nullptr, nullptr, nullptr, 0, 0);
    freqadd_kernel<<<(T_TOK * 512) / 256, 256>>>(h, freq_emb, fid);

    for (int l = 0; l < 12; l++) {
        // attention
        ln512_kernel<<<256, 256>>>(h, hn, ln1_g + (size_t)l * 512, ln1_b + (size_t)l * 512);
        mma_gemm<0,false,false,false><<<dim3(12, 32), 256, SMEM_MMA>>>(hn,
            qkv_w + (size_t)l * 512 * 1536, qkv_b + (size_t)l * 1536, qkv,
            T_TOK, 1536, 512, nullptr, nullptr, nullptr, nullptr, 0, 0);
        attn_kernel<<<2048, 256>>>(qkv, attn);
        mma_gemm<3,false,false,false><<<dim3(4, 32), 256, SMEM_MMA>>>(attn,
            out_w + (size_t)l * 512 * 512, out_b + (size_t)l * 512, h,
            T_TOK, 512, 512, nullptr, nullptr, nullptr, nullptr, 0, 0);
        // sparse MoE (4 experts fused via blockIdx.z)
        ln512_kernel<<<256, 256>>>(h, hn, ln2_g + (size_t)l * 512, ln2_b + (size_t)l * 512);
        zero_cnt_kernel<<<1, 32>>>(cnt);
        gate_route_kernel<<<256, 256>>>(hn, gate_w + (size_t)l * 512 * 4,
                                        gate_b + (size_t)l * 4, cnt, idx, rw);
        mma_gemm<1,true,true,true><<<dim3(16, 32, 4), 256, SMEM_MMA>>>(hn,
            exp_w1 + (size_t)l * 4 * 512 * 2048, exp_b1 + (size_t)l * 4 * 2048, eh,
            T_TOK, 2048, 512, nullptr, idx, nullptr, cnt, 0, EHZ);
        mma_gemm<5,false,true,true><<<dim3(4, 32, 4), 256, SMEM_MMA>>>(eh,
            exp_w2 + (size_t)l * 4 * 2048 * 512, exp_b2 + (size_t)l * 4 * 512, h,
            T_TOK, 512, 2048, nullptr, idx, rw, cnt, EHZ, 0);
    }

    head_kernel<<<1, 512>>>(h, fn_g, fn_b, head_g, head_b, head_w, head_bias,
                            (float*)d_out, out_size);
}

// round 10
// speedup vs baseline: 4.0081x; 1.1414x over previous
#include <cuda_runtime.h>
#include <cuda_fp16.h>
#include <math.h>
#include <stdint.h>

// ---------------------------------------------------------------------------
// B=16, S=2048, C=8, P=16 -> N=128 patches, T=2048 tokens
// PD=128, IRH=512, D=512, NH=8, dh=64, L=12, E=4, H=2048, top-2 routing
// GEMMs: mma.sync m16n8k16 f16 split-precision, pre-split smem tiles.
// Attention: block flash, thread-per-query, dynamic smem K/V broadcast.
// ---------------------------------------------------------------------------
#define T_TOK 2048
#define DIM   512
#define HDIM  2048

__device__ float g_patches[T_TOK * 128];
__device__ float g_tmp    [T_TOK * 512];
__device__ float g_hp     [T_TOK * 128];
__device__ float g_h      [T_TOK * DIM];
__device__ float g_hn     [T_TOK * DIM];
__device__ float g_qkv    [T_TOK * 3 * DIM];
__device__ float g_attn   [T_TOK * DIM];
__device__ float g_eh     [4 * T_TOK * HDIM];
__device__ int   g_cnt    [4];
__device__ int   g_idx    [4 * T_TOK];
__device__ float g_rw     [4 * T_TOK];

// ---- helpers ---------------------------------------------------------------
__device__ __forceinline__ void split2(float f0, float f1, uint32_t& hi, uint32_t& lo) {
    __half2 h = __floats2half2_rn(f0, f1);
    float2 hf = __half22float2(h);
    __half2 l = __floats2half2_rn(f0 - hf.x, f1 - hf.y);
    hi = *(uint32_t*)&h;
    lo = *(uint32_t*)&l;
}
__device__ __forceinline__ void mma_f16(float* d, const uint32_t* a, const uint32_t* b) {
    asm volatile(
        "mma.sync.aligned.m16n8k16.row.col.f32.f16.f16.f32 "
        "{%0,%1,%2,%3}, {%4,%5,%6,%7}, {%8,%9}, {%0,%1,%2,%3};"
        : "+f"(d[0]), "+f"(d[1]), "+f"(d[2]), "+f"(d[3])
        : "r"(a[0]), "r"(a[1]), "r"(a[2]), "r"(a[3]), "r"(b[0]), "r"(b[1]));
}

// smem layout (halves): stride 40 per row (conflict-free frag LDS)
#define KST 40
#define AH_SZ (64 * KST)
#define BH_SZ (128 * KST)
#define OFF_AH(b) ((b) * AH_SZ)
#define OFF_AL(b) (2 * AH_SZ + (b) * AH_SZ)
#define OFF_BH(b) (4 * AH_SZ + (b) * BH_SZ)
#define OFF_BL(b) (4 * AH_SZ + 2 * BH_SZ + (b) * BH_SZ)
#define SMEM_MMA ((4 * AH_SZ + 4 * BH_SZ) * 2)   // 61440 bytes

// ---------------------------------------------------------------------------
// EPI: 0 store, 1 gelu, 2 res+v, 3 C+=v, 5 atomic scatter C[idx[r]] += rw[r]*v
// ---------------------------------------------------------------------------
template<int EPI, bool GA, bool GUARD, bool EXPZ>
__global__ void __launch_bounds__(256, 2) mma_gemm(
    const float* __restrict__ A, const float* __restrict__ B,
    const float* __restrict__ bias, float* __restrict__ C,
    int M, int N, int K,
    const float* __restrict__ res,
    const int* __restrict__ idx,
    const float* __restrict__ rw,
    const int* __restrict__ cnt,
    size_t zA, size_t zC)
{
    if (EXPZ) {
        const int z = blockIdx.z;
        A    += (size_t)z * zA;
        B    += (size_t)z * K * N;
        bias += (size_t)z * N;
        C    += (size_t)z * zC;
        idx  += z * T_TOK;
        if (rw) rw += z * T_TOK;
        cnt  += z;
    }
    const int t = threadIdx.x, wid = t >> 5, lane = t & 31;
    const int m0 = blockIdx.y * 64, n0 = blockIdx.x * 128;

    int cq = M;
    if (GUARD) { cq = *cnt; if (m0 >= cq) return; }

    extern __shared__ __half sh[];

    const int arow = t >> 2, akof = (t & 3) * 8;
    int garow = m0 + arow;
    if (GA) garow = (garow < cq) ? idx[garow] : idx[0];
    const float* Agp = A + (size_t)garow * K + akof;
    const int nB = t & 127, kk2 = t >> 7;
    const float* Bcol = B + n0 + nB;

    const int wm = wid >> 2, wn = wid & 3;
    const int gid = lane >> 2, tig = lane & 3;

    float4 pa0, pa1;
    float pb[16];

    pa0 = *(const float4*)(Agp);
    pa1 = *(const float4*)(Agp + 4);
    #pragma unroll
    for (int i = 0; i < 4; i++)
        #pragma unroll
        for (int jj = 0; jj < 4; jj++)
            pb[i * 4 + jj] = Bcol[(size_t)(kk2 * 16 + i * 4 + jj) * N];
    {
        uint32_t h0,l0,h1,l1,h2,l2,h3,l3;
        split2(pa0.x, pa0.y, h0, l0); split2(pa0.z, pa0.w, h1, l1);
        split2(pa1.x, pa1.y, h2, l2); split2(pa1.z, pa1.w, h3, l3);
        *(uint4*)&sh[OFF_AH(0) + arow * KST + akof] = make_uint4(h0,h1,h2,h3);
        *(uint4*)&sh[OFF_AL(0) + arow * KST + akof] = make_uint4(l0,l1,l2,l3);
        #pragma unroll
        for (int i = 0; i < 4; i++) {
            const int kb = kk2 * 16 + i * 4;
            uint32_t bh0,bl0,bh1,bl1;
            split2(pb[i*4+0], pb[i*4+1], bh0, bl0);
            split2(pb[i*4+2], pb[i*4+3], bh1, bl1);
            *(uint2*)&sh[OFF_BH(0) + nB * KST + kb] = make_uint2(bh0, bh1);
            *(uint2*)&sh[OFF_BL(0) + nB * KST + kb] = make_uint2(bl0, bl1);
        }
    }
    __syncthreads();

    float acc[2][4][4];
    #pragma unroll
    for (int i = 0; i < 2; i++)
        #pragma unroll
        for (int j = 0; j < 4; j++)
            #pragma unroll
            for (int q = 0; q < 4; q++) acc[i][j][q] = 0.f;

    const int nkt = K >> 5;
    for (int j = 0; j < nkt; j++) {
        const int cur = j & 1;
        const bool more = (j + 1 < nkt);
        if (more) {
            const int k0 = (j + 1) << 5;
            pa0 = *(const float4*)(Agp + k0);
            pa1 = *(const float4*)(Agp + k0 + 4);
            #pragma unroll
            for (int i = 0; i < 4; i++)
                #pragma unroll
                for (int jj = 0; jj < 4; jj++)
                    pb[i * 4 + jj] = Bcol[(size_t)(k0 + kk2 * 16 + i * 4 + jj) * N];
        }
        {
            const __half* Ah = sh + OFF_AH(cur);
            const __half* Al = sh + OFF_AL(cur);
            const __half* Bh = sh + OFF_BH(cur);
            const __half* Bl = sh + OFF_BL(cur);
            #pragma unroll
            for (int ks = 0; ks < 2; ks++) {
                const int kb = ks * 16 + tig * 2;
                uint32_t bh[4][2], bl[4][2];
                #pragma unroll
                for (int ni = 0; ni < 4; ni++) {
                    const int n = (wn * 32 + ni * 8 + gid) * KST + kb;
                    bh[ni][0] = *(const uint32_t*)&Bh[n];
                    bh[ni][1] = *(const uint32_t*)&Bh[n + 8];
                    bl[ni][0] = *(const uint32_t*)&Bl[n];
                    bl[ni][1] = *(const uint32_t*)&Bl[n + 8];
                }
                #pragma unroll
                for (int mi = 0; mi < 2; mi++) {
                    const int r = (wm * 32 + mi * 16 + gid) * KST + kb;
                    uint32_t ah[4], al[4];
                    ah[0] = *(const uint32_t*)&Ah[r];
                    ah[1] = *(const uint32_t*)&Ah[r + 8 * KST];
                    ah[2] = *(const uint32_t*)&Ah[r + 8];
                    ah[3] = *(const uint32_t*)&Ah[r + 8 * KST + 8];
                    al[0] = *(const uint32_t*)&Al[r];
                    al[1] = *(const uint32_t*)&Al[r + 8 * KST];
                    al[2] = *(const uint32_t*)&Al[r + 8];
                    al[3] = *(const uint32_t*)&Al[r + 8 * KST + 8];
                    #pragma unroll
                    for (int ni = 0; ni < 4; ni++) {
                        mma_f16(acc[mi][ni], ah, bh[ni]);
                        mma_f16(acc[mi][ni], ah, bl[ni]);
                        mma_f16(acc[mi][ni], al, bh[ni]);
                    }
                }
            }
        }
        if (more) {
            const int nxt = cur ^ 1;
            uint32_t h0,l0,h1,l1,h2,l2,h3,l3;
            split2(pa0.x, pa0.y, h0, l0); split2(pa0.z, pa0.w, h1, l1);
            split2(pa1.x, pa1.y, h2, l2); split2(pa1.z, pa1.w, h3, l3);
            *(uint4*)&sh[OFF_AH(nxt) + arow * KST + akof] = make_uint4(h0,h1,h2,h3);
            *(uint4*)&sh[OFF_AL(nxt) + arow * KST + akof] = make_uint4(l0,l1,l2,l3);
            #pragma unroll
            for (int i = 0; i < 4; i++) {
                const int kb = kk2 * 16 + i * 4;
                uint32_t bh0,bl0,bh1,bl1;
                split2(pb[i*4+0], pb[i*4+1], bh0, bl0);
                split2(pb[i*4+2], pb[i*4+3], bh1, bl1);
                *(uint2*)&sh[OFF_BH(nxt) + nB * KST + kb] = make_uint2(bh0, bh1);
                *(uint2*)&sh[OFF_BL(nxt) + nB * KST + kb] = make_uint2(bl0, bl1);
            }
            __syncthreads();
        }
    }

    #pragma unroll
    for (int mi = 0; mi < 2; mi++) {
        #pragma unroll
        for (int half = 0; half < 2; half++) {
            const int row = m0 + wm * 32 + mi * 16 + gid + half * 8;
            if (GUARD && row >= cq) continue;
            #pragma unroll
            for (int ni = 0; ni < 4; ni++) {
                const int col = n0 + wn * 32 + ni * 8 + tig * 2;
                float vx = acc[mi][ni][half * 2 + 0] + bias[col];
                float vy = acc[mi][ni][half * 2 + 1] + bias[col + 1];
                if (EPI == 5) {
                    const float w = rw[row];
                    float* dst = C + (size_t)idx[row] * N + col;
                    atomicAdd(dst,     w * vx);
                    atomicAdd(dst + 1, w * vy);
                } else {
                    float* dst = C + (size_t)row * N + col;
                    if (EPI == 1) {
                        vx = 0.5f * vx * (1.0f + erff(vx * 0.70710678118654752f));
                        vy = 0.5f * vy * (1.0f + erff(vy * 0.70710678118654752f));
                    } else if (EPI == 2) {
                        const float2 rr = *(const float2*)(res + (size_t)row * N + col);
                        vx += rr.x; vy += rr.y;
                    } else if (EPI == 3) {
                        const float2 cc = *(const float2*)dst;
                        vx += cc.x; vy += cc.y;
                    }
                    *(float2*)dst = make_float2(vx, vy);
                }
            }
        }
    }
}

// ---------------------------------------------------------------------------
// Flash attention: block per (b,head), thread per query row.
// K/V in DYNAMIC smem (broadcast reads); online softmax in registers.
// ---------------------------------------------------------------------------
#define KVP 68
#define SMEM_ATTN (2 * 128 * KVP * 4)   // 69632 bytes (dynamic, opt-in)

__global__ void __launch_bounds__(128) attn_flash(const float* __restrict__ qkv,
                                                  float* __restrict__ o)
{
    const int bh = blockIdx.x;
    const int b = bh >> 3, hh = bh & 7;
    const int t = threadIdx.x;               // query row
    const float* base = qkv + (size_t)b * 128 * 1536 + hh * 64;

    extern __shared__ float kv[];
    float (*Ks)[KVP] = (float(*)[KVP])kv;
    float (*Vs)[KVP] = (float(*)[KVP])(kv + 128 * KVP);

    {   // load K/V rows: thread t -> row t
        const float* kr = base + (size_t)t * 1536 + 512;
        const float* vr = kr + 512;
        #pragma unroll
        for (int d4 = 0; d4 < 16; d4++) {
            *(float4*)&Ks[t][d4 * 4] = *(const float4*)(kr + d4 * 4);
            *(float4*)&Vs[t][d4 * 4] = *(const float4*)(vr + d4 * 4);
        }
    }
    float q[64];
    {
        const float* qr = base + (size_t)t * 1536;
        #pragma unroll
        for (int d4 = 0; d4 < 16; d4++) {
            float4 f = *(const float4*)(qr + d4 * 4);
            q[d4 * 4 + 0] = f.x; q[d4 * 4 + 1] = f.y;
            q[d4 * 4 + 2] = f.z; q[d4 * 4 + 3] = f.w;
        }
    }
    __syncthreads();

    float oacc[64];
    #pragma unroll
    for (int d = 0; d < 64; d++) oacc[d] = 0.f;
    float m = -1e30f, l = 0.f;

    for (int j = 0; j <= t; j++) {           // warp-lockstep; Ks[j] broadcast
        float s = 0.f;
        #pragma unroll
        for (int d4 = 0; d4 < 16; d4++) {
            float4 k4 = *(const float4*)&Ks[j][d4 * 4];
            s += q[d4 * 4 + 0] * k4.x + q[d4 * 4 + 1] * k4.y
               + q[d4 * 4 + 2] * k4.z + q[d4 * 4 + 3] * k4.w;
        }
        s *= 0.125f;
        const float nm = fmaxf(m, s);
        const float sc = __expf(m - nm), e = __expf(s - nm);
        l = l * sc + e;
        m = nm;
        #pragma unroll
        for (int d4 = 0; d4 < 16; d4++) {
            float4 v4 = *(const float4*)&Vs[j][d4 * 4];
            oacc[d4 * 4 + 0] = oacc[d4 * 4 + 0] * sc + e * v4.x;
            oacc[d4 * 4 + 1] = oacc[d4 * 4 + 1] * sc + e * v4.y;
            oacc[d4 * 4 + 2] = oacc[d4 * 4 + 2] * sc + e * v4.z;
            oacc[d4 * 4 + 3] = oacc[d4 * 4 + 3] * sc + e * v4.w;
        }
    }
    const float inv = 1.0f / l;
    float* op = o + ((size_t)b * 128 + t) * 512 + hh * 64;
    #pragma unroll
    for (int d4 = 0; d4 < 16; d4++) {
        float4 r;
        r.x = oacc[d4 * 4 + 0] * inv; r.y = oacc[d4 * 4 + 1] * inv;
        r.z = oacc[d4 * 4 + 2] * inv; r.w = oacc[d4 * 4 + 3] * inv;
        *(float4*)(op + d4 * 4) = r;
    }
}

// ---------------------------------------------------------------------------
__global__ void patchnorm_kernel(const float* __restrict__ x, float* __restrict__ y)
{
    const int warp = threadIdx.x >> 5, lane = threadIdx.x & 31;
    const int row = blockIdx.x * 8 + warp;
    const float* xr = x + (size_t)row * 128;
    float4 f = *(const float4*)(xr + lane * 4);
    float s = f.x + f.y + f.z + f.w;
    #pragma unroll
    for (int o = 16; o; o >>= 1) s += __shfl_xor_sync(0xffffffffu, s, o);
    const float mu = s * (1.0f / 128.0f);
    float q = (f.x - mu) * (f.x - mu) + (f.y - mu) * (f.y - mu)
            + (f.z - mu) * (f.z - mu) + (f.w - mu) * (f.w - mu);
    #pragma unroll
    for (int o = 16; o; o >>= 1) q += __shfl_xor_sync(0xffffffffu, q, o);
    const float rs = rsqrtf(q * (1.0f / 128.0f) + 1e-6f);
    float4 r = make_float4((f.x - mu) * rs, (f.y - mu) * rs, (f.z - mu) * rs, (f.w - mu) * rs);
    *(float4*)(y + (size_t)row * 128 + lane * 4) = r;
}

__global__ void ln512_kernel(const float* __restrict__ x, float* __restrict__ y,
                             const float* __restrict__ g, const float* __restrict__ b)
{
    const int warp = threadIdx.x >> 5, lane = threadIdx.x & 31;
    const int row = blockIdx.x * 8 + warp;
    const float* xr = x + (size_t)row * 512;
    float v[16];
    float s = 0.f;
    #pragma unroll
    for (int c = 0; c < 4; c++) {
        float4 f = *(const float4*)(xr + c * 128 + lane * 4);
        v[c * 4 + 0] = f.x; v[c * 4 + 1] = f.y; v[c * 4 + 2] = f.z; v[c * 4 + 3] = f.w;
        s += f.x + f.y + f.z + f.w;
    }
    #pragma unroll
    for (int o = 16; o; o >>= 1) s += __shfl_xor_sync(0xffffffffu, s, o);
    const float mu = s * (1.0f / 512.0f);
    float q = 0.f;
    #pragma unroll
    for (int k = 0; k < 16; k++) { float d = v[k] - mu; q += d * d; }
    #pragma unroll
    for (int o = 16; o; o >>= 1) q += __shfl_xor_sync(0xffffffffu, q, o);
    const float rs = rsqrtf(q * (1.0f / 512.0f) + 1e-5f);
    #pragma unroll
    for (int c = 0; c < 4; c++) {
        const int col = c * 128 + lane * 4;
        float4 gg = *(const float4*)(g + col);
        float4 bb = *(const float4*)(b + col);
        float4 r;
        r.x = gg.x * (v[c * 4 + 0] - mu) * rs + bb.x;
        r.y = gg.y * (v[c * 4 + 1] - mu) * rs + bb.y;
        r.z = gg.z * (v[c * 4 + 2] - mu) * rs + bb.z;
        r.w = gg.w * (v[c * 4 + 3] - mu) * rs + bb.w;
        *(float4*)(y + (size_t)row * 512 + col) = r;
    }
}

__global__ void freqadd_kernel(float* __restrict__ h, const float* __restrict__ emb,
                               const int* __restrict__ fid)
{
    const int i = blockIdx.x * 256 + threadIdx.x;
    const int row = i >> 9, d = i & 511, b = row >> 7;
    h[i] += emb[(size_t)fid[b] * 512 + d];
}

__global__ void zero_cnt_kernel(int* cnt)
{
    if (threadIdx.x < 4) cnt[threadIdx.x] = 0;
}

__global__ void gate_route_kernel(const float* __restrict__ hn, const float* __restrict__ gw,
                                  const float* __restrict__ gb,
                                  int* __restrict__ cnt, int* __restrict__ idx,
                                  float* __restrict__ rw)
{
    const int warp = threadIdx.x >> 5, lane = threadIdx.x & 31;
    const int row = blockIdx.x * 8 + warp;
    const float* xr = hn + (size_t)row * 512;
    float a0 = 0.f, a1 = 0.f, a2 = 0.f, a3 = 0.f;
    for (int d = lane; d < 512; d += 32) {
        const float hv = xr[d];
        float4 w = *(const float4*)(gw + (size_t)d * 4);
        a0 += hv * w.x; a1 += hv * w.y; a2 += hv * w.z; a3 += hv * w.w;
    }
    #pragma unroll
    for (int o = 16; o; o >>= 1) {
        a0 += __shfl_xor_sync(0xffffffffu, a0, o);
        a1 += __shfl_xor_sync(0xffffffffu, a1, o);
        a2 += __shfl_xor_sync(0xffffffffu, a2, o);
        a3 += __shfl_xor_sync(0xffffffffu, a3, o);
    }
    if (lane == 0) {
        float p[4] = {a0 + gb[0], a1 + gb[1], a2 + gb[2], a3 + gb[3]};
        const float mx = fmaxf(fmaxf(p[0], p[1]), fmaxf(p[2], p[3]));
        float s = 0.f;
        #pragma unroll
        for (int e = 0; e < 4; e++) { p[e] = expf(p[e] - mx); s += p[e]; }
        const float invs = 1.0f / s;
        #pragma unroll
        for (int e = 0; e < 4; e++) p[e] *= invs;
        int i0 = 0;
        #pragma unroll
        for (int e = 1; e < 4; e++) if (p[e] > p[i0]) i0 = e;
        int i1 = -1;
        #pragma unroll
        for (int e = 0; e < 4; e++) if (e != i0 && (i1 < 0 || p[e] > p[i1])) i1 = e;
        int s0 = atomicAdd(&cnt[i0], 1);
        idx[i0 * T_TOK + s0] = row; rw[i0 * T_TOK + s0] = p[i0];
        int s1 = atomicAdd(&cnt[i1], 1);
        idx[i1 * T_TOK + s1] = row; rw[i1 * T_TOK + s1] = p[i1];
    }
}

__global__ void head_kernel(const float* __restrict__ h,
                            const float* __restrict__ fng, const float* __restrict__ fnb,
                            const float* __restrict__ hg,  const float* __restrict__ hb,
                            const float* __restrict__ hw,  const float* __restrict__ hbias,
                            float* __restrict__ out, int out_size)
{
    const int warp = threadIdx.x >> 5, lane = threadIdx.x & 31;
    const int b = warp;
    const float* xr = h + ((size_t)b * 128 + 127) * 512;
    float v[16];
    float s = 0.f;
    #pragma unroll
    for (int c = 0; c < 4; c++) {
        float4 f = *(const float4*)(xr + c * 128 + lane * 4);
        v[c * 4 + 0] = f.x; v[c * 4 + 1] = f.y; v[c * 4 + 2] = f.z; v[c * 4 + 3] = f.w;
        s += f.x + f.y + f.z + f.w;
    }
    #pragma unroll
    for (int o = 16; o; o >>= 1) s += __shfl_xor_sync(0xffffffffu, s, o);
    float mu = s * (1.0f / 512.0f);
    float q = 0.f;
    #pragma unroll
    for (int k = 0; k < 16; k++) { float d = v[k] - mu; q += d * d; }
    #pragma unroll
    for (int o = 16; o; o >>= 1) q += __shfl_xor_sync(0xffffffffu, q, o);
    float rs = rsqrtf(q * (1.0f / 512.0f) + 1e-5f);
    #pragma unroll
    for (int c = 0; c < 4; c++)
        #pragma unroll
        for (int j = 0; j < 4; j++) {
            const int col = c * 128 + lane * 4 + j;
            v[c * 4 + j] = fng[col] * (v[c * 4 + j] - mu) * rs + fnb[col];
        }
    s = 0.f;
    #pragma unroll
    for (int k = 0; k < 16; k++) s += v[k];
    #pragma unroll
    for (int o = 16; o; o >>= 1) s += __shfl_xor_sync(0xffffffffu, s, o);
    mu = s * (1.0f / 512.0f);
    q = 0.f;
    #pragma unroll
    for (int k = 0; k < 16; k++) { float d = v[k] - mu; q += d * d; }
    #pragma unroll
    for (int o = 16; o; o >>= 1) q += __shfl_xor_sync(0xffffffffu, q, o);
    rs = rsqrtf(q * (1.0f / 512.0f) + 1e-5f);
    float dot = 0.f;
    #pragma unroll
    for (int c = 0; c < 4; c++)
        #pragma unroll
        for (int j = 0; j < 4; j++) {
            const int col = c * 128 + lane * 4 + j;
            const float hl = hg[col] * (v[c * 4 + j] - mu) * rs + hb[col];
            dot += hl * hw[col];
        }
    #pragma unroll
    for (int o = 16; o; o >>= 1) dot += __shfl_xor_sync(0xffffffffu, dot, o);
    if (lane == 0) {
        const float logit = dot + hbias[0];
        if (out_size >= 32) {
            out[b] = logit;
            out[16 + b] = 1.0f / (1.0f + expf(-logit));
        } else {
            out[b] = logit;
        }
    }
}

// ---------------------------------------------------------------------------
extern "C" void kernel_launch(void* const* d_in, const int* in_sizes, int n_in,
                              void* d_out, int out_size)
{
    const float* x        = (const float*)d_in[0];
    const int*   fid      = (const int*)  d_in[1];
    const float* ir_w1    = (const float*)d_in[2];
    const float* ir_b1    = (const float*)d_in[3];
    const float* ir_w2    = (const float*)d_in[4];
    const float* ir_b2    = (const float*)d_in[5];
    const float* p2m_w    = (const float*)d_in[6];
    const float* p2m_b    = (const float*)d_in[7];
    const float* freq_emb = (const float*)d_in[8];
    const float* ln1_g    = (const float*)d_in[9];
    const float* ln1_b    = (const float*)d_in[10];
    const float* qkv_w    = (const float*)d_in[11];
    const float* qkv_b    = (const float*)d_in[12];
    const float* out_w    = (const float*)d_in[13];
    const float* out_b    = (const float*)d_in[14];
    const float* ln2_g    = (const float*)d_in[15];
    const float* ln2_b    = (const float*)d_in[16];
    const float* gate_w   = (const float*)d_in[17];
    const float* gate_b   = (const float*)d_in[18];
    const float* exp_w1   = (const float*)d_in[19];
    const float* exp_b1   = (const float*)d_in[20];
    const float* exp_w2   = (const float*)d_in[21];
    const float* exp_b2   = (const float*)d_in[22];
    const float* fn_g     = (const float*)d_in[23];
    const float* fn_b     = (const float*)d_in[24];
    const float* head_g   = (const float*)d_in[25];
    const float* head_b   = (const float*)d_in[26];
    const float* head_w   = (const float*)d_in[27];
    const float* head_bias= (const float*)d_in[28];

    float *patches, *tmp, *hp, *h, *hn, *qkv, *attn, *eh, *rw;
    int *cnt, *idx;
    cudaGetSymbolAddress((void**)&patches, g_patches);
    cudaGetSymbolAddress((void**)&tmp,     g_tmp);
    cudaGetSymbolAddress((void**)&hp,      g_hp);
    cudaGetSymbolAddress((void**)&h,       g_h);
    cudaGetSymbolAddress((void**)&hn,      g_hn);
    cudaGetSymbolAddress((void**)&qkv,     g_qkv);
    cudaGetSymbolAddress((void**)&attn,    g_attn);
    cudaGetSymbolAddress((void**)&eh,      g_eh);
    cudaGetSymbolAddress((void**)&cnt,     g_cnt);
    cudaGetSymbolAddress((void**)&idx,     g_idx);
    cudaGetSymbolAddress((void**)&rw,      g_rw);

    cudaFuncSetAttribute(mma_gemm<0,false,false,false>, cudaFuncAttributeMaxDynamicSharedMemorySize, SMEM_MMA);
    cudaFuncSetAttribute(mma_gemm<1,false,false,false>, cudaFuncAttributeMaxDynamicSharedMemorySize, SMEM_MMA);
    cudaFuncSetAttribute(mma_gemm<2,false,false,false>, cudaFuncAttributeMaxDynamicSharedMemorySize, SMEM_MMA);
    cudaFuncSetAttribute(mma_gemm<3,false,false,false>, cudaFuncAttributeMaxDynamicSharedMemorySize, SMEM_MMA);
    cudaFuncSetAttribute(mma_gemm<1,true,true,true>,    cudaFuncAttributeMaxDynamicSharedMemorySize, SMEM_MMA);
    cudaFuncSetAttribute(mma_gemm<5,false,true,true>,   cudaFuncAttributeMaxDynamicSharedMemorySize, SMEM_MMA);
    cudaFuncSetAttribute(attn_flash, cudaFuncAttributeMaxDynamicSharedMemorySize, SMEM_ATTN);

    const size_t EHZ = (size_t)T_TOK * HDIM;

    // Front end
    patchnorm_kernel<<<256, 256>>>(x, patches);
    mma_gemm<1,false,false,false><<<dim3(4, 32), 256, SMEM_MMA>>>(patches, ir_w1, ir_b1, tmp,
        T_TOK, 512, 128, nullptr, nullptr, nullptr, nullptr, 0, 0);
    mma_gemm<2,false,false,false><<<dim3(1, 32), 256, SMEM_MMA>>>(tmp, ir_w2, ir_b2, hp,
        T_TOK, 128, 512, patches, nullptr, nullptr, nullptr, 0, 0);
    mma_gemm<0,false,false,false><<<dim3(4, 32), 256, SMEM_MMA>>>(hp, p2m_w, p2m_b, h,
        T_TOK, 512, 128, nullptr, nullptr, nullptr, nullptr, 0, 0);
    freqadd_kernel<<<(T_TOK * 512) / 256, 256>>>(h, freq_emb, fid);

    for (int l = 0; l < 12; l++) {
        // attention
        ln512_kernel<<<256, 256>>>(h, hn, ln1_g + (size_t)l * 512, ln1_b + (size_t)l * 512);
        mma_gemm<0,false,false,false><<<dim3(12, 32), 256, SMEM_MMA>>>(hn,
            qkv_w + (size_t)l * 512 * 1536, qkv_b + (size_t)l * 1536, qkv,
            T_TOK, 1536, 512, nullptr, nullptr, nullptr, nullptr, 0, 0);
        attn_flash<<<128, 128, SMEM_ATTN>>>(qkv, attn);
        mma_gemm<3,false,false,false><<<dim3(4, 32), 256, SMEM_MMA>>>(attn,
            out_w + (size_t)l * 512 * 512, out_b + (size_t)l * 512, h,
            T_TOK, 512, 512, nullptr, nullptr, nullptr, nullptr, 0, 0);
        // sparse MoE (4 experts fused via blockIdx.z)
        ln512_kernel<<<256, 256>>>(h, hn, ln2_g + (size_t)l * 512, ln2_b + (size_t)l * 512);
        zero_cnt_kernel<<<1, 32>>>(cnt);
        gate_route_kernel<<<256, 256>>>(hn, gate_w + (size_t)l * 512 * 4,
                                        gate_b + (size_t)l * 4, cnt, idx, rw);
        mma_gemm<1,true,true,true><<<dim3(16, 32, 4), 256, SMEM_MMA>>>(hn,
            exp_w1 + (size_t)l * 4 * 512 * 2048, exp_b1 + (size_t)l * 4 * 2048, eh,
            T_TOK, 2048, 512, nullptr, idx, nullptr, cnt, 0, EHZ);
        mma_gemm<5,false,true,true><<<dim3(4, 32, 4), 256, SMEM_MMA>>>(eh,
            exp_w2 + (size_t)l * 4 * 2048 * 512, exp_b2 + (size_t)l * 4 * 512, h,
            T_TOK, 512, 2048, nullptr, idx, rw, cnt, EHZ, 0);
    }

    head_kernel<<<1, 512>>>(h, fn_g, fn_b, head_g, head_b, head_w, head_bias,
                            (float*)d_out, out_size);
}

// round 11
// speedup vs baseline: 4.1151x; 1.0267x over previous
#include <cuda_runtime.h>
#include <cuda_fp16.h>
#include <math.h>
#include <stdint.h>

// ---------------------------------------------------------------------------
// B=16, S=2048, C=8, P=16 -> N=128 patches, T=2048 tokens
// PD=128, IRH=512, D=512, NH=8, dh=64, L=12, E=4, H=2048, top-2 routing
// GEMMs: mma.sync m16n8k16 f16 split-precision, pre-split smem tiles,
// fragments loaded via ldmatrix.x4. Attention: block flash, dyn smem.
// ---------------------------------------------------------------------------
#define T_TOK 2048
#define DIM   512
#define HDIM  2048

__device__ float g_patches[T_TOK * 128];
__device__ float g_tmp    [T_TOK * 512];
__device__ float g_hp     [T_TOK * 128];
__device__ float g_h      [T_TOK * DIM];
__device__ float g_hn     [T_TOK * DIM];
__device__ float g_qkv    [T_TOK * 3 * DIM];
__device__ float g_attn   [T_TOK * DIM];
__device__ float g_eh     [4 * T_TOK * HDIM];
__device__ int   g_cnt    [4];
__device__ int   g_idx    [4 * T_TOK];
__device__ float g_rw     [4 * T_TOK];

// ---- helpers ---------------------------------------------------------------
__device__ __forceinline__ void split2(float f0, float f1, uint32_t& hi, uint32_t& lo) {
    __half2 h = __floats2half2_rn(f0, f1);
    float2 hf = __half22float2(h);
    __half2 l = __floats2half2_rn(f0 - hf.x, f1 - hf.y);
    hi = *(uint32_t*)&h;
    lo = *(uint32_t*)&l;
}
__device__ __forceinline__ void mma_f16(float* d, const uint32_t* a, const uint32_t* b) {
    asm volatile(
        "mma.sync.aligned.m16n8k16.row.col.f32.f16.f16.f32 "
        "{%0,%1,%2,%3}, {%4,%5,%6,%7}, {%8,%9}, {%0,%1,%2,%3};"
        : "+f"(d[0]), "+f"(d[1]), "+f"(d[2]), "+f"(d[3])
        : "r"(a[0]), "r"(a[1]), "r"(a[2]), "r"(a[3]), "r"(b[0]), "r"(b[1]));
}
__device__ __forceinline__ void ldsm4(uint32_t& r0, uint32_t& r1, uint32_t& r2,
                                      uint32_t& r3, uint32_t addr) {
    asm volatile("ldmatrix.sync.aligned.m8n8.x4.shared.b16 {%0,%1,%2,%3}, [%4];"
                 : "=r"(r0), "=r"(r1), "=r"(r2), "=r"(r3) : "r"(addr));
}

// smem layout (halves): stride 40 per row (80B, 16B-aligned rows)
#define KST 40
#define AH_SZ (64 * KST)
#define BH_SZ (128 * KST)
#define OFF_AH(b) ((b) * AH_SZ)
#define OFF_AL(b) (2 * AH_SZ + (b) * AH_SZ)
#define OFF_BH(b) (4 * AH_SZ + (b) * BH_SZ)
#define OFF_BL(b) (4 * AH_SZ + 2 * BH_SZ + (b) * BH_SZ)
#define SMEM_MMA ((4 * AH_SZ + 4 * BH_SZ) * 2)   // 61440 bytes

// ---------------------------------------------------------------------------
// EPI: 0 store, 1 gelu, 2 res+v, 3 C+=v, 5 atomic scatter C[idx[r]] += rw[r]*v
// ---------------------------------------------------------------------------
template<int EPI, bool GA, bool GUARD, bool EXPZ>
__global__ void __launch_bounds__(256, 2) mma_gemm(
    const float* __restrict__ A, const float* __restrict__ B,
    const float* __restrict__ bias, float* __restrict__ C,
    int M, int N, int K,
    const float* __restrict__ res,
    const int* __restrict__ idx,
    const float* __restrict__ rw,
    const int* __restrict__ cnt,
    size_t zA, size_t zC)
{
    if (EXPZ) {
        const int z = blockIdx.z;
        A    += (size_t)z * zA;
        B    += (size_t)z * K * N;
        bias += (size_t)z * N;
        C    += (size_t)z * zC;
        idx  += z * T_TOK;
        if (rw) rw += z * T_TOK;
        cnt  += z;
    }
    const int t = threadIdx.x, wid = t >> 5, lane = t & 31;
    const int m0 = blockIdx.y * 64, n0 = blockIdx.x * 128;

    int cq = M;
    if (GUARD) { cq = *cnt; if (m0 >= cq) return; }

    extern __shared__ __half sh[];
    const uint32_t sbase = (uint32_t)__cvta_generic_to_shared(sh);

    const int arow = t >> 2, akof = (t & 3) * 8;
    int garow = m0 + arow;
    if (GA) garow = (garow < cq) ? idx[garow] : idx[0];
    const float* Agp = A + (size_t)garow * K + akof;
    const int nB = t & 127, kk2 = t >> 7;
    const float* Bcol = B + n0 + nB;

    const int wm = wid >> 2, wn = wid & 3;
    const int gid = lane >> 2, tig = lane & 3;

    // ldmatrix per-thread quad addressing
    const int l7 = lane & 7, q8 = lane >> 3;
    const int A_row = (q8 & 1) * 8 + l7, A_k = (q8 >> 1) * 8;   // a0,a1=rows; a2,a3=k+8
    const int B_row = (q8 >> 1) * 8 + l7, B_k = (q8 & 1) * 8;   // r0,r1=k,k+8; r2,r3=n+8
    const uint32_t aoff0 = (uint32_t)((wm * 32 + A_row) * KST + A_k) * 2u;
    const uint32_t aoff1 = aoff0 + 16u * KST * 2u;
    const uint32_t boff0 = (uint32_t)((wn * 32 + B_row) * KST + B_k) * 2u;
    const uint32_t boff1 = boff0 + 16u * KST * 2u;

    float4 pa0, pa1;
    float pb[16];

    pa0 = *(const float4*)(Agp);
    pa1 = *(const float4*)(Agp + 4);
    #pragma unroll
    for (int i = 0; i < 4; i++)
        #pragma unroll
        for (int jj = 0; jj < 4; jj++)
            pb[i * 4 + jj] = Bcol[(size_t)(kk2 * 16 + i * 4 + jj) * N];
    {
        uint32_t h0,l0,h1,l1,h2,l2,h3,l3;
        split2(pa0.x, pa0.y, h0, l0); split2(pa0.z, pa0.w, h1, l1);
        split2(pa1.x, pa1.y, h2, l2); split2(pa1.z, pa1.w, h3, l3);
        *(uint4*)&sh[OFF_AH(0) + arow * KST + akof] = make_uint4(h0,h1,h2,h3);
        *(uint4*)&sh[OFF_AL(0) + arow * KST + akof] = make_uint4(l0,l1,l2,l3);
        #pragma unroll
        for (int i = 0; i < 4; i++) {
            const int kb = kk2 * 16 + i * 4;
            uint32_t bh0,bl0,bh1,bl1;
            split2(pb[i*4+0], pb[i*4+1], bh0, bl0);
            split2(pb[i*4+2], pb[i*4+3], bh1, bl1);
            *(uint2*)&sh[OFF_BH(0) + nB * KST + kb] = make_uint2(bh0, bh1);
            *(uint2*)&sh[OFF_BL(0) + nB * KST + kb] = make_uint2(bl0, bl1);
        }
    }
    __syncthreads();

    float acc[2][4][4];
    #pragma unroll
    for (int i = 0; i < 2; i++)
        #pragma unroll
        for (int j = 0; j < 4; j++)
            #pragma unroll
            for (int q = 0; q < 4; q++) acc[i][j][q] = 0.f;

    const int nkt = K >> 5;
    for (int j = 0; j < nkt; j++) {
        const int cur = j & 1;
        const bool more = (j + 1 < nkt);
        if (more) {
            const int k0 = (j + 1) << 5;
            pa0 = *(const float4*)(Agp + k0);
            pa1 = *(const float4*)(Agp + k0 + 4);
            #pragma unroll
            for (int i = 0; i < 4; i++)
                #pragma unroll
                for (int jj = 0; jj < 4; jj++)
                    pb[i * 4 + jj] = Bcol[(size_t)(k0 + kk2 * 16 + i * 4 + jj) * N];
        }
        {
            const uint32_t aHiB = sbase + (uint32_t)OFF_AH(cur) * 2u;
            const uint32_t aLoB = sbase + (uint32_t)OFF_AL(cur) * 2u;
            const uint32_t bHiB = sbase + (uint32_t)OFF_BH(cur) * 2u;
            const uint32_t bLoB = sbase + (uint32_t)OFF_BL(cur) * 2u;
            #pragma unroll
            for (int ks = 0; ks < 2; ks++) {
                const uint32_t kadd = (uint32_t)ks * 32u;   // 16 halves
                uint32_t bh[2][4], bl[2][4];
                ldsm4(bh[0][0], bh[0][1], bh[0][2], bh[0][3], bHiB + boff0 + kadd);
                ldsm4(bh[1][0], bh[1][1], bh[1][2], bh[1][3], bHiB + boff1 + kadd);
                ldsm4(bl[0][0], bl[0][1], bl[0][2], bl[0][3], bLoB + boff0 + kadd);
                ldsm4(bl[1][0], bl[1][1], bl[1][2], bl[1][3], bLoB + boff1 + kadd);
                #pragma unroll
                for (int mi = 0; mi < 2; mi++) {
                    const uint32_t ao = (mi == 0) ? aoff0 : aoff1;
                    uint32_t ah[4], al[4];
                    ldsm4(ah[0], ah[1], ah[2], ah[3], aHiB + ao + kadd);
                    ldsm4(al[0], al[1], al[2], al[3], aLoB + ao + kadd);
                    #pragma unroll
                    for (int ni = 0; ni < 4; ni++) {
                        const uint32_t* bph = &bh[ni >> 1][(ni & 1) * 2];
                        const uint32_t* bpl = &bl[ni >> 1][(ni & 1) * 2];
                        mma_f16(acc[mi][ni], ah, bph);
                        mma_f16(acc[mi][ni], ah, bpl);
                        mma_f16(acc[mi][ni], al, bph);
                    }
                }
            }
        }
        if (more) {
            const int nxt = cur ^ 1;
            uint32_t h0,l0,h1,l1,h2,l2,h3,l3;
            split2(pa0.x, pa0.y, h0, l0); split2(pa0.z, pa0.w, h1, l1);
            split2(pa1.x, pa1.y, h2, l2); split2(pa1.z, pa1.w, h3, l3);
            __syncthreads();
            *(uint4*)&sh[OFF_AH(nxt) + arow * KST + akof] = make_uint4(h0,h1,h2,h3);
            *(uint4*)&sh[OFF_AL(nxt) + arow * KST + akof] = make_uint4(l0,l1,l2,l3);
            #pragma unroll
            for (int i = 0; i < 4; i++) {
                const int kb = kk2 * 16 + i * 4;
                uint32_t bh0,bl0,bh1,bl1;
                split2(pb[i*4+0], pb[i*4+1], bh0, bl0);
                split2(pb[i*4+2], pb[i*4+3], bh1, bl1);
                *(uint2*)&sh[OFF_BH(nxt) + nB * KST + kb] = make_uint2(bh0, bh1);
                *(uint2*)&sh[OFF_BL(nxt) + nB * KST + kb] = make_uint2(bl0, bl1);
            }
            __syncthreads();
        }
    }

    #pragma unroll
    for (int mi = 0; mi < 2; mi++) {
        #pragma unroll
        for (int half = 0; half < 2; half++) {
            const int row = m0 + wm * 32 + mi * 16 + gid + half * 8;
            if (GUARD && row >= cq) continue;
            #pragma unroll
            for (int ni = 0; ni < 4; ni++) {
                const int col = n0 + wn * 32 + ni * 8 + tig * 2;
                float vx = acc[mi][ni][half * 2 + 0] + bias[col];
                float vy = acc[mi][ni][half * 2 + 1] + bias[col + 1];
                if (EPI == 5) {
                    const float w = rw[row];
                    float* dst = C + (size_t)idx[row] * N + col;
                    atomicAdd(dst,     w * vx);
                    atomicAdd(dst + 1, w * vy);
                } else {
                    float* dst = C + (size_t)row * N + col;
                    if (EPI == 1) {
                        vx = 0.5f * vx * (1.0f + erff(vx * 0.70710678118654752f));
                        vy = 0.5f * vy * (1.0f + erff(vy * 0.70710678118654752f));
                    } else if (EPI == 2) {
                        const float2 rr = *(const float2*)(res + (size_t)row * N + col);
                        vx += rr.x; vy += rr.y;
                    } else if (EPI == 3) {
                        const float2 cc = *(const float2*)dst;
                        vx += cc.x; vy += cc.y;
                    }
                    *(float2*)dst = make_float2(vx, vy);
                }
            }
        }
    }
}

// ---------------------------------------------------------------------------
// Flash attention: block per (b,head), thread per query row, dynamic smem.
// ---------------------------------------------------------------------------
#define KVP 68
#define SMEM_ATTN (2 * 128 * KVP * 4)   // 69632 bytes

__global__ void __launch_bounds__(128) attn_flash(const float* __restrict__ qkv,
                                                  float* __restrict__ o)
{
    const int bh = blockIdx.x;
    const int b = bh >> 3, hh = bh & 7;
    const int t = threadIdx.x;
    const float* base = qkv + (size_t)b * 128 * 1536 + hh * 64;

    extern __shared__ float kv[];
    float (*Ks)[KVP] = (float(*)[KVP])kv;
    float (*Vs)[KVP] = (float(*)[KVP])(kv + 128 * KVP);

    {
        const float* kr = base + (size_t)t * 1536 + 512;
        const float* vr = kr + 512;
        #pragma unroll
        for (int d4 = 0; d4 < 16; d4++) {
            *(float4*)&Ks[t][d4 * 4] = *(const float4*)(kr + d4 * 4);
            *(float4*)&Vs[t][d4 * 4] = *(const float4*)(vr + d4 * 4);
        }
    }
    float q[64];
    {
        const float* qr = base + (size_t)t * 1536;
        #pragma unroll
        for (int d4 = 0; d4 < 16; d4++) {
            float4 f = *(const float4*)(qr + d4 * 4);
            q[d4 * 4 + 0] = f.x; q[d4 * 4 + 1] = f.y;
            q[d4 * 4 + 2] = f.z; q[d4 * 4 + 3] = f.w;
        }
    }
    __syncthreads();

    float oacc[64];
    #pragma unroll
    for (int d = 0; d < 64; d++) oacc[d] = 0.f;
    float m = -1e30f, l = 0.f;

    for (int j = 0; j <= t; j++) {
        float s = 0.f;
        #pragma unroll
        for (int d4 = 0; d4 < 16; d4++) {
            float4 k4 = *(const float4*)&Ks[j][d4 * 4];
            s += q[d4 * 4 + 0] * k4.x + q[d4 * 4 + 1] * k4.y
               + q[d4 * 4 + 2] * k4.z + q[d4 * 4 + 3] * k4.w;
        }
        s *= 0.125f;
        const float nm = fmaxf(m, s);
        const float sc = __expf(m - nm), e = __expf(s - nm);
        l = l * sc + e;
        m = nm;
        #pragma unroll
        for (int d4 = 0; d4 < 16; d4++) {
            float4 v4 = *(const float4*)&Vs[j][d4 * 4];
            oacc[d4 * 4 + 0] = oacc[d4 * 4 + 0] * sc + e * v4.x;
            oacc[d4 * 4 + 1] = oacc[d4 * 4 + 1] * sc + e * v4.y;
            oacc[d4 * 4 + 2] = oacc[d4 * 4 + 2] * sc + e * v4.z;
            oacc[d4 * 4 + 3] = oacc[d4 * 4 + 3] * sc + e * v4.w;
        }
    }
    const float inv = 1.0f / l;
    float* op = o + ((size_t)b * 128 + t) * 512 + hh * 64;
    #pragma unroll
    for (int d4 = 0; d4 < 16; d4++) {
        float4 r;
        r.x = oacc[d4 * 4 + 0] * inv; r.y = oacc[d4 * 4 + 1] * inv;
        r.z = oacc[d4 * 4 + 2] * inv; r.w = oacc[d4 * 4 + 3] * inv;
        *(float4*)(op + d4 * 4) = r;
    }
}

// ---------------------------------------------------------------------------
__global__ void patchnorm_kernel(const float* __restrict__ x, float* __restrict__ y)
{
    const int warp = threadIdx.x >> 5, lane = threadIdx.x & 31;
    const int row = blockIdx.x * 8 + warp;
    const float* xr = x + (size_t)row * 128;
    float4 f = *(const float4*)(xr + lane * 4);
    float s = f.x + f.y + f.z + f.w;
    #pragma unroll
    for (int o = 16; o; o >>= 1) s += __shfl_xor_sync(0xffffffffu, s, o);
    const float mu = s * (1.0f / 128.0f);
    float q = (f.x - mu) * (f.x - mu) + (f.y - mu) * (f.y - mu)
            + (f.z - mu) * (f.z - mu) + (f.w - mu) * (f.w - mu);
    #pragma unroll
    for (int o = 16; o; o >>= 1) q += __shfl_xor_sync(0xffffffffu, q, o);
    const float rs = rsqrtf(q * (1.0f / 128.0f) + 1e-6f);
    float4 r = make_float4((f.x - mu) * rs, (f.y - mu) * rs, (f.z - mu) * rs, (f.w - mu) * rs);
    *(float4*)(y + (size_t)row * 128 + lane * 4) = r;
}

__global__ void ln512_kernel(const float* __restrict__ x, float* __restrict__ y,
                             const float* __restrict__ g, const float* __restrict__ b)
{
    const int warp = threadIdx.x >> 5, lane = threadIdx.x & 31;
    const int row = blockIdx.x * 8 + warp;
    const float* xr = x + (size_t)row * 512;
    float v[16];
    float s = 0.f;
    #pragma unroll
    for (int c = 0; c < 4; c++) {
        float4 f = *(const float4*)(xr + c * 128 + lane * 4);
        v[c * 4 + 0] = f.x; v[c * 4 + 1] = f.y; v[c * 4 + 2] = f.z; v[c * 4 + 3] = f.w;
        s += f.x + f.y + f.z + f.w;
    }
    #pragma unroll
    for (int o = 16; o; o >>= 1) s += __shfl_xor_sync(0xffffffffu, s, o);
    const float mu = s * (1.0f / 512.0f);
    float q = 0.f;
    #pragma unroll
    for (int k = 0; k < 16; k++) { float d = v[k] - mu; q += d * d; }
    #pragma unroll
    for (int o = 16; o; o >>= 1) q += __shfl_xor_sync(0xffffffffu, q, o);
    const float rs = rsqrtf(q * (1.0f / 512.0f) + 1e-5f);
    #pragma unroll
    for (int c = 0; c < 4; c++) {
        const int col = c * 128 + lane * 4;
        float4 gg = *(const float4*)(g + col);
        float4 bb = *(const float4*)(b + col);
        float4 r;
        r.x = gg.x * (v[c * 4 + 0] - mu) * rs + bb.x;
        r.y = gg.y * (v[c * 4 + 1] - mu) * rs + bb.y;
        r.z = gg.z * (v[c * 4 + 2] - mu) * rs + bb.z;
        r.w = gg.w * (v[c * 4 + 3] - mu) * rs + bb.w;
        *(float4*)(y + (size_t)row * 512 + col) = r;
    }
}

__global__ void freqadd_kernel(float* __restrict__ h, const float* __restrict__ emb,
                               const int* __restrict__ fid)
{
    const int i = blockIdx.x * 256 + threadIdx.x;
    const int row = i >> 9, d = i & 511, b = row >> 7;
    h[i] += emb[(size_t)fid[b] * 512 + d];
}

__global__ void zero_cnt_kernel(int* cnt)
{
    if (threadIdx.x < 4) cnt[threadIdx.x] = 0;
}

__global__ void gate_route_kernel(const float* __restrict__ hn, const float* __restrict__ gw,
                                  const float* __restrict__ gb,
                                  int* __restrict__ cnt, int* __restrict__ idx,
                                  float* __restrict__ rw)
{
    const int warp = threadIdx.x >> 5, lane = threadIdx.x & 31;
    const int row = blockIdx.x * 8 + warp;
    const float* xr = hn + (size_t)row * 512;
    float a0 = 0.f, a1 = 0.f, a2 = 0.f, a3 = 0.f;
    for (int d = lane; d < 512; d += 32) {
        const float hv = xr[d];
        float4 w = *(const float4*)(gw + (size_t)d * 4);
        a0 += hv * w.x; a1 += hv * w.y; a2 += hv * w.z; a3 += hv * w.w;
    }
    #pragma unroll
    for (int o = 16; o; o >>= 1) {
        a0 += __shfl_xor_sync(0xffffffffu, a0, o);
        a1 += __shfl_xor_sync(0xffffffffu, a1, o);
        a2 += __shfl_xor_sync(0xffffffffu, a2, o);
        a3 += __shfl_xor_sync(0xffffffffu, a3, o);
    }
    if (lane == 0) {
        float p[4] = {a0 + gb[0], a1 + gb[1], a2 + gb[2], a3 + gb[3]};
        const float mx = fmaxf(fmaxf(p[0], p[1]), fmaxf(p[2], p[3]));
        float s = 0.f;
        #pragma unroll
        for (int e = 0; e < 4; e++) { p[e] = expf(p[e] - mx); s += p[e]; }
        const float invs = 1.0f / s;
        #pragma unroll
        for (int e = 0; e < 4; e++) p[e] *= invs;
        int i0 = 0;
        #pragma unroll
        for (int e = 1; e < 4; e++) if (p[e] > p[i0]) i0 = e;
        int i1 = -1;
        #pragma unroll
        for (int e = 0; e < 4; e++) if (e != i0 && (i1 < 0 || p[e] > p[i1])) i1 = e;
        int s0 = atomicAdd(&cnt[i0], 1);
        idx[i0 * T_TOK + s0] = row; rw[i0 * T_TOK + s0] = p[i0];
        int s1 = atomicAdd(&cnt[i1], 1);
        idx[i1 * T_TOK + s1] = row; rw[i1 * T_TOK + s1] = p[i1];
    }
}

__global__ void head_kernel(const float* __restrict__ h,
                            const float* __restrict__ fng, const float* __restrict__ fnb,
                            const float* __restrict__ hg,  const float* __restrict__ hb,
                            const float* __restrict__ hw,  const float* __restrict__ hbias,
                            float* __restrict__ out, int out_size)
{
    const int warp = threadIdx.x >> 5, lane = threadIdx.x & 31;
    const int b = warp;
    const float* xr = h + ((size_t)b * 128 + 127) * 512;
    float v[16];
    float s = 0.f;
    #pragma unroll
    for (int c = 0; c < 4; c++) {
        float4 f = *(const float4*)(xr + c * 128 + lane * 4);
        v[c * 4 + 0] = f.x; v[c * 4 + 1] = f.y; v[c * 4 + 2] = f.z; v[c * 4 + 3] = f.w;
        s += f.x + f.y + f.z + f.w;
    }
    #pragma unroll
    for (int o = 16; o; o >>= 1) s += __shfl_xor_sync(0xffffffffu, s, o);
    float mu = s * (1.0f / 512.0f);
    float q = 0.f;
    #pragma unroll
    for (int k = 0; k < 16; k++) { float d = v[k] - mu; q += d * d; }
    #pragma unroll
    for (int o = 16; o; o >>= 1) q += __shfl_xor_sync(0xffffffffu, q, o);
    float rs = rsqrtf(q * (1.0f / 512.0f) + 1e-5f);
    #pragma unroll
    for (int c = 0; c < 4; c++)
        #pragma unroll
        for (int j = 0; j < 4; j++) {
            const int col = c * 128 + lane * 4 + j;
            v[c * 4 + j] = fng[col] * (v[c * 4 + j] - mu) * rs + fnb[col];
        }
    s = 0.f;
    #pragma unroll
    for (int k = 0; k < 16; k++) s += v[k];
    #pragma unroll
    for (int o = 16; o; o >>= 1) s += __shfl_xor_sync(0xffffffffu, s, o);
    mu = s * (1.0f / 512.0f);
    q = 0.f;
    #pragma unroll
    for (int k = 0; k < 16; k++) { float d = v[k] - mu; q += d * d; }
    #pragma unroll
    for (int o = 16; o; o >>= 1) q += __shfl_xor_sync(0xffffffffu, q, o);
    rs = rsqrtf(q * (1.0f / 512.0f) + 1e-5f);
    float dot = 0.f;
    #pragma unroll
    for (int c = 0; c < 4; c++)
        #pragma unroll
        for (int j = 0; j < 4; j++) {
            const int col = c * 128 + lane * 4 + j;
            const float hl = hg[col] * (v[c * 4 + j] - mu) * rs + hb[col];
            dot += hl * hw[col];
        }
    #pragma unroll
    for (int o = 16; o; o >>= 1) dot += __shfl_xor_sync(0xffffffffu, dot, o);
    if (lane == 0) {
        const float logit = dot + hbias[0];
        if (out_size >= 32) {
            out[b] = logit;
            out[16 + b] = 1.0f / (1.0f + expf(-logit));
        } else {
            out[b] = logit;
        }
    }
}

// ---------------------------------------------------------------------------
extern "C" void kernel_launch(void* const* d_in, const int* in_sizes, int n_in,
                              void* d_out, int out_size)
{
    const float* x        = (const float*)d_in[0];
    const int*   fid      = (const int*)  d_in[1];
    const float* ir_w1    = (const float*)d_in[2];
    const float* ir_b1    = (const float*)d_in[3];
    const float* ir_w2    = (const float*)d_in[4];
    const float* ir_b2    = (const float*)d_in[5];
    const float* p2m_w    = (const float*)d_in[6];
    const float* p2m_b    = (const float*)d_in[7];
    const float* freq_emb = (const float*)d_in[8];
    const float* ln1_g    = (const float*)d_in[9];
    const float* ln1_b    = (const float*)d_in[10];
    const float* qkv_w    = (const float*)d_in[11];
    const float* qkv_b    = (const float*)d_in[12];
    const float* out_w    = (const float*)d_in[13];
    const float* out_b    = (const float*)d_in[14];
    const float* ln2_g    = (const float*)d_in[15];
    const float* ln2_b    = (const float*)d_in[16];
    const float* gate_w   = (const float*)d_in[17];
    const float* gate_b   = (const float*)d_in[18];
    const float* exp_w1   = (const float*)d_in[19];
    const float* exp_b1   = (const float*)d_in[20];
    const float* exp_w2   = (const float*)d_in[21];
    const float* exp_b2   = (const float*)d_in[22];
    const float* fn_g     = (const float*)d_in[23];
    const float* fn_b     = (const float*)d_in[24];
    const float* head_g   = (const float*)d_in[25];
    const float* head_b   = (const float*)d_in[26];
    const float* head_w   = (const float*)d_in[27];
    const float* head_bias= (const float*)d_in[28];

    float *patches, *tmp, *hp, *h, *hn, *qkv, *attn, *eh, *rw;
    int *cnt, *idx;
    cudaGetSymbolAddress((void**)&patches, g_patches);
    cudaGetSymbolAddress((void**)&tmp,     g_tmp);
    cudaGetSymbolAddress((void**)&hp,      g_hp);
    cudaGetSymbolAddress((void**)&h,       g_h);
    cudaGetSymbolAddress((void**)&hn,      g_hn);
    cudaGetSymbolAddress((void**)&qkv,     g_qkv);
    cudaGetSymbolAddress((void**)&attn,    g_attn);
    cudaGetSymbolAddress((void**)&eh,      g_eh);
    cudaGetSymbolAddress((void**)&cnt,     g_cnt);
    cudaGetSymbolAddress((void**)&idx,     g_idx);
    cudaGetSymbolAddress((void**)&rw,      g_rw);

    cudaFuncSetAttribute(mma_gemm<0,false,false,false>, cudaFuncAttributeMaxDynamicSharedMemorySize, SMEM_MMA);
    cudaFuncSetAttribute(mma_gemm<1,false,false,false>, cudaFuncAttributeMaxDynamicSharedMemorySize, SMEM_MMA);
    cudaFuncSetAttribute(mma_gemm<2,false,false,false>, cudaFuncAttributeMaxDynamicSharedMemorySize, SMEM_MMA);
    cudaFuncSetAttribute(mma_gemm<3,false,false,false>, cudaFuncAttributeMaxDynamicSharedMemorySize, SMEM_MMA);
    cudaFuncSetAttribute(mma_gemm<1,true,true,true>,    cudaFuncAttributeMaxDynamicSharedMemorySize, SMEM_MMA);
    cudaFuncSetAttribute(mma_gemm<5,false,true,true>,   cudaFuncAttributeMaxDynamicSharedMemorySize, SMEM_MMA);
    cudaFuncSetAttribute(attn_flash, cudaFuncAttributeMaxDynamicSharedMemorySize, SMEM_ATTN);

    const size_t EHZ = (size_t)T_TOK * HDIM;

    // Front end
    patchnorm_kernel<<<256, 256>>>(x, patches);
    mma_gemm<1,false,false,false><<<dim3(4, 32), 256, SMEM_MMA>>>(patches, ir_w1, ir_b1, tmp,
        T_TOK, 512, 128, nullptr, nullptr, nullptr, nullptr, 0, 0);
    mma_gemm<2,false,false,false><<<dim3(1, 32), 256, SMEM_MMA>>>(tmp, ir_w2, ir_b2, hp,
        T_TOK, 128, 512, patches, nullptr, nullptr, nullptr, 0, 0);
    mma_gemm<0,false,false,false><<<dim3(4, 32), 256, SMEM_MMA>>>(hp, p2m_w, p2m_b, h,
        T_TOK, 512, 128, nullptr, nullptr, nullptr, nullptr, 0, 0);
    freqadd_kernel<<<(T_TOK * 512) / 256, 256>>>(h, freq_emb, fid);

    for (int l = 0; l < 12; l++) {
        // attention
        ln512_kernel<<<256, 256>>>(h, hn, ln1_g + (size_t)l * 512, ln1_b + (size_t)l * 512);
        mma_gemm<0,false,false,false><<<dim3(12, 32), 256, SMEM_MMA>>>(hn,
            qkv_w + (size_t)l * 512 * 1536, qkv_b + (size_t)l * 1536, qkv,
            T_TOK, 1536, 512, nullptr, nullptr, nullptr, nullptr, 0, 0);
        attn_flash<<<128, 128, SMEM_ATTN>>>(qkv, attn);
        mma_gemm<3,false,false,false><<<dim3(4, 32), 256, SMEM_MMA>>>(attn,
            out_w + (size_t)l * 512 * 512, out_b + (size_t)l * 512, h,
            T_TOK, 512, 512, nullptr, nullptr, nullptr, nullptr, 0, 0);
        // sparse MoE (4 experts fused via blockIdx.z)
        ln512_kernel<<<256, 256>>>(h, hn, ln2_g + (size_t)l * 512, ln2_b + (size_t)l * 512);
        zero_cnt_kernel<<<1, 32>>>(cnt);
        gate_route_kernel<<<256, 256>>>(hn, gate_w + (size_t)l * 512 * 4,
                                        gate_b + (size_t)l * 4, cnt, idx, rw);
        mma_gemm<1,true,true,true><<<dim3(16, 32, 4), 256, SMEM_MMA>>>(hn,
            exp_w1 + (size_t)l * 4 * 512 * 2048, exp_b1 + (size_t)l * 4 * 2048, eh,
            T_TOK, 2048, 512, nullptr, idx, nullptr, cnt, 0, EHZ);
        mma_gemm<5,false,true,true><<<dim3(4, 32, 4), 256, SMEM_MMA>>>(eh,
            exp_w2 + (size_t)l * 4 * 2048 * 512, exp_b2 + (size_t)l * 4 * 512, h,
            T_TOK, 512, 2048, nullptr, idx, rw, cnt, EHZ, 0);
    }

    head_kernel<<<1, 512>>>(h, fn_g, fn_b, head_g, head_b, head_w, head_bias,
                            (float*)d_out, out_size);
}

// round 12
// speedup vs baseline: 4.1589x; 1.0106x over previous
#include <cuda_runtime.h>
#include <cuda_fp16.h>
#include <math.h>
#include <stdint.h>

// ---------------------------------------------------------------------------
// B=16, S=2048, C=8, P=16 -> N=128 patches, T=2048 tokens
// PD=128, IRH=512, D=512, NH=8, dh=64, L=12, E=4, H=2048, top-2 routing
// GEMMs: mma.sync m16n8k16 f16 split-precision, pre-split smem tiles,
// ldmatrix fragment loads, interleaved-term scheduling (dep distance 8).
// ---------------------------------------------------------------------------
#define T_TOK 2048
#define DIM   512
#define HDIM  2048

__device__ float g_patches[T_TOK * 128];
__device__ float g_tmp    [T_TOK * 512];
__device__ float g_hp     [T_TOK * 128];
__device__ float g_h      [T_TOK * DIM];
__device__ float g_hn     [T_TOK * DIM];
__device__ float g_qkv    [T_TOK * 3 * DIM];
__device__ float g_attn   [T_TOK * DIM];
__device__ float g_eh     [4 * T_TOK * HDIM];
__device__ int   g_cnt    [4];
__device__ int   g_idx    [4 * T_TOK];
__device__ float g_rw     [4 * T_TOK];

// ---- helpers ---------------------------------------------------------------
__device__ __forceinline__ void split2(float f0, float f1, uint32_t& hi, uint32_t& lo) {
    __half2 h = __floats2half2_rn(f0, f1);
    float2 hf = __half22float2(h);
    __half2 l = __floats2half2_rn(f0 - hf.x, f1 - hf.y);
    hi = *(uint32_t*)&h;
    lo = *(uint32_t*)&l;
}
__device__ __forceinline__ void mma_f16(float* d, const uint32_t* a, const uint32_t* b) {
    asm volatile(
        "mma.sync.aligned.m16n8k16.row.col.f32.f16.f16.f32 "
        "{%0,%1,%2,%3}, {%4,%5,%6,%7}, {%8,%9}, {%0,%1,%2,%3};"
        : "+f"(d[0]), "+f"(d[1]), "+f"(d[2]), "+f"(d[3])
        : "r"(a[0]), "r"(a[1]), "r"(a[2]), "r"(a[3]), "r"(b[0]), "r"(b[1]));
}
__device__ __forceinline__ void ldsm4(uint32_t& r0, uint32_t& r1, uint32_t& r2,
                                      uint32_t& r3, uint32_t addr) {
    asm volatile("ldmatrix.sync.aligned.m8n8.x4.shared.b16 {%0,%1,%2,%3}, [%4];"
                 : "=r"(r0), "=r"(r1), "=r"(r2), "=r"(r3) : "r"(addr));
}

// smem layout (halves): stride 40 per row (80B, 16B-aligned rows)
#define KST 40
#define AH_SZ (64 * KST)
#define BH_SZ (128 * KST)
#define OFF_AH(b) ((b) * AH_SZ)
#define OFF_AL(b) (2 * AH_SZ + (b) * AH_SZ)
#define OFF_BH(b) (4 * AH_SZ + (b) * BH_SZ)
#define OFF_BL(b) (4 * AH_SZ + 2 * BH_SZ + (b) * BH_SZ)
#define SMEM_MMA ((4 * AH_SZ + 4 * BH_SZ) * 2)   // 61440 bytes

// ---------------------------------------------------------------------------
// EPI: 0 store, 1 gelu, 2 res+v, 3 C+=v, 5 atomic scatter C[idx[r]] += rw[r]*v
// ---------------------------------------------------------------------------
template<int EPI, bool GA, bool GUARD, bool EXPZ>
__global__ void __launch_bounds__(256, 2) mma_gemm(
    const float* __restrict__ A, const float* __restrict__ B,
    const float* __restrict__ bias, float* __restrict__ C,
    int M, int N, int K,
    const float* __restrict__ res,
    const int* __restrict__ idx,
    const float* __restrict__ rw,
    const int* __restrict__ cnt,
    size_t zA, size_t zC)
{
    if (EXPZ) {
        const int z = blockIdx.z;
        A    += (size_t)z * zA;
        B    += (size_t)z * K * N;
        bias += (size_t)z * N;
        C    += (size_t)z * zC;
        idx  += z * T_TOK;
        if (rw) rw += z * T_TOK;
        cnt  += z;
    }
    const int t = threadIdx.x, wid = t >> 5, lane = t & 31;
    const int m0 = blockIdx.y * 64, n0 = blockIdx.x * 128;

    int cq = M;
    if (GUARD) { cq = *cnt; if (m0 >= cq) return; }

    extern __shared__ __half sh[];
    const uint32_t sbase = (uint32_t)__cvta_generic_to_shared(sh);

    const int arow = t >> 2, akof = (t & 3) * 8;
    int garow = m0 + arow;
    if (GA) garow = (garow < cq) ? idx[garow] : idx[0];
    const float* Agp = A + (size_t)garow * K + akof;
    const int nB = t & 127, kk2 = t >> 7;
    const float* Bcol = B + n0 + nB;

    const int wm = wid >> 2, wn = wid & 3;
    const int gid = lane >> 2, tig = lane & 3;

    // ldmatrix per-thread quad addressing
    const int l7 = lane & 7, q8 = lane >> 3;
    const int A_row = (q8 & 1) * 8 + l7, A_k = (q8 >> 1) * 8;
    const int B_row = (q8 >> 1) * 8 + l7, B_k = (q8 & 1) * 8;
    const uint32_t aoff0 = (uint32_t)((wm * 32 + A_row) * KST + A_k) * 2u;
    const uint32_t aoff1 = aoff0 + 16u * KST * 2u;
    const uint32_t boff0 = (uint32_t)((wn * 32 + B_row) * KST + B_k) * 2u;
    const uint32_t boff1 = boff0 + 16u * KST * 2u;

    float4 pa0, pa1;
    float pb[16];

    pa0 = *(const float4*)(Agp);
    pa1 = *(const float4*)(Agp + 4);
    #pragma unroll
    for (int i = 0; i < 4; i++)
        #pragma unroll
        for (int jj = 0; jj < 4; jj++)
            pb[i * 4 + jj] = Bcol[(size_t)(kk2 * 16 + i * 4 + jj) * N];
    {
        uint32_t h0,l0,h1,l1,h2,l2,h3,l3;
        split2(pa0.x, pa0.y, h0, l0); split2(pa0.z, pa0.w, h1, l1);
        split2(pa1.x, pa1.y, h2, l2); split2(pa1.z, pa1.w, h3, l3);
        *(uint4*)&sh[OFF_AH(0) + arow * KST + akof] = make_uint4(h0,h1,h2,h3);
        *(uint4*)&sh[OFF_AL(0) + arow * KST + akof] = make_uint4(l0,l1,l2,l3);
        #pragma unroll
        for (int i = 0; i < 4; i++) {
            const int kb = kk2 * 16 + i * 4;
            uint32_t bh0,bl0,bh1,bl1;
            split2(pb[i*4+0], pb[i*4+1], bh0, bl0);
            split2(pb[i*4+2], pb[i*4+3], bh1, bl1);
            *(uint2*)&sh[OFF_BH(0) + nB * KST + kb] = make_uint2(bh0, bh1);
            *(uint2*)&sh[OFF_BL(0) + nB * KST + kb] = make_uint2(bl0, bl1);
        }
    }
    __syncthreads();

    float acc[2][4][4];
    #pragma unroll
    for (int i = 0; i < 2; i++)
        #pragma unroll
        for (int j = 0; j < 4; j++)
            #pragma unroll
            for (int q = 0; q < 4; q++) acc[i][j][q] = 0.f;

    const int nkt = K >> 5;
    for (int j = 0; j < nkt; j++) {
        const int cur = j & 1;
        const bool more = (j + 1 < nkt);
        if (more) {
            const int k0 = (j + 1) << 5;
            pa0 = *(const float4*)(Agp + k0);
            pa1 = *(const float4*)(Agp + k0 + 4);
            #pragma unroll
            for (int i = 0; i < 4; i++)
                #pragma unroll
                for (int jj = 0; jj < 4; jj++)
                    pb[i * 4 + jj] = Bcol[(size_t)(k0 + kk2 * 16 + i * 4 + jj) * N];
        }
        {
            const uint32_t aHiB = sbase + (uint32_t)OFF_AH(cur) * 2u;
            const uint32_t aLoB = sbase + (uint32_t)OFF_AL(cur) * 2u;
            const uint32_t bHiB = sbase + (uint32_t)OFF_BH(cur) * 2u;
            const uint32_t bLoB = sbase + (uint32_t)OFF_BL(cur) * 2u;
            #pragma unroll
            for (int ks = 0; ks < 2; ks++) {
                const uint32_t kadd = (uint32_t)ks * 32u;
                uint32_t bh[2][4], bl[2][4], ah[2][4], al[2][4];
                ldsm4(bh[0][0], bh[0][1], bh[0][2], bh[0][3], bHiB + boff0 + kadd);
                ldsm4(bh[1][0], bh[1][1], bh[1][2], bh[1][3], bHiB + boff1 + kadd);
                ldsm4(bl[0][0], bl[0][1], bl[0][2], bl[0][3], bLoB + boff0 + kadd);
                ldsm4(bl[1][0], bl[1][1], bl[1][2], bl[1][3], bLoB + boff1 + kadd);
                ldsm4(ah[0][0], ah[0][1], ah[0][2], ah[0][3], aHiB + aoff0 + kadd);
                ldsm4(ah[1][0], ah[1][1], ah[1][2], ah[1][3], aHiB + aoff1 + kadd);
                ldsm4(al[0][0], al[0][1], al[0][2], al[0][3], aLoB + aoff0 + kadd);
                ldsm4(al[1][0], al[1][1], al[1][2], al[1][3], aLoB + aoff1 + kadd);
                // pass 1: hi*hi (8 independent mmas)
                #pragma unroll
                for (int mi = 0; mi < 2; mi++)
                    #pragma unroll
                    for (int ni = 0; ni < 4; ni++)
                        mma_f16(acc[mi][ni], ah[mi], &bh[ni >> 1][(ni & 1) * 2]);
                // pass 2: hi*lo
                #pragma unroll
                for (int mi = 0; mi < 2; mi++)
                    #pragma unroll
                    for (int ni = 0; ni < 4; ni++)
                        mma_f16(acc[mi][ni], ah[mi], &bl[ni >> 1][(ni & 1) * 2]);
                // pass 3: lo*hi
                #pragma unroll
                for (int mi = 0; mi < 2; mi++)
                    #pragma unroll
                    for (int ni = 0; ni < 4; ni++)
                        mma_f16(acc[mi][ni], al[mi], &bh[ni >> 1][(ni & 1) * 2]);
            }
        }
        if (more) {
            const int nxt = cur ^ 1;
            uint32_t h0,l0,h1,l1,h2,l2,h3,l3;
            split2(pa0.x, pa0.y, h0, l0); split2(pa0.z, pa0.w, h1, l1);
            split2(pa1.x, pa1.y, h2, l2); split2(pa1.z, pa1.w, h3, l3);
            *(uint4*)&sh[OFF_AH(nxt) + arow * KST + akof] = make_uint4(h0,h1,h2,h3);
            *(uint4*)&sh[OFF_AL(nxt) + arow * KST + akof] = make_uint4(l0,l1,l2,l3);
            #pragma unroll
            for (int i = 0; i < 4; i++) {
                const int kb = kk2 * 16 + i * 4;
                uint32_t bh0,bl0,bh1,bl1;
                split2(pb[i*4+0], pb[i*4+1], bh0, bl0);
                split2(pb[i*4+2], pb[i*4+3], bh1, bl1);
                *(uint2*)&sh[OFF_BH(nxt) + nB * KST + kb] = make_uint2(bh0, bh1);
                *(uint2*)&sh[OFF_BL(nxt) + nB * KST + kb] = make_uint2(bl0, bl1);
            }
            __syncthreads();
        }
    }

    #pragma unroll
    for (int mi = 0; mi < 2; mi++) {
        #pragma unroll
        for (int half = 0; half < 2; half++) {
            const int row = m0 + wm * 32 + mi * 16 + gid + half * 8;
            if (GUARD && row >= cq) continue;
            #pragma unroll
            for (int ni = 0; ni < 4; ni++) {
                const int col = n0 + wn * 32 + ni * 8 + tig * 2;
                float vx = acc[mi][ni][half * 2 + 0] + bias[col];
                float vy = acc[mi][ni][half * 2 + 1] + bias[col + 1];
                if (EPI == 5) {
                    const float w = rw[row];
                    float* dst = C + (size_t)idx[row] * N + col;
                    atomicAdd(dst,     w * vx);
                    atomicAdd(dst + 1, w * vy);
                } else {
                    float* dst = C + (size_t)row * N + col;
                    if (EPI == 1) {
                        vx = 0.5f * vx * (1.0f + erff(vx * 0.70710678118654752f));
                        vy = 0.5f * vy * (1.0f + erff(vy * 0.70710678118654752f));
                    } else if (EPI == 2) {
                        const float2 rr = *(const float2*)(res + (size_t)row * N + col);
                        vx += rr.x; vy += rr.y;
                    } else if (EPI == 3) {
                        const float2 cc = *(const float2*)dst;
                        vx += cc.x; vy += cc.y;
                    }
                    *(float2*)dst = make_float2(vx, vy);
                }
            }
        }
    }
}

// ---------------------------------------------------------------------------
// Flash attention: block per (b,head), thread per query row, dynamic smem.
// ---------------------------------------------------------------------------
#define KVP 68
#define SMEM_ATTN (2 * 128 * KVP * 4)   // 69632 bytes

__global__ void __launch_bounds__(128) attn_flash(const float* __restrict__ qkv,
                                                  float* __restrict__ o)
{
    const int bh = blockIdx.x;
    const int b = bh >> 3, hh = bh & 7;
    const int t = threadIdx.x;
    const float* base = qkv + (size_t)b * 128 * 1536 + hh * 64;

    extern __shared__ float kv[];
    float (*Ks)[KVP] = (float(*)[KVP])kv;
    float (*Vs)[KVP] = (float(*)[KVP])(kv + 128 * KVP);

    {
        const float* kr = base + (size_t)t * 1536 + 512;
        const float* vr = kr + 512;
        #pragma unroll
        for (int d4 = 0; d4 < 16; d4++) {
            *(float4*)&Ks[t][d4 * 4] = *(const float4*)(kr + d4 * 4);
            *(float4*)&Vs[t][d4 * 4] = *(const float4*)(vr + d4 * 4);
        }
    }
    float q[64];
    {
        const float* qr = base + (size_t)t * 1536;
        #pragma unroll
        for (int d4 = 0; d4 < 16; d4++) {
            float4 f = *(const float4*)(qr + d4 * 4);
            q[d4 * 4 + 0] = f.x; q[d4 * 4 + 1] = f.y;
            q[d4 * 4 + 2] = f.z; q[d4 * 4 + 3] = f.w;
        }
    }
    __syncthreads();

    float oacc[64];
    #pragma unroll
    for (int d = 0; d < 64; d++) oacc[d] = 0.f;
    float m = -1e30f, l = 0.f;

    for (int j = 0; j <= t; j++) {
        float s = 0.f;
        #pragma unroll
        for (int d4 = 0; d4 < 16; d4++) {
            float4 k4 = *(const float4*)&Ks[j][d4 * 4];
            s += q[d4 * 4 + 0] * k4.x + q[d4 * 4 + 1] * k4.y
               + q[d4 * 4 + 2] * k4.z + q[d4 * 4 + 3] * k4.w;
        }
        s *= 0.125f;
        const float nm = fmaxf(m, s);
        const float sc = __expf(m - nm), e = __expf(s - nm);
        l = l * sc + e;
        m = nm;
        #pragma unroll
        for (int d4 = 0; d4 < 16; d4++) {
            float4 v4 = *(const float4*)&Vs[j][d4 * 4];
            oacc[d4 * 4 + 0] = oacc[d4 * 4 + 0] * sc + e * v4.x;
            oacc[d4 * 4 + 1] = oacc[d4 * 4 + 1] * sc + e * v4.y;
            oacc[d4 * 4 + 2] = oacc[d4 * 4 + 2] * sc + e * v4.z;
            oacc[d4 * 4 + 3] = oacc[d4 * 4 + 3] * sc + e * v4.w;
        }
    }
    const float inv = 1.0f / l;
    float* op = o + ((size_t)b * 128 + t) * 512 + hh * 64;
    #pragma unroll
    for (int d4 = 0; d4 < 16; d4++) {
        float4 r;
        r.x = oacc[d4 * 4 + 0] * inv; r.y = oacc[d4 * 4 + 1] * inv;
        r.z = oacc[d4 * 4 + 2] * inv; r.w = oacc[d4 * 4 + 3] * inv;
        *(float4*)(op + d4 * 4) = r;
    }
}

// ---------------------------------------------------------------------------
__global__ void patchnorm_kernel(const float* __restrict__ x, float* __restrict__ y)
{
    const int warp = threadIdx.x >> 5, lane = threadIdx.x & 31;
    const int row = blockIdx.x * 8 + warp;
    const float* xr = x + (size_t)row * 128;
    float4 f = *(const float4*)(xr + lane * 4);
    float s = f.x + f.y + f.z + f.w;
    #pragma unroll
    for (int o = 16; o; o >>= 1) s += __shfl_xor_sync(0xffffffffu, s, o);
    const float mu = s * (1.0f / 128.0f);
    float q = (f.x - mu) * (f.x - mu) + (f.y - mu) * (f.y - mu)
            + (f.z - mu) * (f.z - mu) + (f.w - mu) * (f.w - mu);
    #pragma unroll
    for (int o = 16; o; o >>= 1) q += __shfl_xor_sync(0xffffffffu, q, o);
    const float rs = rsqrtf(q * (1.0f / 128.0f) + 1e-6f);
    float4 r = make_float4((f.x - mu) * rs, (f.y - mu) * rs, (f.z - mu) * rs, (f.w - mu) * rs);
    *(float4*)(y + (size_t)row * 128 + lane * 4) = r;
}

__global__ void ln512_kernel(const float* __restrict__ x, float* __restrict__ y,
                             const float* __restrict__ g, const float* __restrict__ b)
{
    const int warp = threadIdx.x >> 5, lane = threadIdx.x & 31;
    const int row = blockIdx.x * 8 + warp;
    const float* xr = x + (size_t)row * 512;
    float v[16];
    float s = 0.f;
    #pragma unroll
    for (int c = 0; c < 4; c++) {
        float4 f = *(const float4*)(xr + c * 128 + lane * 4);
        v[c * 4 + 0] = f.x; v[c * 4 + 1] = f.y; v[c * 4 + 2] = f.z; v[c * 4 + 3] = f.w;
        s += f.x + f.y + f.z + f.w;
    }
    #pragma unroll
    for (int o = 16; o; o >>= 1) s += __shfl_xor_sync(0xffffffffu, s, o);
    const float mu = s * (1.0f / 512.0f);
    float q = 0.f;
    #pragma unroll
    for (int k = 0; k < 16; k++) { float d = v[k] - mu; q += d * d; }
    #pragma unroll
    for (int o = 16; o; o >>= 1) q += __shfl_xor_sync(0xffffffffu, q, o);
    const float rs = rsqrtf(q * (1.0f / 512.0f) + 1e-5f);
    #pragma unroll
    for (int c = 0; c < 4; c++) {
        const int col = c * 128 + lane * 4;
        float4 gg = *(const float4*)(g + col);
        float4 bb = *(const float4*)(b + col);
        float4 r;
        r.x = gg.x * (v[c * 4 + 0] - mu) * rs + bb.x;
        r.y = gg.y * (v[c * 4 + 1] - mu) * rs + bb.y;
        r.z = gg.z * (v[c * 4 + 2] - mu) * rs + bb.z;
        r.w = gg.w * (v[c * 4 + 3] - mu) * rs + bb.w;
        *(float4*)(y + (size_t)row * 512 + col) = r;
    }
}

__global__ void freqadd_kernel(float* __restrict__ h, const float* __restrict__ emb,
                               const int* __restrict__ fid)
{
    const int i = blockIdx.x * 256 + threadIdx.x;
    const int row = i >> 9, d = i & 511, b = row >> 7;
    h[i] += emb[(size_t)fid[b] * 512 + d];
}

__global__ void zero_cnt_kernel(int* cnt)
{
    if (threadIdx.x < 4) cnt[threadIdx.x] = 0;
}

__global__ void gate_route_kernel(const float* __restrict__ hn, const float* __restrict__ gw,
                                  const float* __restrict__ gb,
                                  int* __restrict__ cnt, int* __restrict__ idx,
                                  float* __restrict__ rw)
{
    const int warp = threadIdx.x >> 5, lane = threadIdx.x & 31;
    const int row = blockIdx.x * 8 + warp;
    const float* xr = hn + (size_t)row * 512;
    float a0 = 0.f, a1 = 0.f, a2 = 0.f, a3 = 0.f;
    for (int d = lane; d < 512; d += 32) {
        const float hv = xr[d];
        float4 w = *(const float4*)(gw + (size_t)d * 4);
        a0 += hv * w.x; a1 += hv * w.y; a2 += hv * w.z; a3 += hv * w.w;
    }
    #pragma unroll
    for (int o = 16; o; o >>= 1) {
        a0 += __shfl_xor_sync(0xffffffffu, a0, o);
        a1 += __shfl_xor_sync(0xffffffffu, a1, o);
        a2 += __shfl_xor_sync(0xffffffffu, a2, o);
        a3 += __shfl_xor_sync(0xffffffffu, a3, o);
    }
    if (lane == 0) {
        float p[4] = {a0 + gb[0], a1 + gb[1], a2 + gb[2], a3 + gb[3]};
        const float mx = fmaxf(fmaxf(p[0], p[1]), fmaxf(p[2], p[3]));
        float s = 0.f;
        #pragma unroll
        for (int e = 0; e < 4; e++) { p[e] = expf(p[e] - mx); s += p[e]; }
        const float invs = 1.0f / s;
        #pragma unroll
        for (int e = 0; e < 4; e++) p[e] *= invs;
        int i0 = 0;
        #pragma unroll
        for (int e = 1; e < 4; e++) if (p[e] > p[i0]) i0 = e;
        int i1 = -1;
        #pragma unroll
        for (int e = 0; e < 4; e++) if (e != i0 && (i1 < 0 || p[e] > p[i1])) i1 = e;
        int s0 = atomicAdd(&cnt[i0], 1);
        idx[i0 * T_TOK + s0] = row; rw[i0 * T_TOK + s0] = p[i0];
        int s1 = atomicAdd(&cnt[i1], 1);
        idx[i1 * T_TOK + s1] = row; rw[i1 * T_TOK + s1] = p[i1];
    }
}

__global__ void head_kernel(const float* __restrict__ h,
                            const float* __restrict__ fng, const float* __restrict__ fnb,
                            const float* __restrict__ hg,  const float* __restrict__ hb,
                            const float* __restrict__ hw,  const float* __restrict__ hbias,
                            float* __restrict__ out, int out_size)
{
    const int warp = threadIdx.x >> 5, lane = threadIdx.x & 31;
    const int b = warp;
    const float* xr = h + ((size_t)b * 128 + 127) * 512;
    float v[16];
    float s = 0.f;
    #pragma unroll
    for (int c = 0; c < 4; c++) {
        float4 f = *(const float4*)(xr + c * 128 + lane * 4);
        v[c * 4 + 0] = f.x; v[c * 4 + 1] = f.y; v[c * 4 + 2] = f.z; v[c * 4 + 3] = f.w;
        s += f.x + f.y + f.z + f.w;
    }
    #pragma unroll
    for (int o = 16; o; o >>= 1) s += __shfl_xor_sync(0xffffffffu, s, o);
    float mu = s * (1.0f / 512.0f);
    float q = 0.f;
    #pragma unroll
    for (int k = 0; k < 16; k++) { float d = v[k] - mu; q += d * d; }
    #pragma unroll
    for (int o = 16; o; o >>= 1) q += __shfl_xor_sync(0xffffffffu, q, o);
    float rs = rsqrtf(q * (1.0f / 512.0f) + 1e-5f);
    #pragma unroll
    for (int c = 0; c < 4; c++)
        #pragma unroll
        for (int j = 0; j < 4; j++) {
            const int col = c * 128 + lane * 4 + j;
            v[c * 4 + j] = fng[col] * (v[c * 4 + j] - mu) * rs + fnb[col];
        }
    s = 0.f;
    #pragma unroll
    for (int k = 0; k < 16; k++) s += v[k];
    #pragma unroll
    for (int o = 16; o; o >>= 1) s += __shfl_xor_sync(0xffffffffu, s, o);
    mu = s * (1.0f / 512.0f);
    q = 0.f;
    #pragma unroll
    for (int k = 0; k < 16; k++) { float d = v[k] - mu; q += d * d; }
    #pragma unroll
    for (int o = 16; o; o >>= 1) q += __shfl_xor_sync(0xffffffffu, q, o);
    rs = rsqrtf(q * (1.0f / 512.0f) + 1e-5f);
    float dot = 0.f;
    #pragma unroll
    for (int c = 0; c < 4; c++)
        #pragma unroll
        for (int j = 0; j < 4; j++) {
            const int col = c * 128 + lane * 4 + j;
            const float hl = hg[col] * (v[c * 4 + j] - mu) * rs + hb[col];
            dot += hl * hw[col];
        }
    #pragma unroll
    for (int o = 16; o; o >>= 1) dot += __shfl_xor_sync(0xffffffffu, dot, o);
    if (lane == 0) {
        const float logit = dot + hbias[0];
        if (out_size >= 32) {
            out[b] = logit;
            out[16 + b] = 1.0f / (1.0f + expf(-logit));
        } else {
            out[b] = logit;
        }
    }
}

// ---------------------------------------------------------------------------
extern "C" void kernel_launch(void* const* d_in, const int* in_sizes, int n_in,
                              void* d_out, int out_size)
{
    const float* x        = (const float*)d_in[0];
    const int*   fid      = (const int*)  d_in[1];
    const float* ir_w1    = (const float*)d_in[2];
    const float* ir_b1    = (const float*)d_in[3];
    const float* ir_w2    = (const float*)d_in[4];
    const float* ir_b2    = (const float*)d_in[5];
    const float* p2m_w    = (const float*)d_in[6];
    const float* p2m_b    = (const float*)d_in[7];
    const float* freq_emb = (const float*)d_in[8];
    const float* ln1_g    = (const float*)d_in[9];
    const float* ln1_b    = (const float*)d_in[10];
    const float* qkv_w    = (const float*)d_in[11];
    const float* qkv_b    = (const float*)d_in[12];
    const float* out_w    = (const float*)d_in[13];
    const float* out_b    = (const float*)d_in[14];
    const float* ln2_g    = (const float*)d_in[15];
    const float* ln2_b    = (const float*)d_in[16];
    const float* gate_w   = (const float*)d_in[17];
    const float* gate_b   = (const float*)d_in[18];
    const float* exp_w1   = (const float*)d_in[19];
    const float* exp_b1   = (const float*)d_in[20];
    const float* exp_w2   = (const float*)d_in[21];
    const float* exp_b2   = (const float*)d_in[22];
    const float* fn_g     = (const float*)d_in[23];
    const float* fn_b     = (const float*)d_in[24];
    const float* head_g   = (const float*)d_in[25];
    const float* head_b   = (const float*)d_in[26];
    const float* head_w   = (const float*)d_in[27];
    const float* head_bias= (const float*)d_in[28];

    float *patches, *tmp, *hp, *h, *hn, *qkv, *attn, *eh, *rw;
    int *cnt, *idx;
    cudaGetSymbolAddress((void**)&patches, g_patches);
    cudaGetSymbolAddress((void**)&tmp,     g_tmp);
    cudaGetSymbolAddress((void**)&hp,      g_hp);
    cudaGetSymbolAddress((void**)&h,       g_h);
    cudaGetSymbolAddress((void**)&hn,      g_hn);
    cudaGetSymbolAddress((void**)&qkv,     g_qkv);
    cudaGetSymbolAddress((void**)&attn,    g_attn);
    cudaGetSymbolAddress((void**)&eh,      g_eh);
    cudaGetSymbolAddress((void**)&cnt,     g_cnt);
    cudaGetSymbolAddress((void**)&idx,     g_idx);
    cudaGetSymbolAddress((void**)&rw,      g_rw);

    cudaFuncSetAttribute(mma_gemm<0,false,false,false>, cudaFuncAttributeMaxDynamicSharedMemorySize, SMEM_MMA);
    cudaFuncSetAttribute(mma_gemm<1,false,false,false>, cudaFuncAttributeMaxDynamicSharedMemorySize, SMEM_MMA);
    cudaFuncSetAttribute(mma_gemm<2,false,false,false>, cudaFuncAttributeMaxDynamicSharedMemorySize, SMEM_MMA);
    cudaFuncSetAttribute(mma_gemm<3,false,false,false>, cudaFuncAttributeMaxDynamicSharedMemorySize, SMEM_MMA);
    cudaFuncSetAttribute(mma_gemm<1,true,true,true>,    cudaFuncAttributeMaxDynamicSharedMemorySize, SMEM_MMA);
    cudaFuncSetAttribute(mma_gemm<5,false,true,true>,   cudaFuncAttributeMaxDynamicSharedMemorySize, SMEM_MMA);
    cudaFuncSetAttribute(attn_flash, cudaFuncAttributeMaxDynamicSharedMemorySize, SMEM_ATTN);

    const size_t EHZ = (size_t)T_TOK * HDIM;

    // Front end
    patchnorm_kernel<<<256, 256>>>(x, patches);
    mma_gemm<1,false,false,false><<<dim3(4, 32), 256, SMEM_MMA>>>(patches, ir_w1, ir_b1, tmp,
        T_TOK, 512, 128, nullptr, nullptr, nullptr, nullptr, 0, 0);
    mma_gemm<2,false,false,false><<<dim3(1, 32), 256, SMEM_MMA>>>(tmp, ir_w2, ir_b2, hp,
        T_TOK, 128, 512, patches, nullptr, nullptr, nullptr, 0, 0);
    mma_gemm<0,false,false,false><<<dim3(4, 32), 256, SMEM_MMA>>>(hp, p2m_w, p2m_b, h,
        T_TOK, 512, 128, nullptr, nullptr, nullptr, nullptr, 0, 0);
    freqadd_kernel<<<(T_TOK * 512) / 256, 256>>>(h, freq_emb, fid);

    for (int l = 0; l < 12; l++) {
        // attention
        ln512_kernel<<<256, 256>>>(h, hn, ln1_g + (size_t)l * 512, ln1_b + (size_t)l * 512);
        mma_gemm<0,false,false,false><<<dim3(12, 32), 256, SMEM_MMA>>>(hn,
            qkv_w + (size_t)l * 512 * 1536, qkv_b + (size_t)l * 1536, qkv,
            T_TOK, 1536, 512, nullptr, nullptr, nullptr, nullptr, 0, 0);
        attn_flash<<<128, 128, SMEM_ATTN>>>(qkv, attn);
        mma_gemm<3,false,false,false><<<dim3(4, 32), 256, SMEM_MMA>>>(attn,
            out_w + (size_t)l * 512 * 512, out_b + (size_t)l * 512, h,
            T_TOK, 512, 512, nullptr, nullptr, nullptr, nullptr, 0, 0);
        // sparse MoE (4 experts fused via blockIdx.z)
        ln512_kernel<<<256, 256>>>(h, hn, ln2_g + (size_t)l * 512, ln2_b + (size_t)l * 512);
        zero_cnt_kernel<<<1, 32>>>(cnt);
        gate_route_kernel<<<256, 256>>>(hn, gate_w + (size_t)l * 512 * 4,
                                        gate_b + (size_t)l * 4, cnt, idx, rw);
        mma_gemm<1,true,true,true><<<dim3(16, 32, 4), 256, SMEM_MMA>>>(hn,
            exp_w1 + (size_t)l * 4 * 512 * 2048, exp_b1 + (size_t)l * 4 * 2048, eh,
            T_TOK, 2048, 512, nullptr, idx, nullptr, cnt, 0, EHZ);
        mma_gemm<5,false,true,true><<<dim3(4, 32, 4), 256, SMEM_MMA>>>(eh,
            exp_w2 + (size_t)l * 4 * 2048 * 512, exp_b2 + (size_t)l * 4 * 512, h,
            T_TOK, 512, 2048, nullptr, idx, rw, cnt, EHZ, 0);
    }

    head_kernel<<<1, 512>>>(h, fn_g, fn_b, head_g, head_b, head_w, head_bias,
                            (float*)d_out, out_size);
}